// round 7
// baseline (speedup 1.0000x reference)
#include <cuda_runtime.h>
#include <math.h>

#define BB 8
#define NN 16384
#define DD 128
#define OO 256
#define CH1 448
#define NCH 37
#define LN_EPS 1e-5f
// K3 smem: M (32768 floats) + 8 warps * 2048 floats of duplicated q
#define K3_SMEM ((32768 + 8 * 2048) * 4)

typedef unsigned long long u64;

__device__ float g_ctx_part[(size_t)BB * NCH * DD * DD]; // ~19.4MB
__device__ float g_ksum_part[(size_t)BB * NCH * DD];
__device__ float g_wT[DD * OO];
__device__ float g_M[(size_t)BB * DD * OO];

__device__ __forceinline__ void ffma2(u64 &d, u64 a, u64 b) {
    asm("fma.rn.f32x2 %0, %1, %2, %0;" : "+l"(d) : "l"(a), "l"(b));
}
__device__ __forceinline__ u64 add2(u64 a, u64 b) {
    u64 r; asm("add.rn.f32x2 %0, %1, %2;" : "=l"(r) : "l"(a), "l"(b));
    return r;
}
__device__ __forceinline__ float2 unpack2(u64 v) {
    unsigned int lo, hi;
    asm("mov.b64 {%0, %1}, %2;" : "=r"(lo), "=r"(hi) : "l"(v));
    return make_float2(__uint_as_float(lo), __uint_as_float(hi));
}

// ---------------- K0: transpose W[256,128] -> wT[128,256] ----------------
__global__ void k0_transpose(const float* __restrict__ w) {
    int i = blockIdx.x * blockDim.x + threadIdx.x;
    if (i < DD * OO) { int o = i / DD, v = i % DD; g_wT[v * OO + o] = w[i]; }
}

// ---------------- K1: context partials + column exp-sums ----------------
// E (exp of x1) stored DUPLICATED in smem with XOR bank swizzle so the
// ffma2 broadcast operand comes straight from LDS.128 (no splat MOVs).
__global__ void __launch_bounds__(256, 2) k1_context(const float* __restrict__ x1,
                                                     const float* __restrict__ x2) {
    __shared__ __align__(16) float Ed[2][8][256];   // dup: slot c (0..127) -> float2
    __shared__ __align__(16) float Xs[2][8][132];
    __shared__ float csum_s[8][128];

    const int b = blockIdx.y, ch = blockIdx.x;
    const int n0 = ch * CH1;
    const int nrows = (NN - n0 < CH1) ? (NN - n0) : CH1;
    const int nit = nrows >> 3;

    const int t = threadIdx.x;
    const int lrow = t >> 5, lq = t & 31;
    const int ty = t >> 4, tx = t & 15;
    const int ldidx = lrow * 32 + lq;
    const int swq = (lq & 7) << 1;   // write-side swizzle
    const int c0 = 4 * lq;
    const int sr = (ty & 7) << 1;    // read-side swizzle
    const int cA = 4 * ty;

    const float4* x1p = (const float4*)(x1 + ((size_t)b * NN + n0) * DD);
    const float4* x2p = (const float4*)(x2 + ((size_t)b * NN + n0) * DD);

    u64 acc[8][4];
#pragma unroll
    for (int i = 0; i < 8; ++i)
#pragma unroll
        for (int j = 0; j < 4; ++j) acc[i][j] = 0ull;

    float4 cs = make_float4(0.f, 0.f, 0.f, 0.f);
    float4 ra = x1p[ldidx];
    float4 rb = x2p[ldidx];

    for (int it = 0; it < nit; ++it) {
        const int buf = it & 1;
        float4 ea;
        ea.x = __expf(ra.x); ea.y = __expf(ra.y); ea.z = __expf(ra.z); ea.w = __expf(ra.w);
        cs.x += ea.x; cs.y += ea.y; cs.z += ea.z; cs.w += ea.w;
        {
            float* erow = &Ed[buf][lrow][0];
            *(float2*)&erow[2 * ((c0 + 0) ^ swq)] = make_float2(ea.x, ea.x);
            *(float2*)&erow[2 * ((c0 + 1) ^ swq)] = make_float2(ea.y, ea.y);
            *(float2*)&erow[2 * ((c0 + 2) ^ swq)] = make_float2(ea.z, ea.z);
            *(float2*)&erow[2 * ((c0 + 3) ^ swq)] = make_float2(ea.w, ea.w);
        }
        *(float4*)&Xs[buf][lrow][lq * 4] = rb;
        __syncthreads();
        if (it + 1 < nit) {
            ra = x1p[(it + 1) * 256 + ldidx];
            rb = x2p[(it + 1) * 256 + ldidx];
        }
#pragma unroll
        for (int r = 0; r < 8; ++r) {
            const float* er = &Ed[buf][r][0];
            const float* xr = &Xs[buf][r][0];
            ulonglong2 a01 = *(const ulonglong2*)&er[2 * ((cA + 0)  ^ sr)];
            ulonglong2 a23 = *(const ulonglong2*)&er[2 * ((cA + 2)  ^ sr)];
            ulonglong2 a45 = *(const ulonglong2*)&er[2 * ((cA + 64) ^ sr)];
            ulonglong2 a67 = *(const ulonglong2*)&er[2 * ((cA + 66) ^ sr)];
            ulonglong2 b0 = *(const ulonglong2*)(xr + 4 * tx);
            ulonglong2 b1 = *(const ulonglong2*)(xr + 64 + 4 * tx);
            u64 av[8];
            av[0] = a01.x; av[1] = a01.y; av[2] = a23.x; av[3] = a23.y;
            av[4] = a45.x; av[5] = a45.y; av[6] = a67.x; av[7] = a67.y;
#pragma unroll
            for (int i = 0; i < 8; ++i) {
                ffma2(acc[i][0], av[i], b0.x);
                ffma2(acc[i][1], av[i], b0.y);
                ffma2(acc[i][2], av[i], b1.x);
                ffma2(acc[i][3], av[i], b1.y);
            }
        }
    }

    *(float4*)&csum_s[lrow][lq * 4] = cs;
    __syncthreads();
    if (t < 128) {
        float s = 0.f;
#pragma unroll
        for (int g = 0; g < 8; ++g) s += csum_s[g][t];
        g_ksum_part[((size_t)b * NCH + ch) * DD + t] = s;
    }

    float* outp = g_ctx_part + ((size_t)b * NCH + ch) * DD * DD;
#pragma unroll
    for (int i = 0; i < 8; ++i) {
        const int d = (i < 4) ? (4 * ty + i) : (64 + 4 * ty + (i - 4));
        float* rowp = outp + (size_t)d * DD;
        ulonglong2 s01; s01.x = acc[i][0]; s01.y = acc[i][1];
        ulonglong2 s23; s23.x = acc[i][2]; s23.y = acc[i][3];
        *(ulonglong2*)(rowp + 4 * tx)      = s01;
        *(ulonglong2*)(rowp + 64 + 4 * tx) = s23;
    }
}

// ---------------- K2: merge partials, normalize, M = ctx_norm @ W^T ----------------
__global__ void k2_M() {
    __shared__ float ctx_s[4][128];
    __shared__ float ks_s[4];
    const int b = blockIdx.y, dg = blockIdx.x;
    const int t = threadIdx.x;

    if (t < 4) {
        float s = 0.f;
        for (int ch = 0; ch < NCH; ++ch)
            s += g_ksum_part[((size_t)b * NCH + ch) * DD + dg * 4 + t];
        ks_s[t] = 1.0f / s;
    }
    __syncthreads();

    for (int e = t; e < 512; e += 256) {
        const int d = e >> 7, v = e & 127;
        const float* p = g_ctx_part + (size_t)b * NCH * DD * DD + (size_t)(dg * 4 + d) * DD + v;
        float s = 0.f;
        for (int ch = 0; ch < NCH; ++ch) s += p[(size_t)ch * DD * DD];
        ctx_s[d][v] = s * ks_s[d];
    }
    __syncthreads();

    float a0 = 0.f, a1 = 0.f, a2 = 0.f, a3 = 0.f;
#pragma unroll 8
    for (int v = 0; v < 128; ++v) {
        const float wv = g_wT[v * OO + t];
        a0 = fmaf(ctx_s[0][v], wv, a0);
        a1 = fmaf(ctx_s[1][v], wv, a1);
        a2 = fmaf(ctx_s[2][v], wv, a2);
        a3 = fmaf(ctx_s[3][v], wv, a3);
    }
    float* Mp = g_M + ((size_t)b * DD + dg * 4) * OO + t;
    Mp[0] = a0; Mp[OO] = a1; Mp[2 * OO] = a2; Mp[3 * OO] = a3;
}

// ---------------- K3: eff = softmax_D(x1) @ M + bias, fused LayerNorm ----------------
// q stored duplicated per-warp (XOR-swizzled); acc pairs over OUTPUTS.
// Per d per warp: 4 LDS.128 (q) + 4 LDS.64 (md) + 32 ffma2, zero MOV splats.
__global__ void __launch_bounds__(256, 1) k3_final(const float* __restrict__ x1,
                                                   const float* __restrict__ bias,
                                                   const float* __restrict__ gamma,
                                                   const float* __restrict__ beta,
                                                   float* __restrict__ out) {
    extern __shared__ float sm[];
    float* M_s = sm;                          // 32768 floats
    const int t = threadIdx.x;
    const int lane = t & 31, g = t >> 5;
    float* q_w = sm + 32768 + g * 2048;       // per-warp dup-q (1024 float2 slots)

    // per-thread outputs: o = 64p + 2lane (+1)
    float2 gam2[4], bet2[4];
    u64 bia2[4];
#pragma unroll
    for (int p = 0; p < 4; ++p) {
        gam2[p] = *(const float2*)&gamma[64 * p + 2 * lane];
        bet2[p] = *(const float2*)&beta[64 * p + 2 * lane];
        bia2[p] = *(const u64*)&bias[64 * p + 2 * lane];
    }
    const int swq = (lane & 7) << 1;

    const int TILES = BB * (NN / 64); // 2048
    const int start = (blockIdx.x * TILES) / gridDim.x;
    const int end   = ((blockIdx.x + 1) * TILES) / gridDim.x;
    int curb = -1;

    for (int tile = start; tile < end; ++tile) {
        const int b = tile >> 8;
        const int n0 = (tile & 255) * 64;

        if (b != curb) {
            __syncthreads();
            const float4* Mp = (const float4*)(g_M + (size_t)b * DD * OO);
            for (int i = t; i < 8192; i += 256) ((float4*)M_s)[i] = Mp[i];
            curb = b;
            __syncthreads();
        }

        // --- softmax over D for this warp's 8 rows; store duplicated q ---
#pragma unroll
        for (int j = 0; j < 8; ++j) {
            const int r = g * 8 + j;
            const float4 v = ((const float4*)(x1 + ((size_t)b * NN + n0 + r) * DD))[lane];
            float e0 = __expf(v.x), e1 = __expf(v.y), e2 = __expf(v.z), e3 = __expf(v.w);
            float s = e0 + e1 + e2 + e3;
#pragma unroll
            for (int m = 16; m; m >>= 1) s += __shfl_xor_sync(0xffffffffu, s, m);
            const float inv = 1.0f / s;
            e0 *= inv; e1 *= inv; e2 *= inv; e3 *= inv;
            const int base = 32 * lane;   // idx2 = 32*lane + 8*k + j, pos = idx2 ^ swq
            *(float2*)&q_w[2 * (base + ((0  + j) ^ swq))] = make_float2(e0, e0);
            *(float2*)&q_w[2 * (base + ((8  + j) ^ swq))] = make_float2(e1, e1);
            *(float2*)&q_w[2 * (base + ((16 + j) ^ swq))] = make_float2(e2, e2);
            *(float2*)&q_w[2 * (base + ((24 + j) ^ swq))] = make_float2(e3, e3);
        }
        __syncwarp();

        // --- GEMM: acc[row j][output pair p] ---
        u64 acc[8][4];
#pragma unroll
        for (int j = 0; j < 8; ++j)
#pragma unroll
            for (int p = 0; p < 4; ++p) acc[j][p] = 0ull;

#pragma unroll 4
        for (int d = 0; d < 128; ++d) {
            const int sd = ((d >> 2) & 7) << 1;
            const int P = (8 * d) ^ sd;
            ulonglong2 q01 = *(const ulonglong2*)&q_w[2 * (P ^ 0)];
            ulonglong2 q23 = *(const ulonglong2*)&q_w[2 * (P ^ 2)];
            ulonglong2 q45 = *(const ulonglong2*)&q_w[2 * (P ^ 4)];
            ulonglong2 q67 = *(const ulonglong2*)&q_w[2 * (P ^ 6)];
            const float* md = M_s + (d << 8) + 2 * lane;
            u64 m0 = *(const u64*)(md);
            u64 m1 = *(const u64*)(md + 64);
            u64 m2 = *(const u64*)(md + 128);
            u64 m3 = *(const u64*)(md + 192);
            u64 qv[8];
            qv[0] = q01.x; qv[1] = q01.y; qv[2] = q23.x; qv[3] = q23.y;
            qv[4] = q45.x; qv[5] = q45.y; qv[6] = q67.x; qv[7] = q67.y;
#pragma unroll
            for (int j = 0; j < 8; ++j) {
                ffma2(acc[j][0], qv[j], m0);
                ffma2(acc[j][1], qv[j], m1);
                ffma2(acc[j][2], qv[j], m2);
                ffma2(acc[j][3], qv[j], m3);
            }
        }

        // --- bias + LayerNorm + store ---
#pragma unroll
        for (int j = 0; j < 8; ++j) {
            u64 s2 = 0ull, ss2 = 0ull;
#pragma unroll
            for (int p = 0; p < 4; ++p) {
                acc[j][p] = add2(acc[j][p], bia2[p]);
                s2 = add2(s2, acc[j][p]);
                ffma2(ss2, acc[j][p], acc[j][p]);
            }
            const float2 sf = unpack2(s2), ssf = unpack2(ss2);
            float s = sf.x + sf.y, ss = ssf.x + ssf.y;
#pragma unroll
            for (int m = 16; m; m >>= 1) {
                s  += __shfl_xor_sync(0xffffffffu, s,  m);
                ss += __shfl_xor_sync(0xffffffffu, ss, m);
            }
            const float mean = s * 0.00390625f;
            const float rstd = rsqrtf(ss * 0.00390625f - mean * mean + LN_EPS);
            float* op = out + ((size_t)b * NN + n0 + g * 8 + j) * OO + 2 * lane;
#pragma unroll
            for (int p = 0; p < 4; ++p) {
                const float2 v = unpack2(acc[j][p]);
                float2 o;
                o.x = (v.x - mean) * (rstd * gam2[p].x) + bet2[p].x;
                o.y = (v.y - mean) * (rstd * gam2[p].y) + bet2[p].y;
                *(float2*)(op + 64 * p) = o;
            }
        }
        __syncwarp();
    }
}

extern "C" void kernel_launch(void* const* d_in, const int* in_sizes, int n_in,
                              void* d_out, int out_size) {
    const float* x1  = (const float*)d_in[0];
    const float* x2  = (const float*)d_in[1];
    const float* w   = (const float*)d_in[2];
    const float* brp = (const float*)d_in[3];
    const float* gam = (const float*)d_in[4];
    const float* bet = (const float*)d_in[5];
    float* out = (float*)d_out;

    cudaFuncSetAttribute(k3_final, cudaFuncAttributeMaxDynamicSharedMemorySize, K3_SMEM);

    k0_transpose<<<128, 256>>>(w);
    k1_context<<<dim3(NCH, BB), 256>>>(x1, x2);
    k2_M<<<dim3(32, BB), 256>>>();
    k3_final<<<148, 256, K3_SMEM>>>(x1, brp, gam, bet, out);
}

// round 9
// speedup vs baseline: 1.3567x; 1.3567x over previous
#include <cuda_runtime.h>
#include <cuda_bf16.h>
#include <math.h>
#include <stdint.h>

#define BB 8
#define NN 16384
#define DD 128
#define OO 256
#define CH1 448
#define NCH 37
#define LN_EPS 1e-5f

typedef unsigned long long u64;

// ---------------- scratch (device globals) ----------------
__device__ float g_ctx_part[(size_t)BB * NCH * DD * DD]; // ~19.4MB
__device__ float g_ksum_part[(size_t)BB * NCH * DD];
__device__ float g_wT[DD * OO];
// B = (ctx_norm@W^T + bias)^T in bf16 hi/lo, packed in mma B-fragment layout:
// u64 word index = ((ks*32 + ntile)*32 + (gid*4 + tig)); word = bf16 k={2t,2t+1,2t+8,2t+9}
__device__ __align__(16) unsigned char g_Bh[(size_t)BB * 65536];
__device__ __align__(16) unsigned char g_Bl[(size_t)BB * 65536];

// ---------------- f32x2 helpers (K1) ----------------
__device__ __forceinline__ u64 splat2(float a) {
    u64 r; unsigned int ai = __float_as_uint(a);
    asm("mov.b64 %0, {%1, %1};" : "=l"(r) : "r"(ai));
    return r;
}
__device__ __forceinline__ void ffma2(u64 &d, u64 a, u64 b) {
    asm("fma.rn.f32x2 %0, %1, %2, %0;" : "+l"(d) : "l"(a), "l"(b));
}

__device__ __forceinline__ uint32_t smem_u32(const void* p) {
    uint32_t a;
    asm("{ .reg .u64 t; cvta.to.shared.u64 t, %1; cvt.u32.u64 %0, t; }" : "=r"(a) : "l"(p));
    return a;
}

// mma.sync m16n8k16 row.col f32 += bf16*bf16
__device__ __forceinline__ void mma16816(float* c, const uint32_t* a, u64 b) {
    uint32_t b0 = (uint32_t)b, b1 = (uint32_t)(b >> 32);
    asm volatile(
        "mma.sync.aligned.m16n8k16.row.col.f32.bf16.bf16.f32 "
        "{%0,%1,%2,%3}, {%4,%5,%6,%7}, {%8,%9}, {%0,%1,%2,%3};"
        : "+f"(c[0]), "+f"(c[1]), "+f"(c[2]), "+f"(c[3])
        : "r"(a[0]), "r"(a[1]), "r"(a[2]), "r"(a[3]), "r"(b0), "r"(b1));
}
__device__ __forceinline__ void ldsm4(uint32_t* r, uint32_t addr) {
    asm volatile("ldmatrix.sync.aligned.m8n8.x4.shared.b16 {%0,%1,%2,%3}, [%4];"
                 : "=r"(r[0]), "=r"(r[1]), "=r"(r[2]), "=r"(r[3]) : "r"(addr));
}

// K3 smem layout (bytes)
#define SM_GAM 0
#define SM_BET 1024
#define SM_AHI 2048
#define SM_ALO (SM_AHI + 34816)      // 128 rows * 272B
#define SM_BHI (SM_ALO + 34816)      // 71680
#define SM_BLO (SM_BHI + 65536)      // 137216
#define K3_SMEM (SM_BLO + 65536)     // 202752

// ================== K0: transpose W ==================
__global__ void k0_transpose(const float* __restrict__ w) {
    int i = blockIdx.x * blockDim.x + threadIdx.x;
    if (i < DD * OO) { int o = i / DD, v = i % DD; g_wT[v * OO + o] = w[i]; }
}

// ================== K1: context partials (validated R5 version) ==================
__global__ void __launch_bounds__(256, 2) k1_context(const float* __restrict__ x1,
                                                     const float* __restrict__ x2) {
    __shared__ __align__(16) float Es[2][8][132];
    __shared__ __align__(16) float Xs[2][8][132];
    __shared__ float csum_s[8][128];

    const int b = blockIdx.y, ch = blockIdx.x;
    const int n0 = ch * CH1;
    const int nrows = (NN - n0 < CH1) ? (NN - n0) : CH1;
    const int nit = nrows >> 3;

    const int t = threadIdx.x;
    const int lrow = t >> 5, lq = t & 31;
    const int ty = t >> 4, tx = t & 15;
    const int ldidx = lrow * 32 + lq;

    const float4* x1p = (const float4*)(x1 + ((size_t)b * NN + n0) * DD);
    const float4* x2p = (const float4*)(x2 + ((size_t)b * NN + n0) * DD);

    u64 acc[8][4];
#pragma unroll
    for (int i = 0; i < 8; ++i)
#pragma unroll
        for (int j = 0; j < 4; ++j) acc[i][j] = 0ull;

    float4 cs = make_float4(0.f, 0.f, 0.f, 0.f);
    float4 ra = x1p[ldidx];
    float4 rb = x2p[ldidx];

    for (int it = 0; it < nit; ++it) {
        const int buf = it & 1;
        float4 ea;
        ea.x = __expf(ra.x); ea.y = __expf(ra.y); ea.z = __expf(ra.z); ea.w = __expf(ra.w);
        cs.x += ea.x; cs.y += ea.y; cs.z += ea.z; cs.w += ea.w;
        *(float4*)&Es[buf][lrow][lq * 4] = ea;
        *(float4*)&Xs[buf][lrow][lq * 4] = rb;
        __syncthreads();
        if (it + 1 < nit) {
            ra = x1p[(it + 1) * 256 + ldidx];
            rb = x2p[(it + 1) * 256 + ldidx];
        }
#pragma unroll
        for (int r = 0; r < 8; ++r) {
            const float* er = &Es[buf][r][0];
            const float* xr = &Xs[buf][r][0];
            float a[8];
            *(float4*)&a[0] = *(const float4*)(er + 4 * ty);
            *(float4*)&a[4] = *(const float4*)(er + 64 + 4 * ty);
            ulonglong2 b0 = *(const ulonglong2*)(xr + 4 * tx);
            ulonglong2 b1 = *(const ulonglong2*)(xr + 64 + 4 * tx);
#pragma unroll
            for (int i = 0; i < 8; ++i) {
                u64 s = splat2(a[i]);
                ffma2(acc[i][0], s, b0.x);
                ffma2(acc[i][1], s, b0.y);
                ffma2(acc[i][2], s, b1.x);
                ffma2(acc[i][3], s, b1.y);
            }
        }
    }

    *(float4*)&csum_s[lrow][lq * 4] = cs;
    __syncthreads();
    if (t < 128) {
        float s = 0.f;
#pragma unroll
        for (int g = 0; g < 8; ++g) s += csum_s[g][t];
        g_ksum_part[((size_t)b * NCH + ch) * DD + t] = s;
    }

    float* outp = g_ctx_part + ((size_t)b * NCH + ch) * DD * DD;
#pragma unroll
    for (int i = 0; i < 8; ++i) {
        const int d = (i < 4) ? (4 * ty + i) : (64 + 4 * ty + (i - 4));
        float* rowp = outp + (size_t)d * DD;
        ulonglong2 s01; s01.x = acc[i][0]; s01.y = acc[i][1];
        ulonglong2 s23; s23.x = acc[i][2]; s23.y = acc[i][3];
        *(ulonglong2*)(rowp + 4 * tx)      = s01;
        *(ulonglong2*)(rowp + 64 + 4 * tx) = s23;
    }
}

// ================== K2: merge, normalize, pack B-fragments bf16 hi/lo ==================
__global__ void k2_M(const float* __restrict__ bias) {
    __shared__ float ctx_s[4][128];
    __shared__ float ks_s[4];
    const int b = blockIdx.y, dg = blockIdx.x;
    const int t = threadIdx.x;

    if (t < 4) {
        float s = 0.f;
        for (int ch = 0; ch < NCH; ++ch)
            s += g_ksum_part[((size_t)b * NCH + ch) * DD + dg * 4 + t];
        ks_s[t] = 1.0f / s;
    }
    __syncthreads();

    for (int e = t; e < 512; e += 256) {
        const int d = e >> 7, v = e & 127;
        const float* p = g_ctx_part + (size_t)b * NCH * DD * DD + (size_t)(dg * 4 + d) * DD + v;
        float s = 0.f;
        for (int ch = 0; ch < NCH; ++ch) s += p[(size_t)ch * DD * DD];
        ctx_s[d][v] = s * ks_s[d];
    }
    __syncthreads();

    const float bo = bias[t];   // fold bias (softmax rows sum to 1)
    float av[4] = {bo, bo, bo, bo};
#pragma unroll 8
    for (int v = 0; v < 128; ++v) {
        const float wv = g_wT[v * OO + t];
        av[0] = fmaf(ctx_s[0][v], wv, av[0]);
        av[1] = fmaf(ctx_s[1][v], wv, av[1]);
        av[2] = fmaf(ctx_s[2][v], wv, av[2]);
        av[3] = fmaf(ctx_s[3][v], wv, av[3]);
    }

    const int o = t, nt = o >> 3, gid = o & 7;
    unsigned char* Bh = g_Bh + (size_t)b * 65536;
    unsigned char* Bl = g_Bl + (size_t)b * 65536;
#pragma unroll
    for (int d = 0; d < 4; ++d) {
        const int k = dg * 4 + d;
        const int ks = k >> 4, r = k & 15;
        const int half = r >> 3, tg = (r & 7) >> 1, pos = r & 1;
        const size_t off = ((size_t)((ks * 32 + nt) * 32 + (gid * 4 + tg))) * 8
                         + half * 4 + pos * 2;
        const __nv_bfloat16 h = __float2bfloat16(av[d]);
        const __nv_bfloat16 l = __float2bfloat16(av[d] - __bfloat162float(h));
        *(__nv_bfloat16*)(Bh + off) = h;
        *(__nv_bfloat16*)(Bl + off) = l;
    }
}

// ================== K3: mma.sync bf16 split GEMM + fused softmax/LN ==================
// grid 128: block = (batch b = blk>>4, slice w = blk&15), 8 tiles of 128 rows each.
// Each warp owns 16 rows end-to-end: softmax -> A staging -> 768 MMAs -> LN in regs.
__global__ void __launch_bounds__(256, 1) k3_mma(const float* __restrict__ x1,
                                                 const float* __restrict__ gamma,
                                                 const float* __restrict__ beta,
                                                 float* __restrict__ out) {
    extern __shared__ __align__(16) unsigned char smem[];
    const uint32_t sb = smem_u32(smem);
    const int t = threadIdx.x, lane = t & 31, g = t >> 5;
    const int b = blockIdx.x >> 4;
    const int w = blockIdx.x & 15;

    ((float*)(smem + SM_GAM))[t] = gamma[t];
    ((float*)(smem + SM_BET))[t] = beta[t];
    {
        const float4* sh = (const float4*)(g_Bh + (size_t)b * 65536);
        const float4* sl = (const float4*)(g_Bl + (size_t)b * 65536);
        float4* dh = (float4*)(smem + SM_BHI);
        float4* dl = (float4*)(smem + SM_BLO);
        for (int i = t; i < 4096; i += 256) { dh[i] = sh[i]; dl[i] = sl[i]; }
    }
    __syncthreads();

    const int gid = lane >> 2, tig = lane & 3;
    const int m = lane >> 3;
    const int arow = g * 16 + (m & 1) * 8 + (lane & 7);
    const uint32_t a_off = (uint32_t)(arow * 272 + (m >> 1) * 16);
    const uint32_t aHaddr = sb + SM_AHI + a_off;
    const uint32_t aLaddr = sb + SM_ALO + a_off;
    const u64* Bh = (const u64*)(smem + SM_BHI);
    const u64* Bl = (const u64*)(smem + SM_BLO);
    const float2* gam2 = (const float2*)(smem + SM_GAM);
    const float2* bet2 = (const float2*)(smem + SM_BET);
    unsigned char* Ah = smem + SM_AHI + (size_t)(g * 16) * 272;
    unsigned char* Al = smem + SM_ALO + (size_t)(g * 16) * 272;

    for (int i = 0; i < 8; ++i) {
        const int n0g = (w * 8 + i) * 128;

        // --- stage A: softmax over D for this warp's 16 rows, bf16 hi/lo ---
        const float4* xp = (const float4*)(x1 + ((size_t)b * NN + n0g + g * 16) * DD);
#pragma unroll 4
        for (int j = 0; j < 16; ++j) {
            const float4 v = xp[j * 32 + lane];
            float e0 = __expf(v.x), e1 = __expf(v.y), e2 = __expf(v.z), e3 = __expf(v.w);
            float s = e0 + e1 + e2 + e3;
#pragma unroll
            for (int mm = 16; mm; mm >>= 1) s += __shfl_xor_sync(0xffffffffu, s, mm);
            const float inv = 1.0f / s;
            e0 *= inv; e1 *= inv; e2 *= inv; e3 *= inv;
            __nv_bfloat16 h0 = __float2bfloat16(e0), h1 = __float2bfloat16(e1);
            __nv_bfloat16 h2 = __float2bfloat16(e2), h3 = __float2bfloat16(e3);
            __nv_bfloat16 l0 = __float2bfloat16(e0 - __bfloat162float(h0));
            __nv_bfloat16 l1 = __float2bfloat16(e1 - __bfloat162float(h1));
            __nv_bfloat16 l2 = __float2bfloat16(e2 - __bfloat162float(h2));
            __nv_bfloat16 l3 = __float2bfloat16(e3 - __bfloat162float(h3));
            __nv_bfloat162 hA; hA.x = h0; hA.y = h1;
            __nv_bfloat162 hB; hB.x = h2; hB.y = h3;
            __nv_bfloat162 lA; lA.x = l0; lA.y = l1;
            __nv_bfloat162 lB; lB.x = l2; lB.y = l3;
            uint2 hw; hw.x = *(uint32_t*)&hA; hw.y = *(uint32_t*)&hB;
            uint2 lw; lw.x = *(uint32_t*)&lA; lw.y = *(uint32_t*)&lB;
            *(uint2*)(Ah + j * 272 + lane * 8) = hw;
            *(uint2*)(Al + j * 272 + lane * 8) = lw;
        }
        __syncwarp();

        // --- GEMM: 32 n-tiles x 8 k-steps x 3 passes ---
        float c[32][4];
#pragma unroll
        for (int nt = 0; nt < 32; ++nt)
#pragma unroll
            for (int q = 0; q < 4; ++q) c[nt][q] = 0.f;

        for (int ks = 0; ks < 8; ++ks) {
            uint32_t ah[4], al[4];
            ldsm4(ah, aHaddr + ks * 32);
            ldsm4(al, aLaddr + ks * 32);
            const u64* bhk = Bh + (size_t)(ks * 32) * 32 + lane;
            const u64* blk = Bl + (size_t)(ks * 32) * 32 + lane;
#pragma unroll
            for (int nt = 0; nt < 32; ++nt) {
                const u64 bh = bhk[nt * 32];
                mma16816(c[nt], ah, bh);
                mma16816(c[nt], al, bh);
                const u64 bl = blk[nt * 32];
                mma16816(c[nt], ah, bl);
            }
        }

        // --- LN epilogue in registers ---
        float sA = 0.f, sB = 0.f, qA = 0.f, qB = 0.f;
#pragma unroll
        for (int nt = 0; nt < 32; ++nt) {
            sA += c[nt][0] + c[nt][1];
            sB += c[nt][2] + c[nt][3];
            qA = fmaf(c[nt][0], c[nt][0], qA); qA = fmaf(c[nt][1], c[nt][1], qA);
            qB = fmaf(c[nt][2], c[nt][2], qB); qB = fmaf(c[nt][3], c[nt][3], qB);
        }
#pragma unroll
        for (int mm = 1; mm <= 2; mm <<= 1) {
            sA += __shfl_xor_sync(0xffffffffu, sA, mm);
            sB += __shfl_xor_sync(0xffffffffu, sB, mm);
            qA += __shfl_xor_sync(0xffffffffu, qA, mm);
            qB += __shfl_xor_sync(0xffffffffu, qB, mm);
        }
        const float mA = sA * 0.00390625f, mB = sB * 0.00390625f;
        const float rA = rsqrtf(qA * 0.00390625f - mA * mA + LN_EPS);
        const float rB = rsqrtf(qB * 0.00390625f - mB * mB + LN_EPS);

        const int rowA = n0g + g * 16 + gid;
        float* oA = out + ((size_t)b * NN + rowA) * OO;
        float* oB = oA + 8 * OO;
#pragma unroll
        for (int nt = 0; nt < 32; ++nt) {
            const int col = nt * 8 + 2 * tig;
            const float2 ga = gam2[col >> 1];
            const float2 be = bet2[col >> 1];
            float2 wA, wB;
            wA.x = (c[nt][0] - mA) * rA * ga.x + be.x;
            wA.y = (c[nt][1] - mA) * rA * ga.y + be.y;
            wB.x = (c[nt][2] - mB) * rB * ga.x + be.x;
            wB.y = (c[nt][3] - mB) * rB * ga.y + be.y;
            *(float2*)(oA + col) = wA;
            *(float2*)(oB + col) = wB;
        }
        __syncwarp();
    }
}

extern "C" void kernel_launch(void* const* d_in, const int* in_sizes, int n_in,
                              void* d_out, int out_size) {
    const float* x1  = (const float*)d_in[0];
    const float* x2  = (const float*)d_in[1];
    const float* w   = (const float*)d_in[2];
    const float* brp = (const float*)d_in[3];
    const float* gam = (const float*)d_in[4];
    const float* bet = (const float*)d_in[5];
    float* out = (float*)d_out;

    cudaFuncSetAttribute(k3_mma, cudaFuncAttributeMaxDynamicSharedMemorySize, K3_SMEM);

    k0_transpose<<<128, 256>>>(w);
    k1_context<<<dim3(NCH, BB), 256>>>(x1, x2);
    k2_M<<<dim3(32, BB), 256>>>(brp);
    k3_mma<<<128, 256, K3_SMEM>>>(x1, gam, bet, out);
}

// round 10
// speedup vs baseline: 1.4169x; 1.0443x over previous
#include <cuda_runtime.h>
#include <cuda_bf16.h>
#include <math.h>
#include <stdint.h>

#define BB 8
#define NN 16384
#define DD 128
#define OO 256
#define CH1 448
#define NCH 37
#define LN_EPS 1e-5f

typedef unsigned long long u64;

// ---------------- scratch (device globals) ----------------
__device__ float g_ctx_part[(size_t)BB * NCH * DD * DD]; // ~19.4MB
__device__ float g_ksum_part[(size_t)BB * NCH * DD];
__device__ float g_wT[DD * OO];
// B = (ctx_norm@W^T + bias)^T in bf16 hi/lo, packed in mma B-fragment layout:
// u64 word index = ((ks*32 + ntile)*32 + (gid*4 + tig)); word = bf16 k={2t,2t+1,2t+8,2t+9}
__device__ __align__(16) unsigned char g_Bh[(size_t)BB * 65536];
__device__ __align__(16) unsigned char g_Bl[(size_t)BB * 65536];

// ---------------- f32x2 helpers (K1) ----------------
__device__ __forceinline__ u64 splat2(float a) {
    u64 r; unsigned int ai = __float_as_uint(a);
    asm("mov.b64 %0, {%1, %1};" : "=l"(r) : "r"(ai));
    return r;
}
__device__ __forceinline__ void ffma2(u64 &d, u64 a, u64 b) {
    asm("fma.rn.f32x2 %0, %1, %2, %0;" : "+l"(d) : "l"(a), "l"(b));
}

__device__ __forceinline__ uint32_t smem_u32(const void* p) {
    uint32_t a;
    asm("{ .reg .u64 t; cvta.to.shared.u64 t, %1; cvt.u32.u64 %0, t; }" : "=r"(a) : "l"(p));
    return a;
}

// mma.sync m16n8k16 row.col f32 += bf16*bf16
__device__ __forceinline__ void mma16816(float* c, const uint32_t* a, u64 b) {
    uint32_t b0 = (uint32_t)b, b1 = (uint32_t)(b >> 32);
    asm volatile(
        "mma.sync.aligned.m16n8k16.row.col.f32.bf16.bf16.f32 "
        "{%0,%1,%2,%3}, {%4,%5,%6,%7}, {%8,%9}, {%0,%1,%2,%3};"
        : "+f"(c[0]), "+f"(c[1]), "+f"(c[2]), "+f"(c[3])
        : "r"(a[0]), "r"(a[1]), "r"(a[2]), "r"(a[3]), "r"(b0), "r"(b1));
}
__device__ __forceinline__ void ldsm4(uint32_t* r, uint32_t addr) {
    asm volatile("ldmatrix.sync.aligned.m8n8.x4.shared.b16 {%0,%1,%2,%3}, [%4];"
                 : "=r"(r[0]), "=r"(r[1]), "=r"(r[2]), "=r"(r[3]) : "r"(addr));
}

// K3 smem layout (bytes)
#define SM_GAM 0
#define SM_BET 1024
#define SM_RS  2048                  // LN partial sums:   128 rows x 4 cg floats
#define SM_RQ  4096                  // LN partial squares
#define SM_AHI 6144
#define SM_ALO (SM_AHI + 34816)      // 128 rows * 272B
#define SM_BHI (SM_ALO + 34816)
#define SM_BLO (SM_BHI + 65536)
#define K3_SMEM (SM_BLO + 65536)     // 206848

// ================== K0: transpose W ==================
__global__ void k0_transpose(const float* __restrict__ w) {
    int i = blockIdx.x * blockDim.x + threadIdx.x;
    if (i < DD * OO) { int o = i / DD, v = i % DD; g_wT[v * OO + o] = w[i]; }
}

// ================== K1: context partials (validated) ==================
__global__ void __launch_bounds__(256, 2) k1_context(const float* __restrict__ x1,
                                                     const float* __restrict__ x2) {
    __shared__ __align__(16) float Es[2][8][132];
    __shared__ __align__(16) float Xs[2][8][132];
    __shared__ float csum_s[8][128];

    const int b = blockIdx.y, ch = blockIdx.x;
    const int n0 = ch * CH1;
    const int nrows = (NN - n0 < CH1) ? (NN - n0) : CH1;
    const int nit = nrows >> 3;

    const int t = threadIdx.x;
    const int lrow = t >> 5, lq = t & 31;
    const int ty = t >> 4, tx = t & 15;
    const int ldidx = lrow * 32 + lq;

    const float4* x1p = (const float4*)(x1 + ((size_t)b * NN + n0) * DD);
    const float4* x2p = (const float4*)(x2 + ((size_t)b * NN + n0) * DD);

    u64 acc[8][4];
#pragma unroll
    for (int i = 0; i < 8; ++i)
#pragma unroll
        for (int j = 0; j < 4; ++j) acc[i][j] = 0ull;

    float4 cs = make_float4(0.f, 0.f, 0.f, 0.f);
    float4 ra = x1p[ldidx];
    float4 rb = x2p[ldidx];

    for (int it = 0; it < nit; ++it) {
        const int buf = it & 1;
        float4 ea;
        ea.x = __expf(ra.x); ea.y = __expf(ra.y); ea.z = __expf(ra.z); ea.w = __expf(ra.w);
        cs.x += ea.x; cs.y += ea.y; cs.z += ea.z; cs.w += ea.w;
        *(float4*)&Es[buf][lrow][lq * 4] = ea;
        *(float4*)&Xs[buf][lrow][lq * 4] = rb;
        __syncthreads();
        if (it + 1 < nit) {
            ra = x1p[(it + 1) * 256 + ldidx];
            rb = x2p[(it + 1) * 256 + ldidx];
        }
#pragma unroll
        for (int r = 0; r < 8; ++r) {
            const float* er = &Es[buf][r][0];
            const float* xr = &Xs[buf][r][0];
            float a[8];
            *(float4*)&a[0] = *(const float4*)(er + 4 * ty);
            *(float4*)&a[4] = *(const float4*)(er + 64 + 4 * ty);
            ulonglong2 b0 = *(const ulonglong2*)(xr + 4 * tx);
            ulonglong2 b1 = *(const ulonglong2*)(xr + 64 + 4 * tx);
#pragma unroll
            for (int i = 0; i < 8; ++i) {
                u64 s = splat2(a[i]);
                ffma2(acc[i][0], s, b0.x);
                ffma2(acc[i][1], s, b0.y);
                ffma2(acc[i][2], s, b1.x);
                ffma2(acc[i][3], s, b1.y);
            }
        }
    }

    *(float4*)&csum_s[lrow][lq * 4] = cs;
    __syncthreads();
    if (t < 128) {
        float s = 0.f;
#pragma unroll
        for (int g = 0; g < 8; ++g) s += csum_s[g][t];
        g_ksum_part[((size_t)b * NCH + ch) * DD + t] = s;
    }

    float* outp = g_ctx_part + ((size_t)b * NCH + ch) * DD * DD;
#pragma unroll
    for (int i = 0; i < 8; ++i) {
        const int d = (i < 4) ? (4 * ty + i) : (64 + 4 * ty + (i - 4));
        float* rowp = outp + (size_t)d * DD;
        ulonglong2 s01; s01.x = acc[i][0]; s01.y = acc[i][1];
        ulonglong2 s23; s23.x = acc[i][2]; s23.y = acc[i][3];
        *(ulonglong2*)(rowp + 4 * tx)      = s01;
        *(ulonglong2*)(rowp + 64 + 4 * tx) = s23;
    }
}

// ================== K2: merge, normalize, pack B-fragments bf16 hi/lo ==================
__global__ void k2_M(const float* __restrict__ bias) {
    __shared__ float ctx_s[4][128];
    __shared__ float ks_s[4];
    const int b = blockIdx.y, dg = blockIdx.x;
    const int t = threadIdx.x;

    if (t < 4) {
        float s = 0.f;
        for (int ch = 0; ch < NCH; ++ch)
            s += g_ksum_part[((size_t)b * NCH + ch) * DD + dg * 4 + t];
        ks_s[t] = 1.0f / s;
    }
    __syncthreads();

    for (int e = t; e < 512; e += 256) {
        const int d = e >> 7, v = e & 127;
        const float* p = g_ctx_part + (size_t)b * NCH * DD * DD + (size_t)(dg * 4 + d) * DD + v;
        float s = 0.f;
        for (int ch = 0; ch < NCH; ++ch) s += p[(size_t)ch * DD * DD];
        ctx_s[d][v] = s * ks_s[d];
    }
    __syncthreads();

    const float bo = bias[t];   // fold bias (softmax rows sum to 1)
    float av[4] = {bo, bo, bo, bo};
#pragma unroll 8
    for (int v = 0; v < 128; ++v) {
        const float wv = g_wT[v * OO + t];
        av[0] = fmaf(ctx_s[0][v], wv, av[0]);
        av[1] = fmaf(ctx_s[1][v], wv, av[1]);
        av[2] = fmaf(ctx_s[2][v], wv, av[2]);
        av[3] = fmaf(ctx_s[3][v], wv, av[3]);
    }

    const int o = t, nt = o >> 3, gid = o & 7;
    unsigned char* Bh = g_Bh + (size_t)b * 65536;
    unsigned char* Bl = g_Bl + (size_t)b * 65536;
#pragma unroll
    for (int d = 0; d < 4; ++d) {
        const int k = dg * 4 + d;
        const int ks = k >> 4, r = k & 15;
        const int half = r >> 3, tg = (r & 7) >> 1, pos = r & 1;
        const size_t off = ((size_t)((ks * 32 + nt) * 32 + (gid * 4 + tg))) * 8
                         + half * 4 + pos * 2;
        const __nv_bfloat16 h = __float2bfloat16(av[d]);
        const __nv_bfloat16 l = __float2bfloat16(av[d] - __bfloat162float(h));
        *(__nv_bfloat16*)(Bh + off) = h;
        *(__nv_bfloat16*)(Bl + off) = l;
    }
}

// ================== K3: cooperative 128x256 tile, 2x4 warp grid ==================
// Persistent 148 blocks over 1024 tiles; each warp = 64 rows x 64 cols, so each
// B fragment read feeds 4 A fragments (4x less smem B traffic than R8).
__global__ void __launch_bounds__(256, 1) k3_mma(const float* __restrict__ x1,
                                                 const float* __restrict__ gamma,
                                                 const float* __restrict__ beta,
                                                 float* __restrict__ out) {
    extern __shared__ __align__(16) unsigned char smem[];
    const uint32_t sb = smem_u32(smem);
    const int t = threadIdx.x, lane = t & 31, g = t >> 5;
    const int rg = g >> 2;          // row-group 0..1 (64 rows)
    const int cg = g & 3;           // col-group 0..3 (64 cols)
    const int gid = lane >> 2, tig = lane & 3;
    const int m = lane >> 3;

    ((float*)(smem + SM_GAM))[t] = gamma[t];
    ((float*)(smem + SM_BET))[t] = beta[t];

    // ldmatrix base addresses for the 4 A fragments (rows rg*64 + af*16)
    const int arow0 = rg * 64 + (m & 1) * 8 + (lane & 7);
    const uint32_t acol = (uint32_t)((m >> 1) * 16);
    uint32_t aH[4], aL[4];
#pragma unroll
    for (int af = 0; af < 4; ++af) {
        aH[af] = sb + SM_AHI + (uint32_t)(arow0 + af * 16) * 272 + acol;
        aL[af] = sb + SM_ALO + (uint32_t)(arow0 + af * 16) * 272 + acol;
    }
    const u64* Bh = (const u64*)(smem + SM_BHI);
    const u64* Bl = (const u64*)(smem + SM_BLO);
    const float2* gam2 = (const float2*)(smem + SM_GAM);
    const float2* bet2 = (const float2*)(smem + SM_BET);
    float* red_s = (float*)(smem + SM_RS);
    float* red_q = (float*)(smem + SM_RQ);
    unsigned char* Ah = smem + SM_AHI + (size_t)(g * 16) * 272;
    unsigned char* Al = smem + SM_ALO + (size_t)(g * 16) * 272;

    const int start = (blockIdx.x * 1024) / gridDim.x;
    const int end   = ((blockIdx.x + 1) * 1024) / gridDim.x;
    int curb = -1;

    for (int tile = start; tile < end; ++tile) {
        const int b = tile >> 7;
        const int n0 = (tile & 127) << 7;

        if (b != curb) {   // safe: all B reads of prev tile precede the prev sync
            const float4* sh = (const float4*)(g_Bh + (size_t)b * 65536);
            const float4* sl = (const float4*)(g_Bl + (size_t)b * 65536);
            float4* dh = (float4*)(smem + SM_BHI);
            float4* dl = (float4*)(smem + SM_BLO);
            for (int i = t; i < 4096; i += 256) { dh[i] = sh[i]; dl[i] = sl[i]; }
            curb = b;
        }

        // --- stage A: softmax over D for rows g*16..g*16+15, bf16 hi/lo ---
        const float4* xp = (const float4*)(x1 + ((size_t)b * NN + n0 + g * 16) * DD);
#pragma unroll 4
        for (int j = 0; j < 16; ++j) {
            const float4 v = xp[j * 32 + lane];
            float e0 = __expf(v.x), e1 = __expf(v.y), e2 = __expf(v.z), e3 = __expf(v.w);
            float s = e0 + e1 + e2 + e3;
#pragma unroll
            for (int mm = 16; mm; mm >>= 1) s += __shfl_xor_sync(0xffffffffu, s, mm);
            const float inv = 1.0f / s;
            e0 *= inv; e1 *= inv; e2 *= inv; e3 *= inv;
            __nv_bfloat16 h0 = __float2bfloat16(e0), h1 = __float2bfloat16(e1);
            __nv_bfloat16 h2 = __float2bfloat16(e2), h3 = __float2bfloat16(e3);
            __nv_bfloat16 l0 = __float2bfloat16(e0 - __bfloat162float(h0));
            __nv_bfloat16 l1 = __float2bfloat16(e1 - __bfloat162float(h1));
            __nv_bfloat16 l2 = __float2bfloat16(e2 - __bfloat162float(h2));
            __nv_bfloat16 l3 = __float2bfloat16(e3 - __bfloat162float(h3));
            __nv_bfloat162 hA; hA.x = h0; hA.y = h1;
            __nv_bfloat162 hB; hB.x = h2; hB.y = h3;
            __nv_bfloat162 lA; lA.x = l0; lA.y = l1;
            __nv_bfloat162 lB; lB.x = l2; lB.y = l3;
            uint2 hw; hw.x = *(uint32_t*)&hA; hw.y = *(uint32_t*)&hB;
            uint2 lw; lw.x = *(uint32_t*)&lA; lw.y = *(uint32_t*)&lB;
            *(uint2*)(Ah + j * 272 + lane * 8) = hw;
            *(uint2*)(Al + j * 272 + lane * 8) = lw;
        }
        __syncthreads();   // A (all 128 rows) + B visible to all warps

        // --- GEMM: 4 A-frags x 8 n-tiles x 8 k-steps x 3 passes ---
        float c[4][8][4];
#pragma unroll
        for (int af = 0; af < 4; ++af)
#pragma unroll
            for (int nt = 0; nt < 8; ++nt)
#pragma unroll
                for (int q = 0; q < 4; ++q) c[af][nt][q] = 0.f;

        for (int ks = 0; ks < 8; ++ks) {
            uint32_t ah[4][4], al[4][4];
#pragma unroll
            for (int af = 0; af < 4; ++af) {
                ldsm4(ah[af], aH[af] + ks * 32);
                ldsm4(al[af], aL[af] + ks * 32);
            }
            const u64* bhk = Bh + (size_t)(ks * 32 + cg * 8) * 32 + lane;
            const u64* blk = Bl + (size_t)(ks * 32 + cg * 8) * 32 + lane;
#pragma unroll
            for (int nt = 0; nt < 8; ++nt) {
                const u64 bh = bhk[nt * 32];
                const u64 bl = blk[nt * 32];
#pragma unroll
                for (int af = 0; af < 4; ++af) {
                    mma16816(c[af][nt], ah[af], bh);
                    mma16816(c[af][nt], al[af], bh);
                    mma16816(c[af][nt], ah[af], bl);
                }
            }
        }

        // --- LN partial sums (this warp's 64 cols) -> smem ---
#pragma unroll
        for (int af = 0; af < 4; ++af) {
            float sA = 0.f, sB = 0.f, qA = 0.f, qB = 0.f;
#pragma unroll
            for (int nt = 0; nt < 8; ++nt) {
                sA += c[af][nt][0] + c[af][nt][1];
                sB += c[af][nt][2] + c[af][nt][3];
                qA = fmaf(c[af][nt][0], c[af][nt][0], qA);
                qA = fmaf(c[af][nt][1], c[af][nt][1], qA);
                qB = fmaf(c[af][nt][2], c[af][nt][2], qB);
                qB = fmaf(c[af][nt][3], c[af][nt][3], qB);
            }
#pragma unroll
            for (int mm = 1; mm <= 2; mm <<= 1) {
                sA += __shfl_xor_sync(0xffffffffu, sA, mm);
                sB += __shfl_xor_sync(0xffffffffu, sB, mm);
                qA += __shfl_xor_sync(0xffffffffu, qA, mm);
                qB += __shfl_xor_sync(0xffffffffu, qB, mm);
            }
            if (tig == 0) {
                const int row = rg * 64 + af * 16 + gid;
                red_s[row * 4 + cg] = sA; red_q[row * 4 + cg] = qA;
                red_s[(row + 8) * 4 + cg] = sB; red_q[(row + 8) * 4 + cg] = qB;
            }
        }
        __syncthreads();

        // --- LN finalize + store (fixed-order 4-term sums -> deterministic) ---
#pragma unroll
        for (int af = 0; af < 4; ++af) {
            const int row = rg * 64 + af * 16 + gid;
            float4 s4 = *(float4*)&red_s[row * 4];
            float4 q4 = *(float4*)&red_q[row * 4];
            float4 s4b = *(float4*)&red_s[(row + 8) * 4];
            float4 q4b = *(float4*)&red_q[(row + 8) * 4];
            const float sA = s4.x + s4.y + s4.z + s4.w;
            const float qA = q4.x + q4.y + q4.z + q4.w;
            const float sB = s4b.x + s4b.y + s4b.z + s4b.w;
            const float qB = q4b.x + q4b.y + q4b.z + q4b.w;
            const float mA = sA * 0.00390625f, mB = sB * 0.00390625f;
            const float rA = rsqrtf(qA * 0.00390625f - mA * mA + LN_EPS);
            const float rB = rsqrtf(qB * 0.00390625f - mB * mB + LN_EPS);

            float* oA = out + ((size_t)b * NN + n0 + row) * OO;
            float* oB = oA + 8 * OO;
#pragma unroll
            for (int nt = 0; nt < 8; ++nt) {
                const int col = cg * 64 + nt * 8 + 2 * tig;
                const float2 ga = gam2[col >> 1];
                const float2 be = bet2[col >> 1];
                float2 wA, wB;
                wA.x = (c[af][nt][0] - mA) * rA * ga.x + be.x;
                wA.y = (c[af][nt][1] - mA) * rA * ga.y + be.y;
                wB.x = (c[af][nt][2] - mB) * rB * ga.x + be.x;
                wB.y = (c[af][nt][3] - mB) * rB * ga.y + be.y;
                *(float2*)(oA + col) = wA;
                *(float2*)(oB + col) = wB;
            }
        }
    }
}

extern "C" void kernel_launch(void* const* d_in, const int* in_sizes, int n_in,
                              void* d_out, int out_size) {
    const float* x1  = (const float*)d_in[0];
    const float* x2  = (const float*)d_in[1];
    const float* w   = (const float*)d_in[2];
    const float* brp = (const float*)d_in[3];
    const float* gam = (const float*)d_in[4];
    const float* bet = (const float*)d_in[5];
    float* out = (float*)d_out;

    cudaFuncSetAttribute(k3_mma, cudaFuncAttributeMaxDynamicSharedMemorySize, K3_SMEM);

    k0_transpose<<<128, 256>>>(w);
    k1_context<<<dim3(NCH, BB), 256>>>(x1, x2);
    k2_M<<<dim3(32, BB), 256>>>(brp);
    k3_mma<<<148, 256, K3_SMEM>>>(x1, gam, bet, out);
}

// round 11
// speedup vs baseline: 1.5813x; 1.1161x over previous
#include <cuda_runtime.h>
#include <cuda_bf16.h>
#include <math.h>
#include <stdint.h>

#define BB 8
#define NN 16384
#define DD 128
#define OO 256
#define CH1 448
#define NCH 37
#define LN_EPS 1e-5f

typedef unsigned long long u64;

// ---------------- scratch (device globals) ----------------
__device__ float g_ctx_part[(size_t)BB * NCH * DD * DD]; // ~19.4MB
__device__ float g_ksum_part[(size_t)BB * NCH * DD];
__device__ float g_wT[DD * OO];
// B = (ctx_norm@W^T + bias)^T in bf16 hi/lo, packed in mma B-fragment layout:
// u64 word index = ((ks*32 + ntile)*32 + (gid*4 + tig)); word = bf16 k={2t,2t+1,2t+8,2t+9}
__device__ __align__(16) unsigned char g_Bh[(size_t)BB * 65536];
__device__ __align__(16) unsigned char g_Bl[(size_t)BB * 65536];

// ---------------- f32x2 helpers (K1) ----------------
__device__ __forceinline__ u64 splat2(float a) {
    u64 r; unsigned int ai = __float_as_uint(a);
    asm("mov.b64 %0, {%1, %1};" : "=l"(r) : "r"(ai));
    return r;
}
__device__ __forceinline__ void ffma2(u64 &d, u64 a, u64 b) {
    asm("fma.rn.f32x2 %0, %1, %2, %0;" : "+l"(d) : "l"(a), "l"(b));
}

__device__ __forceinline__ uint32_t smem_u32(const void* p) {
    uint32_t a;
    asm("{ .reg .u64 t; cvta.to.shared.u64 t, %1; cvt.u32.u64 %0, t; }" : "=r"(a) : "l"(p));
    return a;
}

// mma.sync m16n8k16 row.col f32 += bf16*bf16
__device__ __forceinline__ void mma16816(float* c, const uint32_t* a, u64 b) {
    uint32_t b0 = (uint32_t)b, b1 = (uint32_t)(b >> 32);
    asm volatile(
        "mma.sync.aligned.m16n8k16.row.col.f32.bf16.bf16.f32 "
        "{%0,%1,%2,%3}, {%4,%5,%6,%7}, {%8,%9}, {%0,%1,%2,%3};"
        : "+f"(c[0]), "+f"(c[1]), "+f"(c[2]), "+f"(c[3])
        : "r"(a[0]), "r"(a[1]), "r"(a[2]), "r"(a[3]), "r"(b0), "r"(b1));
}
__device__ __forceinline__ void ldsm4(uint32_t* r, uint32_t addr) {
    asm volatile("ldmatrix.sync.aligned.m8n8.x4.shared.b16 {%0,%1,%2,%3}, [%4];"
                 : "=r"(r[0]), "=r"(r[1]), "=r"(r[2]), "=r"(r[3]) : "r"(addr));
}

// K3 smem layout (bytes)
#define SM_GAM 0
#define SM_BET 1024
#define SM_RS  2048                  // LN partial sums:   128 rows x 4 cg floats
#define SM_RQ  4096                  // LN partial squares
#define SM_AHI 6144
#define SM_ALO (SM_AHI + 34816)      // 128 rows * 272B
#define SM_BHI (SM_ALO + 34816)
#define SM_BLO (SM_BHI + 65536)
#define K3_SMEM (SM_BLO + 65536)     // 206848

// ================== K0: transpose W ==================
__global__ void k0_transpose(const float* __restrict__ w) {
    int i = blockIdx.x * blockDim.x + threadIdx.x;
    if (i < DD * OO) { int o = i / DD, v = i % DD; g_wT[v * OO + o] = w[i]; }
}

// ================== K1: context partials (validated) ==================
__global__ void __launch_bounds__(256, 2) k1_context(const float* __restrict__ x1,
                                                     const float* __restrict__ x2) {
    __shared__ __align__(16) float Es[2][8][132];
    __shared__ __align__(16) float Xs[2][8][132];
    __shared__ float csum_s[8][128];

    const int b = blockIdx.y, ch = blockIdx.x;
    const int n0 = ch * CH1;
    const int nrows = (NN - n0 < CH1) ? (NN - n0) : CH1;
    const int nit = nrows >> 3;

    const int t = threadIdx.x;
    const int lrow = t >> 5, lq = t & 31;
    const int ty = t >> 4, tx = t & 15;
    const int ldidx = lrow * 32 + lq;

    const float4* x1p = (const float4*)(x1 + ((size_t)b * NN + n0) * DD);
    const float4* x2p = (const float4*)(x2 + ((size_t)b * NN + n0) * DD);

    u64 acc[8][4];
#pragma unroll
    for (int i = 0; i < 8; ++i)
#pragma unroll
        for (int j = 0; j < 4; ++j) acc[i][j] = 0ull;

    float4 cs = make_float4(0.f, 0.f, 0.f, 0.f);
    float4 ra = x1p[ldidx];
    float4 rb = x2p[ldidx];

    for (int it = 0; it < nit; ++it) {
        const int buf = it & 1;
        float4 ea;
        ea.x = __expf(ra.x); ea.y = __expf(ra.y); ea.z = __expf(ra.z); ea.w = __expf(ra.w);
        cs.x += ea.x; cs.y += ea.y; cs.z += ea.z; cs.w += ea.w;
        *(float4*)&Es[buf][lrow][lq * 4] = ea;
        *(float4*)&Xs[buf][lrow][lq * 4] = rb;
        __syncthreads();
        if (it + 1 < nit) {
            ra = x1p[(it + 1) * 256 + ldidx];
            rb = x2p[(it + 1) * 256 + ldidx];
        }
#pragma unroll
        for (int r = 0; r < 8; ++r) {
            const float* er = &Es[buf][r][0];
            const float* xr = &Xs[buf][r][0];
            float a[8];
            *(float4*)&a[0] = *(const float4*)(er + 4 * ty);
            *(float4*)&a[4] = *(const float4*)(er + 64 + 4 * ty);
            ulonglong2 b0 = *(const ulonglong2*)(xr + 4 * tx);
            ulonglong2 b1 = *(const ulonglong2*)(xr + 64 + 4 * tx);
#pragma unroll
            for (int i = 0; i < 8; ++i) {
                u64 s = splat2(a[i]);
                ffma2(acc[i][0], s, b0.x);
                ffma2(acc[i][1], s, b0.y);
                ffma2(acc[i][2], s, b1.x);
                ffma2(acc[i][3], s, b1.y);
            }
        }
    }

    *(float4*)&csum_s[lrow][lq * 4] = cs;
    __syncthreads();
    if (t < 128) {
        float s = 0.f;
#pragma unroll
        for (int g = 0; g < 8; ++g) s += csum_s[g][t];
        g_ksum_part[((size_t)b * NCH + ch) * DD + t] = s;
    }

    float* outp = g_ctx_part + ((size_t)b * NCH + ch) * DD * DD;
#pragma unroll
    for (int i = 0; i < 8; ++i) {
        const int d = (i < 4) ? (4 * ty + i) : (64 + 4 * ty + (i - 4));
        float* rowp = outp + (size_t)d * DD;
        ulonglong2 s01; s01.x = acc[i][0]; s01.y = acc[i][1];
        ulonglong2 s23; s23.x = acc[i][2]; s23.y = acc[i][3];
        *(ulonglong2*)(rowp + 4 * tx)      = s01;
        *(ulonglong2*)(rowp + 64 + 4 * tx) = s23;
    }
}

// ================== K2: merge, normalize, pack B-fragments bf16 hi/lo ==================
__global__ void k2_M(const float* __restrict__ bias) {
    __shared__ float ctx_s[4][128];
    __shared__ float ks_s[4];
    const int b = blockIdx.y, dg = blockIdx.x;
    const int t = threadIdx.x;

    if (t < 4) {
        float s = 0.f;
        for (int ch = 0; ch < NCH; ++ch)
            s += g_ksum_part[((size_t)b * NCH + ch) * DD + dg * 4 + t];
        ks_s[t] = 1.0f / s;
    }
    __syncthreads();

    for (int e = t; e < 512; e += 256) {
        const int d = e >> 7, v = e & 127;
        const float* p = g_ctx_part + (size_t)b * NCH * DD * DD + (size_t)(dg * 4 + d) * DD + v;
        float s = 0.f;
        for (int ch = 0; ch < NCH; ++ch) s += p[(size_t)ch * DD * DD];
        ctx_s[d][v] = s * ks_s[d];
    }
    __syncthreads();

    const float bo = bias[t];   // fold bias (softmax rows sum to 1)
    float av[4] = {bo, bo, bo, bo};
#pragma unroll 8
    for (int v = 0; v < 128; ++v) {
        const float wv = g_wT[v * OO + t];
        av[0] = fmaf(ctx_s[0][v], wv, av[0]);
        av[1] = fmaf(ctx_s[1][v], wv, av[1]);
        av[2] = fmaf(ctx_s[2][v], wv, av[2]);
        av[3] = fmaf(ctx_s[3][v], wv, av[3]);
    }

    const int o = t, nt = o >> 3, gid = o & 7;
    unsigned char* Bh = g_Bh + (size_t)b * 65536;
    unsigned char* Bl = g_Bl + (size_t)b * 65536;
#pragma unroll
    for (int d = 0; d < 4; ++d) {
        const int k = dg * 4 + d;
        const int ks = k >> 4, r = k & 15;
        const int half = r >> 3, tg = (r & 7) >> 1, pos = r & 1;
        const size_t off = ((size_t)((ks * 32 + nt) * 32 + (gid * 4 + tg))) * 8
                         + half * 4 + pos * 2;
        const __nv_bfloat16 h = __float2bfloat16(av[d]);
        const __nv_bfloat16 l = __float2bfloat16(av[d] - __bfloat162float(h));
        *(__nv_bfloat16*)(Bh + off) = h;
        *(__nv_bfloat16*)(Bl + off) = l;
    }
}

// ================== K3: cooperative 128x256 tile, 4x4 warp grid, 512 threads ==================
// 16 warps (4/SMSP) so LDG staging + LDSM/HMMA latency is hidden by warp slip.
// Each warp = 32 rows x 64 cols (2 A frags x 8 n-tiles).
__global__ void __launch_bounds__(512, 1) k3_mma(const float* __restrict__ x1,
                                                 const float* __restrict__ gamma,
                                                 const float* __restrict__ beta,
                                                 float* __restrict__ out) {
    extern __shared__ __align__(16) unsigned char smem[];
    const uint32_t sb = smem_u32(smem);
    const int t = threadIdx.x, lane = t & 31, g = t >> 5;
    const int rg = g >> 2;          // row-group 0..3 (32 rows)
    const int cg = g & 3;           // col-group 0..3 (64 cols)
    const int gid = lane >> 2, tig = lane & 3;
    const int m = lane >> 3;

    if (t < 256) {
        ((float*)(smem + SM_GAM))[t] = gamma[t];
        ((float*)(smem + SM_BET))[t] = beta[t];
    }

    // ldmatrix base addresses for the 2 A fragments (rows rg*32 + af*16)
    const int arow0 = rg * 32 + (m & 1) * 8 + (lane & 7);
    const uint32_t acol = (uint32_t)((m >> 1) * 16);
    uint32_t aH[2], aL[2];
#pragma unroll
    for (int af = 0; af < 2; ++af) {
        aH[af] = sb + SM_AHI + (uint32_t)(arow0 + af * 16) * 272 + acol;
        aL[af] = sb + SM_ALO + (uint32_t)(arow0 + af * 16) * 272 + acol;
    }
    const u64* Bh = (const u64*)(smem + SM_BHI);
    const u64* Bl = (const u64*)(smem + SM_BLO);
    const float2* gam2 = (const float2*)(smem + SM_GAM);
    const float2* bet2 = (const float2*)(smem + SM_BET);
    float* red_s = (float*)(smem + SM_RS);
    float* red_q = (float*)(smem + SM_RQ);
    unsigned char* Ah = smem + SM_AHI + (size_t)(g * 8) * 272;
    unsigned char* Al = smem + SM_ALO + (size_t)(g * 8) * 272;

    const int start = (blockIdx.x * 1024) / gridDim.x;
    const int end   = ((blockIdx.x + 1) * 1024) / gridDim.x;
    int curb = -1;

    for (int tile = start; tile < end; ++tile) {
        const int b = tile >> 7;
        const int n0 = (tile & 127) << 7;

        if (b != curb) {   // safe: all B reads of prev tile precede the prev sync
            const float4* sh = (const float4*)(g_Bh + (size_t)b * 65536);
            const float4* sl = (const float4*)(g_Bl + (size_t)b * 65536);
            float4* dh = (float4*)(smem + SM_BHI);
            float4* dl = (float4*)(smem + SM_BLO);
            for (int i = t; i < 4096; i += 512) { dh[i] = sh[i]; dl[i] = sl[i]; }
            curb = b;
        }

        // --- stage A: softmax over D for rows g*8..g*8+7, bf16 hi/lo ---
        const float4* xp = (const float4*)(x1 + ((size_t)b * NN + n0 + g * 8) * DD);
#pragma unroll 4
        for (int j = 0; j < 8; ++j) {
            const float4 v = xp[j * 32 + lane];
            float e0 = __expf(v.x), e1 = __expf(v.y), e2 = __expf(v.z), e3 = __expf(v.w);
            float s = e0 + e1 + e2 + e3;
#pragma unroll
            for (int mm = 16; mm; mm >>= 1) s += __shfl_xor_sync(0xffffffffu, s, mm);
            const float inv = 1.0f / s;
            e0 *= inv; e1 *= inv; e2 *= inv; e3 *= inv;
            __nv_bfloat16 h0 = __float2bfloat16(e0), h1 = __float2bfloat16(e1);
            __nv_bfloat16 h2 = __float2bfloat16(e2), h3 = __float2bfloat16(e3);
            __nv_bfloat16 l0 = __float2bfloat16(e0 - __bfloat162float(h0));
            __nv_bfloat16 l1 = __float2bfloat16(e1 - __bfloat162float(h1));
            __nv_bfloat16 l2 = __float2bfloat16(e2 - __bfloat162float(h2));
            __nv_bfloat16 l3 = __float2bfloat16(e3 - __bfloat162float(h3));
            __nv_bfloat162 hA; hA.x = h0; hA.y = h1;
            __nv_bfloat162 hB; hB.x = h2; hB.y = h3;
            __nv_bfloat162 lA; lA.x = l0; lA.y = l1;
            __nv_bfloat162 lB; lB.x = l2; lB.y = l3;
            uint2 hw; hw.x = *(uint32_t*)&hA; hw.y = *(uint32_t*)&hB;
            uint2 lw; lw.x = *(uint32_t*)&lA; lw.y = *(uint32_t*)&lB;
            *(uint2*)(Ah + j * 272 + lane * 8) = hw;
            *(uint2*)(Al + j * 272 + lane * 8) = lw;
        }
        __syncthreads();   // A (all 128 rows) + B visible to all warps

        // --- GEMM: 2 A-frags x 8 n-tiles x 8 k-steps x 3 passes ---
        float c[2][8][4];
#pragma unroll
        for (int af = 0; af < 2; ++af)
#pragma unroll
            for (int nt = 0; nt < 8; ++nt)
#pragma unroll
                for (int q = 0; q < 4; ++q) c[af][nt][q] = 0.f;

        for (int ks = 0; ks < 8; ++ks) {
            uint32_t ah[2][4], al[2][4];
#pragma unroll
            for (int af = 0; af < 2; ++af) {
                ldsm4(ah[af], aH[af] + ks * 32);
                ldsm4(al[af], aL[af] + ks * 32);
            }
            const u64* bhk = Bh + (size_t)(ks * 32 + cg * 8) * 32 + lane;
            const u64* blk = Bl + (size_t)(ks * 32 + cg * 8) * 32 + lane;
#pragma unroll
            for (int nt = 0; nt < 8; ++nt) {
                const u64 bh = bhk[nt * 32];
                const u64 bl = blk[nt * 32];
#pragma unroll
                for (int af = 0; af < 2; ++af) {
                    mma16816(c[af][nt], ah[af], bh);
                    mma16816(c[af][nt], al[af], bh);
                    mma16816(c[af][nt], ah[af], bl);
                }
            }
        }

        // --- LN partial sums (this warp's 64 cols) -> smem ---
#pragma unroll
        for (int af = 0; af < 2; ++af) {
            float sA = 0.f, sB = 0.f, qA = 0.f, qB = 0.f;
#pragma unroll
            for (int nt = 0; nt < 8; ++nt) {
                sA += c[af][nt][0] + c[af][nt][1];
                sB += c[af][nt][2] + c[af][nt][3];
                qA = fmaf(c[af][nt][0], c[af][nt][0], qA);
                qA = fmaf(c[af][nt][1], c[af][nt][1], qA);
                qB = fmaf(c[af][nt][2], c[af][nt][2], qB);
                qB = fmaf(c[af][nt][3], c[af][nt][3], qB);
            }
#pragma unroll
            for (int mm = 1; mm <= 2; mm <<= 1) {
                sA += __shfl_xor_sync(0xffffffffu, sA, mm);
                sB += __shfl_xor_sync(0xffffffffu, sB, mm);
                qA += __shfl_xor_sync(0xffffffffu, qA, mm);
                qB += __shfl_xor_sync(0xffffffffu, qB, mm);
            }
            if (tig == 0) {
                const int row = rg * 32 + af * 16 + gid;
                red_s[row * 4 + cg] = sA; red_q[row * 4 + cg] = qA;
                red_s[(row + 8) * 4 + cg] = sB; red_q[(row + 8) * 4 + cg] = qB;
            }
        }
        __syncthreads();

        // --- LN finalize + store (fixed-order 4-term sums -> deterministic) ---
#pragma unroll
        for (int af = 0; af < 2; ++af) {
            const int row = rg * 32 + af * 16 + gid;
            float4 s4 = *(float4*)&red_s[row * 4];
            float4 q4 = *(float4*)&red_q[row * 4];
            float4 s4b = *(float4*)&red_s[(row + 8) * 4];
            float4 q4b = *(float4*)&red_q[(row + 8) * 4];
            const float sA = s4.x + s4.y + s4.z + s4.w;
            const float qA = q4.x + q4.y + q4.z + q4.w;
            const float sB = s4b.x + s4b.y + s4b.z + s4b.w;
            const float qB = q4b.x + q4b.y + q4b.z + q4b.w;
            const float mA = sA * 0.00390625f, mB = sB * 0.00390625f;
            const float rA = rsqrtf(qA * 0.00390625f - mA * mA + LN_EPS);
            const float rB = rsqrtf(qB * 0.00390625f - mB * mB + LN_EPS);

            float* oA = out + ((size_t)b * NN + n0 + row) * OO;
            float* oB = oA + 8 * OO;
#pragma unroll
            for (int nt = 0; nt < 8; ++nt) {
                const int col = cg * 64 + nt * 8 + 2 * tig;
                const float2 ga = gam2[col >> 1];
                const float2 be = bet2[col >> 1];
                float2 wA, wB;
                wA.x = (c[af][nt][0] - mA) * rA * ga.x + be.x;
                wA.y = (c[af][nt][1] - mA) * rA * ga.y + be.y;
                wB.x = (c[af][nt][2] - mB) * rB * ga.x + be.x;
                wB.y = (c[af][nt][3] - mB) * rB * ga.y + be.y;
                *(float2*)(oA + col) = wA;
                *(float2*)(oB + col) = wB;
            }
        }
    }
}

extern "C" void kernel_launch(void* const* d_in, const int* in_sizes, int n_in,
                              void* d_out, int out_size) {
    const float* x1  = (const float*)d_in[0];
    const float* x2  = (const float*)d_in[1];
    const float* w   = (const float*)d_in[2];
    const float* brp = (const float*)d_in[3];
    const float* gam = (const float*)d_in[4];
    const float* bet = (const float*)d_in[5];
    float* out = (float*)d_out;

    cudaFuncSetAttribute(k3_mma, cudaFuncAttributeMaxDynamicSharedMemorySize, K3_SMEM);

    k0_transpose<<<128, 256>>>(w);
    k1_context<<<dim3(NCH, BB), 256>>>(x1, x2);
    k2_M<<<dim3(32, BB), 256>>>(brp);
    k3_mma<<<148, 512, K3_SMEM>>>(x1, gam, bet, out);
}

// round 12
// speedup vs baseline: 1.7328x; 1.0958x over previous
#include <cuda_runtime.h>
#include <cuda_bf16.h>
#include <math.h>
#include <stdint.h>

#define BB 8
#define NN 16384
#define DD 128
#define OO 256
#define SPL 16                 // K1 n-splits per batch
#define LN_EPS 1e-5f

typedef unsigned long long u64;

// ---------------- scratch (device globals) ----------------
__device__ float g_ctx_part[(size_t)BB * SPL * DD * DD];   // 8MB
__device__ float g_ksum_part[(size_t)BB * SPL * DD];
__device__ float g_wT[DD * OO];
// B = (ctx_norm@W^T + bias)^T in bf16 hi/lo, packed in mma B-fragment layout
__device__ __align__(16) unsigned char g_Bh[(size_t)BB * 65536];
__device__ __align__(16) unsigned char g_Bl[(size_t)BB * 65536];

__device__ __forceinline__ uint32_t smem_u32(const void* p) {
    uint32_t a;
    asm("{ .reg .u64 t; cvta.to.shared.u64 t, %1; cvt.u32.u64 %0, t; }" : "=r"(a) : "l"(p));
    return a;
}

// mma.sync m16n8k16 row.col f32 += bf16*bf16
__device__ __forceinline__ void mma16816(float* c, const uint32_t* a, u64 b) {
    uint32_t b0 = (uint32_t)b, b1 = (uint32_t)(b >> 32);
    asm volatile(
        "mma.sync.aligned.m16n8k16.row.col.f32.bf16.bf16.f32 "
        "{%0,%1,%2,%3}, {%4,%5,%6,%7}, {%8,%9}, {%0,%1,%2,%3};"
        : "+f"(c[0]), "+f"(c[1]), "+f"(c[2]), "+f"(c[3])
        : "r"(a[0]), "r"(a[1]), "r"(a[2]), "r"(a[3]), "r"(b0), "r"(b1));
}
__device__ __forceinline__ void mma_b2(float* c, const uint32_t* a, uint32_t b0, uint32_t b1) {
    asm volatile(
        "mma.sync.aligned.m16n8k16.row.col.f32.bf16.bf16.f32 "
        "{%0,%1,%2,%3}, {%4,%5,%6,%7}, {%8,%9}, {%0,%1,%2,%3};"
        : "+f"(c[0]), "+f"(c[1]), "+f"(c[2]), "+f"(c[3])
        : "r"(a[0]), "r"(a[1]), "r"(a[2]), "r"(a[3]), "r"(b0), "r"(b1));
}
__device__ __forceinline__ void ldsm4(uint32_t* r, uint32_t addr) {
    asm volatile("ldmatrix.sync.aligned.m8n8.x4.shared.b16 {%0,%1,%2,%3}, [%4];"
                 : "=r"(r[0]), "=r"(r[1]), "=r"(r[2]), "=r"(r[3]) : "r"(addr));
}
__device__ __forceinline__ void ldsm4t(uint32_t* r, uint32_t addr) {
    asm volatile("ldmatrix.sync.aligned.m8n8.x4.trans.shared.b16 {%0,%1,%2,%3}, [%4];"
                 : "=r"(r[0]), "=r"(r[1]), "=r"(r[2]), "=r"(r[3]) : "r"(addr));
}
__device__ __forceinline__ uint32_t bf2_hi(float a, float b) {
    __nv_bfloat162 h; h.x = __float2bfloat16(a); h.y = __float2bfloat16(b);
    return *(uint32_t*)&h;
}

// ================== K0: transpose W ==================
__global__ void k0_transpose(const float* __restrict__ w) {
    int i = blockIdx.x * blockDim.x + threadIdx.x;
    if (i < DD * OO) { int o = i / DD, v = i % DD; g_wT[v * OO + o] = w[i]; }
}

// ================== K1: context via mma.sync bf16-split ==================
// C[d][v] = sum_n exp(x1[n,d]) * x2[n,v]. Both operands transposed into k=n
// by ldmatrix.x4.trans from natural [n][.] smem layout (272B row stride).
// Block: 512 thr, 4x4 warp grid, full 128x128 C in regs, 8 chunks of 128 n.
#define K1R 272                        // row stride bytes (136 bf16)
#define SM1_EH 0
#define SM1_EL 34816
#define SM1_XH 69632
#define SM1_XL 104448
#define SM1_CS 139264                  // float[16][128]
#define K1_SMEM (SM1_CS + 8192)        // 147456

__global__ void __launch_bounds__(512, 1) k1_mma(const float* __restrict__ x1,
                                                 const float* __restrict__ x2) {
    extern __shared__ __align__(16) unsigned char smem[];
    const uint32_t sb = smem_u32(smem);
    const int t = threadIdx.x, lane = t & 31, g = t >> 5;
    const int mg = g >> 2, cgn = g & 3;
    const int gid = lane >> 2, tig = lane & 3;
    const int b = blockIdx.y, split = blockIdx.x;
    const int base_n = split * (NN / SPL);

    // ldmatrix.trans lane addressing (same pattern for A and B)
    const int row_l = (lane & 7) + ((lane >> 4) << 3);
    const int colsel = ((lane >> 3) & 1) << 3;
    uint32_t aoff[2], boff[2];
#pragma unroll
    for (int af = 0; af < 2; ++af)
        aoff[af] = (uint32_t)(row_l * K1R + (mg * 32 + af * 16 + colsel) * 2);
#pragma unroll
    for (int pr = 0; pr < 2; ++pr)
        boff[pr] = (uint32_t)(row_l * K1R + (cgn * 32 + pr * 16 + colsel) * 2);

    float c[2][4][4];
#pragma unroll
    for (int af = 0; af < 2; ++af)
#pragma unroll
        for (int nt = 0; nt < 4; ++nt)
#pragma unroll
            for (int q = 0; q < 4; ++q) c[af][nt][q] = 0.f;

    float4 cs = make_float4(0.f, 0.f, 0.f, 0.f);
    const int sr = g * 8;   // staging rows sr..sr+7
    unsigned char* Eh = smem + SM1_EH + (size_t)sr * K1R;
    unsigned char* El = smem + SM1_EL + (size_t)sr * K1R;
    unsigned char* Xh = smem + SM1_XH + (size_t)sr * K1R;
    unsigned char* Xl = smem + SM1_XL + (size_t)sr * K1R;

    for (int ch = 0; ch < 8; ++ch) {
        const int n0 = base_n + ch * 128;
        const float4* x1p = (const float4*)(x1 + ((size_t)b * NN + n0 + sr) * DD);
        const float4* x2p = (const float4*)(x2 + ((size_t)b * NN + n0 + sr) * DD);

        // --- stage: exp(x1)->E hi/lo, x2->X hi/lo (bf16 split) ---
#pragma unroll 2
        for (int j = 0; j < 8; ++j) {
            const float4 v1 = x1p[j * 32 + lane];
            const float4 v2 = x2p[j * 32 + lane];
            float e0 = __expf(v1.x), e1 = __expf(v1.y), e2 = __expf(v1.z), e3 = __expf(v1.w);
            cs.x += e0; cs.y += e1; cs.z += e2; cs.w += e3;
            uint2 ehw, elw, xhw, xlw;
            ehw.x = bf2_hi(e0, e1); ehw.y = bf2_hi(e2, e3);
            {
                __nv_bfloat162* hp = (__nv_bfloat162*)&ehw;
                elw.x = bf2_hi(e0 - __bfloat162float(hp[0].x), e1 - __bfloat162float(hp[0].y));
                elw.y = bf2_hi(e2 - __bfloat162float(hp[1].x), e3 - __bfloat162float(hp[1].y));
            }
            xhw.x = bf2_hi(v2.x, v2.y); xhw.y = bf2_hi(v2.z, v2.w);
            {
                __nv_bfloat162* hp = (__nv_bfloat162*)&xhw;
                xlw.x = bf2_hi(v2.x - __bfloat162float(hp[0].x), v2.y - __bfloat162float(hp[0].y));
                xlw.y = bf2_hi(v2.z - __bfloat162float(hp[1].x), v2.w - __bfloat162float(hp[1].y));
            }
            const int so = j * K1R + lane * 8;
            *(uint2*)(Eh + so) = ehw;
            *(uint2*)(El + so) = elw;
            *(uint2*)(Xh + so) = xhw;
            *(uint2*)(Xl + so) = xlw;
        }
        __syncthreads();

        // --- MMA: 8 k-steps x (2 af x 4 nt) x 3 passes ---
#pragma unroll
        for (int ks = 0; ks < 8; ++ks) {
            const uint32_t ro = (uint32_t)(ks * 16 * K1R);
            uint32_t ah[2][4], al[2][4], bh[2][4], bl[2][4];
#pragma unroll
            for (int af = 0; af < 2; ++af) {
                ldsm4t(ah[af], sb + SM1_EH + aoff[af] + ro);
                ldsm4t(al[af], sb + SM1_EL + aoff[af] + ro);
            }
#pragma unroll
            for (int pr = 0; pr < 2; ++pr) {
                ldsm4t(bh[pr], sb + SM1_XH + boff[pr] + ro);
                ldsm4t(bl[pr], sb + SM1_XL + boff[pr] + ro);
            }
#pragma unroll
            for (int af = 0; af < 2; ++af)
#pragma unroll
                for (int pr = 0; pr < 2; ++pr)
#pragma unroll
                    for (int sub = 0; sub < 2; ++sub) {
                        const int nt = pr * 2 + sub;
                        mma_b2(c[af][nt], ah[af], bh[pr][sub], bh[pr][sub + 2]);
                        mma_b2(c[af][nt], al[af], bh[pr][sub], bh[pr][sub + 2]);
                        mma_b2(c[af][nt], ah[af], bl[pr][sub], bl[pr][sub + 2]);
                    }
        }
        __syncthreads();
    }

    // --- write 128x128 C partial ---
    float* outp = g_ctx_part + ((size_t)(b * SPL + split)) * DD * DD;
#pragma unroll
    for (int af = 0; af < 2; ++af) {
        const int d0 = mg * 32 + af * 16 + gid;
#pragma unroll
        for (int nt = 0; nt < 4; ++nt) {
            const int v = cgn * 32 + nt * 8 + 2 * tig;
            *(float2*)(outp + (size_t)d0 * DD + v) = make_float2(c[af][nt][0], c[af][nt][1]);
            *(float2*)(outp + (size_t)(d0 + 8) * DD + v) = make_float2(c[af][nt][2], c[af][nt][3]);
        }
    }

    // --- column exp-sum partial (fixed order) ---
    float* csum = (float*)(smem + SM1_CS);
    *(float4*)&csum[g * 128 + 4 * lane] = cs;
    __syncthreads();
    if (t < 128) {
        float s = 0.f;
#pragma unroll
        for (int k = 0; k < 16; ++k) s += csum[k * 128 + t];
        g_ksum_part[((size_t)(b * SPL + split)) * DD + t] = s;
    }
}

// ================== K2: merge, normalize, pack B-fragments bf16 hi/lo ==================
__global__ void k2_M(const float* __restrict__ bias) {
    __shared__ float ctx_s[4][128];
    __shared__ float ks_s[4];
    const int b = blockIdx.y, dg = blockIdx.x;
    const int t = threadIdx.x;

    if (t < 4) {
        float s = 0.f;
        for (int ch = 0; ch < SPL; ++ch)
            s += g_ksum_part[((size_t)(b * SPL + ch)) * DD + dg * 4 + t];
        ks_s[t] = 1.0f / s;
    }
    __syncthreads();

    for (int e = t; e < 512; e += 256) {
        const int d = e >> 7, v = e & 127;
        const float* p = g_ctx_part + (size_t)b * SPL * DD * DD + (size_t)(dg * 4 + d) * DD + v;
        float s = 0.f;
        for (int ch = 0; ch < SPL; ++ch) s += p[(size_t)ch * DD * DD];
        ctx_s[d][v] = s * ks_s[d];
    }
    __syncthreads();

    const float bo = bias[t];   // fold bias (softmax rows sum to 1)
    float av[4] = {bo, bo, bo, bo};
#pragma unroll 8
    for (int v = 0; v < 128; ++v) {
        const float wv = g_wT[v * OO + t];
        av[0] = fmaf(ctx_s[0][v], wv, av[0]);
        av[1] = fmaf(ctx_s[1][v], wv, av[1]);
        av[2] = fmaf(ctx_s[2][v], wv, av[2]);
        av[3] = fmaf(ctx_s[3][v], wv, av[3]);
    }

    const int nt = t >> 3, gid = t & 7;
    unsigned char* Bh = g_Bh + (size_t)b * 65536;
    unsigned char* Bl = g_Bl + (size_t)b * 65536;
#pragma unroll
    for (int d = 0; d < 4; ++d) {
        const int k = dg * 4 + d;
        const int ks = k >> 4, r = k & 15;
        const int half = r >> 3, tg = (r & 7) >> 1, pos = r & 1;
        const size_t off = ((size_t)((ks * 32 + nt) * 32 + (gid * 4 + tg))) * 8
                         + half * 4 + pos * 2;
        const __nv_bfloat16 h = __float2bfloat16(av[d]);
        const __nv_bfloat16 l = __float2bfloat16(av[d] - __bfloat162float(h));
        *(__nv_bfloat16*)(Bh + off) = h;
        *(__nv_bfloat16*)(Bl + off) = l;
    }
}

// K3 smem layout (bytes)
#define SM_GAM 0
#define SM_BET 1024
#define SM_RS  2048
#define SM_RQ  4096
#define SM_AHI 6144
#define SM_ALO (SM_AHI + 34816)
#define SM_BHI (SM_ALO + 34816)
#define SM_BLO (SM_BHI + 65536)
#define K3_SMEM (SM_BLO + 65536)     // 206848

// ================== K3: cooperative 128x256 tile, 4x4 warp grid, 512 threads ==================
__global__ void __launch_bounds__(512, 1) k3_mma(const float* __restrict__ x1,
                                                 const float* __restrict__ gamma,
                                                 const float* __restrict__ beta,
                                                 float* __restrict__ out) {
    extern __shared__ __align__(16) unsigned char smem[];
    const uint32_t sb = smem_u32(smem);
    const int t = threadIdx.x, lane = t & 31, g = t >> 5;
    const int rg = g >> 2;
    const int cg = g & 3;
    const int gid = lane >> 2, tig = lane & 3;
    const int m = lane >> 3;

    if (t < 256) {
        ((float*)(smem + SM_GAM))[t] = gamma[t];
        ((float*)(smem + SM_BET))[t] = beta[t];
    }

    const int arow0 = rg * 32 + (m & 1) * 8 + (lane & 7);
    const uint32_t acol = (uint32_t)((m >> 1) * 16);
    uint32_t aH[2], aL[2];
#pragma unroll
    for (int af = 0; af < 2; ++af) {
        aH[af] = sb + SM_AHI + (uint32_t)(arow0 + af * 16) * 272 + acol;
        aL[af] = sb + SM_ALO + (uint32_t)(arow0 + af * 16) * 272 + acol;
    }
    const u64* Bh = (const u64*)(smem + SM_BHI);
    const u64* Bl = (const u64*)(smem + SM_BLO);
    const float2* gam2 = (const float2*)(smem + SM_GAM);
    const float2* bet2 = (const float2*)(smem + SM_BET);
    float* red_s = (float*)(smem + SM_RS);
    float* red_q = (float*)(smem + SM_RQ);
    unsigned char* Ah = smem + SM_AHI + (size_t)(g * 8) * 272;
    unsigned char* Al = smem + SM_ALO + (size_t)(g * 8) * 272;

    const int start = (blockIdx.x * 1024) / gridDim.x;
    const int end   = ((blockIdx.x + 1) * 1024) / gridDim.x;
    int curb = -1;

    for (int tile = start; tile < end; ++tile) {
        const int b = tile >> 7;
        const int n0 = (tile & 127) << 7;

        if (b != curb) {
            const float4* sh = (const float4*)(g_Bh + (size_t)b * 65536);
            const float4* sl = (const float4*)(g_Bl + (size_t)b * 65536);
            float4* dh = (float4*)(smem + SM_BHI);
            float4* dl = (float4*)(smem + SM_BLO);
            for (int i = t; i < 4096; i += 512) { dh[i] = sh[i]; dl[i] = sl[i]; }
            curb = b;
        }

        const float4* xp = (const float4*)(x1 + ((size_t)b * NN + n0 + g * 8) * DD);
#pragma unroll 4
        for (int j = 0; j < 8; ++j) {
            const float4 v = xp[j * 32 + lane];
            float e0 = __expf(v.x), e1 = __expf(v.y), e2 = __expf(v.z), e3 = __expf(v.w);
            float s = e0 + e1 + e2 + e3;
#pragma unroll
            for (int mm = 16; mm; mm >>= 1) s += __shfl_xor_sync(0xffffffffu, s, mm);
            const float inv = 1.0f / s;
            e0 *= inv; e1 *= inv; e2 *= inv; e3 *= inv;
            uint2 hw, lw;
            hw.x = bf2_hi(e0, e1); hw.y = bf2_hi(e2, e3);
            {
                __nv_bfloat162* hp = (__nv_bfloat162*)&hw;
                lw.x = bf2_hi(e0 - __bfloat162float(hp[0].x), e1 - __bfloat162float(hp[0].y));
                lw.y = bf2_hi(e2 - __bfloat162float(hp[1].x), e3 - __bfloat162float(hp[1].y));
            }
            *(uint2*)(Ah + j * 272 + lane * 8) = hw;
            *(uint2*)(Al + j * 272 + lane * 8) = lw;
        }
        __syncthreads();

        float c[2][8][4];
#pragma unroll
        for (int af = 0; af < 2; ++af)
#pragma unroll
            for (int nt = 0; nt < 8; ++nt)
#pragma unroll
                for (int q = 0; q < 4; ++q) c[af][nt][q] = 0.f;

        for (int ks = 0; ks < 8; ++ks) {
            uint32_t ah[2][4], al[2][4];
#pragma unroll
            for (int af = 0; af < 2; ++af) {
                ldsm4(ah[af], aH[af] + ks * 32);
                ldsm4(al[af], aL[af] + ks * 32);
            }
            const u64* bhk = Bh + (size_t)(ks * 32 + cg * 8) * 32 + lane;
            const u64* blk = Bl + (size_t)(ks * 32 + cg * 8) * 32 + lane;
#pragma unroll
            for (int nt = 0; nt < 8; ++nt) {
                const u64 bh = bhk[nt * 32];
                const u64 bl = blk[nt * 32];
#pragma unroll
                for (int af = 0; af < 2; ++af) {
                    mma16816(c[af][nt], ah[af], bh);
                    mma16816(c[af][nt], al[af], bh);
                    mma16816(c[af][nt], ah[af], bl);
                }
            }
        }

#pragma unroll
        for (int af = 0; af < 2; ++af) {
            float sA = 0.f, sB = 0.f, qA = 0.f, qB = 0.f;
#pragma unroll
            for (int nt = 0; nt < 8; ++nt) {
                sA += c[af][nt][0] + c[af][nt][1];
                sB += c[af][nt][2] + c[af][nt][3];
                qA = fmaf(c[af][nt][0], c[af][nt][0], qA);
                qA = fmaf(c[af][nt][1], c[af][nt][1], qA);
                qB = fmaf(c[af][nt][2], c[af][nt][2], qB);
                qB = fmaf(c[af][nt][3], c[af][nt][3], qB);
            }
#pragma unroll
            for (int mm = 1; mm <= 2; mm <<= 1) {
                sA += __shfl_xor_sync(0xffffffffu, sA, mm);
                sB += __shfl_xor_sync(0xffffffffu, sB, mm);
                qA += __shfl_xor_sync(0xffffffffu, qA, mm);
                qB += __shfl_xor_sync(0xffffffffu, qB, mm);
            }
            if (tig == 0) {
                const int row = rg * 32 + af * 16 + gid;
                red_s[row * 4 + cg] = sA; red_q[row * 4 + cg] = qA;
                red_s[(row + 8) * 4 + cg] = sB; red_q[(row + 8) * 4 + cg] = qB;
            }
        }
        __syncthreads();

#pragma unroll
        for (int af = 0; af < 2; ++af) {
            const int row = rg * 32 + af * 16 + gid;
            float4 s4 = *(float4*)&red_s[row * 4];
            float4 q4 = *(float4*)&red_q[row * 4];
            float4 s4b = *(float4*)&red_s[(row + 8) * 4];
            float4 q4b = *(float4*)&red_q[(row + 8) * 4];
            const float sA = s4.x + s4.y + s4.z + s4.w;
            const float qA = q4.x + q4.y + q4.z + q4.w;
            const float sB = s4b.x + s4b.y + s4b.z + s4b.w;
            const float qB = q4b.x + q4b.y + q4b.z + q4b.w;
            const float mA = sA * 0.00390625f, mB = sB * 0.00390625f;
            const float rA = rsqrtf(qA * 0.00390625f - mA * mA + LN_EPS);
            const float rB = rsqrtf(qB * 0.00390625f - mB * mB + LN_EPS);

            float* oA = out + ((size_t)b * NN + n0 + row) * OO;
            float* oB = oA + 8 * OO;
#pragma unroll
            for (int nt = 0; nt < 8; ++nt) {
                const int col = cg * 64 + nt * 8 + 2 * tig;
                const float2 ga = gam2[col >> 1];
                const float2 be = bet2[col >> 1];
                float2 wA, wB;
                wA.x = (c[af][nt][0] - mA) * rA * ga.x + be.x;
                wA.y = (c[af][nt][1] - mA) * rA * ga.y + be.y;
                wB.x = (c[af][nt][2] - mB) * rB * ga.x + be.x;
                wB.y = (c[af][nt][3] - mB) * rB * ga.y + be.y;
                *(float2*)(oA + col) = wA;
                *(float2*)(oB + col) = wB;
            }
        }
    }
}

extern "C" void kernel_launch(void* const* d_in, const int* in_sizes, int n_in,
                              void* d_out, int out_size) {
    const float* x1  = (const float*)d_in[0];
    const float* x2  = (const float*)d_in[1];
    const float* w   = (const float*)d_in[2];
    const float* brp = (const float*)d_in[3];
    const float* gam = (const float*)d_in[4];
    const float* bet = (const float*)d_in[5];
    float* out = (float*)d_out;

    cudaFuncSetAttribute(k1_mma, cudaFuncAttributeMaxDynamicSharedMemorySize, K1_SMEM);
    cudaFuncSetAttribute(k3_mma, cudaFuncAttributeMaxDynamicSharedMemorySize, K3_SMEM);

    k0_transpose<<<128, 256>>>(w);
    k1_mma<<<dim3(SPL, BB), 512, K1_SMEM>>>(x1, x2);
    k2_M<<<dim3(32, BB), 256>>>(brp);
    k3_mma<<<148, 512, K3_SMEM>>>(x1, gam, bet, out);
}

// round 13
// speedup vs baseline: 1.8540x; 1.0699x over previous
#include <cuda_runtime.h>
#include <cuda_bf16.h>
#include <math.h>
#include <stdint.h>

#define BB 8
#define NN 16384
#define DD 128
#define OO 256
#define SPL 16                 // K1 n-splits per batch
#define LN_EPS 1e-5f

typedef unsigned long long u64;

// ---------------- scratch (device globals) ----------------
__device__ float g_ctx_part[(size_t)BB * SPL * DD * DD];   // 8MB
__device__ float g_ksum_part[(size_t)BB * SPL * DD];
__device__ float g_wT[DD * OO];
// B = (ctx_norm@W^T + bias)^T in bf16 hi/lo, packed in mma B-fragment layout
__device__ __align__(16) unsigned char g_Bh[(size_t)BB * 65536];
__device__ __align__(16) unsigned char g_Bl[(size_t)BB * 65536];

__device__ __forceinline__ uint32_t smem_u32(const void* p) {
    uint32_t a;
    asm("{ .reg .u64 t; cvta.to.shared.u64 t, %1; cvt.u32.u64 %0, t; }" : "=r"(a) : "l"(p));
    return a;
}

// mma.sync m16n8k16 row.col f32 += bf16*bf16
__device__ __forceinline__ void mma16816(float* c, const uint32_t* a, u64 b) {
    uint32_t b0 = (uint32_t)b, b1 = (uint32_t)(b >> 32);
    asm volatile(
        "mma.sync.aligned.m16n8k16.row.col.f32.bf16.bf16.f32 "
        "{%0,%1,%2,%3}, {%4,%5,%6,%7}, {%8,%9}, {%0,%1,%2,%3};"
        : "+f"(c[0]), "+f"(c[1]), "+f"(c[2]), "+f"(c[3])
        : "r"(a[0]), "r"(a[1]), "r"(a[2]), "r"(a[3]), "r"(b0), "r"(b1));
}
__device__ __forceinline__ void mma_b2(float* c, const uint32_t* a, uint32_t b0, uint32_t b1) {
    asm volatile(
        "mma.sync.aligned.m16n8k16.row.col.f32.bf16.bf16.f32 "
        "{%0,%1,%2,%3}, {%4,%5,%6,%7}, {%8,%9}, {%0,%1,%2,%3};"
        : "+f"(c[0]), "+f"(c[1]), "+f"(c[2]), "+f"(c[3])
        : "r"(a[0]), "r"(a[1]), "r"(a[2]), "r"(a[3]), "r"(b0), "r"(b1));
}
__device__ __forceinline__ void ldsm4(uint32_t* r, uint32_t addr) {
    asm volatile("ldmatrix.sync.aligned.m8n8.x4.shared.b16 {%0,%1,%2,%3}, [%4];"
                 : "=r"(r[0]), "=r"(r[1]), "=r"(r[2]), "=r"(r[3]) : "r"(addr));
}
__device__ __forceinline__ void ldsm4t(uint32_t* r, uint32_t addr) {
    asm volatile("ldmatrix.sync.aligned.m8n8.x4.trans.shared.b16 {%0,%1,%2,%3}, [%4];"
                 : "=r"(r[0]), "=r"(r[1]), "=r"(r[2]), "=r"(r[3]) : "r"(addr));
}
__device__ __forceinline__ uint32_t bf2_hi(float a, float b) {
    __nv_bfloat162 h; h.x = __float2bfloat16(a); h.y = __float2bfloat16(b);
    return *(uint32_t*)&h;
}
#define NBAR(id) asm volatile("bar.sync %0, 128;" :: "r"(id) : "memory")

// ================== K0: transpose W ==================
__global__ void k0_transpose(const float* __restrict__ w) {
    int i = blockIdx.x * blockDim.x + threadIdx.x;
    if (i < DD * OO) { int o = i / DD, v = i % DD; g_wT[v * OO + o] = w[i]; }
}

// ================== K1: context via mma.sync bf16-split ==================
#define K1R 272                        // row stride bytes (136 bf16)
#define SM1_EH 0
#define SM1_EL 34816
#define SM1_XH 69632
#define SM1_XL 104448
#define SM1_CS 139264                  // float[16][128]
#define K1_SMEM (SM1_CS + 8192)        // 147456

__global__ void __launch_bounds__(512, 1) k1_mma(const float* __restrict__ x1,
                                                 const float* __restrict__ x2) {
    extern __shared__ __align__(16) unsigned char smem[];
    const uint32_t sb = smem_u32(smem);
    const int t = threadIdx.x, lane = t & 31, g = t >> 5;
    const int mg = g >> 2, cgn = g & 3;
    const int gid = lane >> 2, tig = lane & 3;
    const int b = blockIdx.y, split = blockIdx.x;
    const int base_n = split * (NN / SPL);

    const int row_l = (lane & 7) + ((lane >> 4) << 3);
    const int colsel = ((lane >> 3) & 1) << 3;
    uint32_t aoff[2], boff[2];
#pragma unroll
    for (int af = 0; af < 2; ++af)
        aoff[af] = (uint32_t)(row_l * K1R + (mg * 32 + af * 16 + colsel) * 2);
#pragma unroll
    for (int pr = 0; pr < 2; ++pr)
        boff[pr] = (uint32_t)(row_l * K1R + (cgn * 32 + pr * 16 + colsel) * 2);

    float c[2][4][4];
#pragma unroll
    for (int af = 0; af < 2; ++af)
#pragma unroll
        for (int nt = 0; nt < 4; ++nt)
#pragma unroll
            for (int q = 0; q < 4; ++q) c[af][nt][q] = 0.f;

    float4 cs = make_float4(0.f, 0.f, 0.f, 0.f);
    const int sr = g * 8;
    unsigned char* Eh = smem + SM1_EH + (size_t)sr * K1R;
    unsigned char* El = smem + SM1_EL + (size_t)sr * K1R;
    unsigned char* Xh = smem + SM1_XH + (size_t)sr * K1R;
    unsigned char* Xl = smem + SM1_XL + (size_t)sr * K1R;

    for (int ch = 0; ch < 8; ++ch) {
        const int n0 = base_n + ch * 128;
        const float4* x1p = (const float4*)(x1 + ((size_t)b * NN + n0 + sr) * DD);
        const float4* x2p = (const float4*)(x2 + ((size_t)b * NN + n0 + sr) * DD);

#pragma unroll 2
        for (int j = 0; j < 8; ++j) {
            const float4 v1 = x1p[j * 32 + lane];
            const float4 v2 = x2p[j * 32 + lane];
            float e0 = __expf(v1.x), e1 = __expf(v1.y), e2 = __expf(v1.z), e3 = __expf(v1.w);
            cs.x += e0; cs.y += e1; cs.z += e2; cs.w += e3;
            uint2 ehw, elw, xhw, xlw;
            ehw.x = bf2_hi(e0, e1); ehw.y = bf2_hi(e2, e3);
            {
                __nv_bfloat162* hp = (__nv_bfloat162*)&ehw;
                elw.x = bf2_hi(e0 - __bfloat162float(hp[0].x), e1 - __bfloat162float(hp[0].y));
                elw.y = bf2_hi(e2 - __bfloat162float(hp[1].x), e3 - __bfloat162float(hp[1].y));
            }
            xhw.x = bf2_hi(v2.x, v2.y); xhw.y = bf2_hi(v2.z, v2.w);
            {
                __nv_bfloat162* hp = (__nv_bfloat162*)&xhw;
                xlw.x = bf2_hi(v2.x - __bfloat162float(hp[0].x), v2.y - __bfloat162float(hp[0].y));
                xlw.y = bf2_hi(v2.z - __bfloat162float(hp[1].x), v2.w - __bfloat162float(hp[1].y));
            }
            const int so = j * K1R + lane * 8;
            *(uint2*)(Eh + so) = ehw;
            *(uint2*)(El + so) = elw;
            *(uint2*)(Xh + so) = xhw;
            *(uint2*)(Xl + so) = xlw;
        }
        __syncthreads();

#pragma unroll
        for (int ks = 0; ks < 8; ++ks) {
            const uint32_t ro = (uint32_t)(ks * 16 * K1R);
            uint32_t ah[2][4], al[2][4], bh[2][4], bl[2][4];
#pragma unroll
            for (int af = 0; af < 2; ++af) {
                ldsm4t(ah[af], sb + SM1_EH + aoff[af] + ro);
                ldsm4t(al[af], sb + SM1_EL + aoff[af] + ro);
            }
#pragma unroll
            for (int pr = 0; pr < 2; ++pr) {
                ldsm4t(bh[pr], sb + SM1_XH + boff[pr] + ro);
                ldsm4t(bl[pr], sb + SM1_XL + boff[pr] + ro);
            }
#pragma unroll
            for (int af = 0; af < 2; ++af)
#pragma unroll
                for (int pr = 0; pr < 2; ++pr)
#pragma unroll
                    for (int sub = 0; sub < 2; ++sub) {
                        const int nt = pr * 2 + sub;
                        mma_b2(c[af][nt], ah[af], bh[pr][sub], bh[pr][sub + 2]);
                        mma_b2(c[af][nt], al[af], bh[pr][sub], bh[pr][sub + 2]);
                        mma_b2(c[af][nt], ah[af], bl[pr][sub], bl[pr][sub + 2]);
                    }
        }
        __syncthreads();
    }

    float* outp = g_ctx_part + ((size_t)(b * SPL + split)) * DD * DD;
#pragma unroll
    for (int af = 0; af < 2; ++af) {
        const int d0 = mg * 32 + af * 16 + gid;
#pragma unroll
        for (int nt = 0; nt < 4; ++nt) {
            const int v = cgn * 32 + nt * 8 + 2 * tig;
            *(float2*)(outp + (size_t)d0 * DD + v) = make_float2(c[af][nt][0], c[af][nt][1]);
            *(float2*)(outp + (size_t)(d0 + 8) * DD + v) = make_float2(c[af][nt][2], c[af][nt][3]);
        }
    }

    float* csum = (float*)(smem + SM1_CS);
    *(float4*)&csum[g * 128 + 4 * lane] = cs;
    __syncthreads();
    if (t < 128) {
        float s = 0.f;
#pragma unroll
        for (int k = 0; k < 16; ++k) s += csum[k * 128 + t];
        g_ksum_part[((size_t)(b * SPL + split)) * DD + t] = s;
    }
}

// ================== K2: merge, normalize, pack B-fragments bf16 hi/lo ==================
__global__ void k2_M(const float* __restrict__ bias) {
    __shared__ float ctx_s[4][128];
    __shared__ float ks_s[4];
    const int b = blockIdx.y, dg = blockIdx.x;
    const int t = threadIdx.x;

    if (t < 4) {
        float s = 0.f;
        for (int ch = 0; ch < SPL; ++ch)
            s += g_ksum_part[((size_t)(b * SPL + ch)) * DD + dg * 4 + t];
        ks_s[t] = 1.0f / s;
    }
    __syncthreads();

    for (int e = t; e < 512; e += 256) {
        const int d = e >> 7, v = e & 127;
        const float* p = g_ctx_part + (size_t)b * SPL * DD * DD + (size_t)(dg * 4 + d) * DD + v;
        float s = 0.f;
        for (int ch = 0; ch < SPL; ++ch) s += p[(size_t)ch * DD * DD];
        ctx_s[d][v] = s * ks_s[d];
    }
    __syncthreads();

    const float bo = bias[t];
    float av[4] = {bo, bo, bo, bo};
#pragma unroll 8
    for (int v = 0; v < 128; ++v) {
        const float wv = g_wT[v * OO + t];
        av[0] = fmaf(ctx_s[0][v], wv, av[0]);
        av[1] = fmaf(ctx_s[1][v], wv, av[1]);
        av[2] = fmaf(ctx_s[2][v], wv, av[2]);
        av[3] = fmaf(ctx_s[3][v], wv, av[3]);
    }

    const int nt = t >> 3, gid = t & 7;
    unsigned char* Bh = g_Bh + (size_t)b * 65536;
    unsigned char* Bl = g_Bl + (size_t)b * 65536;
#pragma unroll
    for (int d = 0; d < 4; ++d) {
        const int k = dg * 4 + d;
        const int ks = k >> 4, r = k & 15;
        const int half = r >> 3, tg = (r & 7) >> 1, pos = r & 1;
        const size_t off = ((size_t)((ks * 32 + nt) * 32 + (gid * 4 + tg))) * 8
                         + half * 4 + pos * 2;
        const __nv_bfloat16 h = __float2bfloat16(av[d]);
        const __nv_bfloat16 l = __float2bfloat16(av[d] - __bfloat162float(h));
        *(__nv_bfloat16*)(Bh + off) = h;
        *(__nv_bfloat16*)(Bl + off) = l;
    }
}

// K3 smem layout (bytes)
#define SM_GAM 0
#define SM_BET 1024
#define SM_RS  2048
#define SM_RQ  4096
#define SM_AHI 6144
#define SM_ALO (SM_AHI + 34816)
#define SM_BHI (SM_ALO + 34816)
#define SM_BLO (SM_BHI + 65536)
#define K3_SMEM (SM_BLO + 65536)     // 206848

// ================== K3: 128x256 tile, 4 independent row-group pipelines ==================
// Row-group rg = warps {rg*4+cg}: its A rows (rg*32..+31) and LN scratch are
// private to the group, so per-tile syncs are named barriers (1+rg, 128 thr).
// Groups skew across phases -> staging/epilogue of one group overlaps MMA of
// another. Full __syncthreads only around the rare B reload (uniform branch).
__global__ void __launch_bounds__(512, 1) k3_mma(const float* __restrict__ x1,
                                                 const float* __restrict__ gamma,
                                                 const float* __restrict__ beta,
                                                 float* __restrict__ out) {
    extern __shared__ __align__(16) unsigned char smem[];
    const uint32_t sb = smem_u32(smem);
    const int t = threadIdx.x, lane = t & 31, g = t >> 5;
    const int rg = g >> 2;
    const int cg = g & 3;
    const int gid = lane >> 2, tig = lane & 3;
    const int m = lane >> 3;
    const int bar = 1 + rg;

    if (t < 256) {
        ((float*)(smem + SM_GAM))[t] = gamma[t];
        ((float*)(smem + SM_BET))[t] = beta[t];
    }

    const int arow0 = rg * 32 + (m & 1) * 8 + (lane & 7);
    const uint32_t acol = (uint32_t)((m >> 1) * 16);
    uint32_t aH[2], aL[2];
#pragma unroll
    for (int af = 0; af < 2; ++af) {
        aH[af] = sb + SM_AHI + (uint32_t)(arow0 + af * 16) * 272 + acol;
        aL[af] = sb + SM_ALO + (uint32_t)(arow0 + af * 16) * 272 + acol;
    }
    const u64* Bh = (const u64*)(smem + SM_BHI);
    const u64* Bl = (const u64*)(smem + SM_BLO);
    const float2* gam2 = (const float2*)(smem + SM_GAM);
    const float2* bet2 = (const float2*)(smem + SM_BET);
    float* red_s = (float*)(smem + SM_RS);
    float* red_q = (float*)(smem + SM_RQ);
    unsigned char* Ah = smem + SM_AHI + (size_t)(g * 8) * 272;
    unsigned char* Al = smem + SM_ALO + (size_t)(g * 8) * 272;

    const int start = (blockIdx.x * 1024) / gridDim.x;
    const int end   = ((blockIdx.x + 1) * 1024) / gridDim.x;
    int curb = -1;

    for (int tile = start; tile < end; ++tile) {
        const int b = tile >> 7;
        const int n0 = (tile & 127) << 7;

        if (b != curb) {                 // uniform branch across the block
            __syncthreads();             // all groups done with old B
            const float4* sh = (const float4*)(g_Bh + (size_t)b * 65536);
            const float4* sl = (const float4*)(g_Bl + (size_t)b * 65536);
            float4* dh = (float4*)(smem + SM_BHI);
            float4* dl = (float4*)(smem + SM_BLO);
            for (int i = t; i < 4096; i += 512) { dh[i] = sh[i]; dl[i] = sl[i]; }
            curb = b;
            __syncthreads();             // new B visible
        }

        // --- stage A: softmax over D for this warp's 8 rows, bf16 hi/lo ---
        const float4* xp = (const float4*)(x1 + ((size_t)b * NN + n0 + g * 8) * DD);
#pragma unroll 4
        for (int j = 0; j < 8; ++j) {
            const float4 v = xp[j * 32 + lane];
            float e0 = __expf(v.x), e1 = __expf(v.y), e2 = __expf(v.z), e3 = __expf(v.w);
            float s = e0 + e1 + e2 + e3;
#pragma unroll
            for (int mm = 16; mm; mm >>= 1) s += __shfl_xor_sync(0xffffffffu, s, mm);
            const float inv = 1.0f / s;
            e0 *= inv; e1 *= inv; e2 *= inv; e3 *= inv;
            uint2 hw, lw;
            hw.x = bf2_hi(e0, e1); hw.y = bf2_hi(e2, e3);
            {
                __nv_bfloat162* hp = (__nv_bfloat162*)&hw;
                lw.x = bf2_hi(e0 - __bfloat162float(hp[0].x), e1 - __bfloat162float(hp[0].y));
                lw.y = bf2_hi(e2 - __bfloat162float(hp[1].x), e3 - __bfloat162float(hp[1].y));
            }
            *(uint2*)(Ah + j * 272 + lane * 8) = hw;
            *(uint2*)(Al + j * 272 + lane * 8) = lw;
        }
        NBAR(bar);    // group's 32 A rows visible to its 4 warps

        // --- GEMM: 2 A-frags x 8 n-tiles x 8 k-steps x 3 passes ---
        float c[2][8][4];
#pragma unroll
        for (int af = 0; af < 2; ++af)
#pragma unroll
            for (int nt = 0; nt < 8; ++nt)
#pragma unroll
                for (int q = 0; q < 4; ++q) c[af][nt][q] = 0.f;

        for (int ks = 0; ks < 8; ++ks) {
            uint32_t ah[2][4], al[2][4];
#pragma unroll
            for (int af = 0; af < 2; ++af) {
                ldsm4(ah[af], aH[af] + ks * 32);
                ldsm4(al[af], aL[af] + ks * 32);
            }
            const u64* bhk = Bh + (size_t)(ks * 32 + cg * 8) * 32 + lane;
            const u64* blk = Bl + (size_t)(ks * 32 + cg * 8) * 32 + lane;
#pragma unroll
            for (int nt = 0; nt < 8; ++nt) {
                const u64 bh = bhk[nt * 32];
                const u64 bl = blk[nt * 32];
#pragma unroll
                for (int af = 0; af < 2; ++af) {
                    mma16816(c[af][nt], ah[af], bh);
                    mma16816(c[af][nt], al[af], bh);
                    mma16816(c[af][nt], ah[af], bl);
                }
            }
        }

        // --- LN partial sums (this warp's 64 cols) -> group scratch ---
#pragma unroll
        for (int af = 0; af < 2; ++af) {
            float sA = 0.f, sB = 0.f, qA = 0.f, qB = 0.f;
#pragma unroll
            for (int nt = 0; nt < 8; ++nt) {
                sA += c[af][nt][0] + c[af][nt][1];
                sB += c[af][nt][2] + c[af][nt][3];
                qA = fmaf(c[af][nt][0], c[af][nt][0], qA);
                qA = fmaf(c[af][nt][1], c[af][nt][1], qA);
                qB = fmaf(c[af][nt][2], c[af][nt][2], qB);
                qB = fmaf(c[af][nt][3], c[af][nt][3], qB);
            }
#pragma unroll
            for (int mm = 1; mm <= 2; mm <<= 1) {
                sA += __shfl_xor_sync(0xffffffffu, sA, mm);
                sB += __shfl_xor_sync(0xffffffffu, sB, mm);
                qA += __shfl_xor_sync(0xffffffffu, qA, mm);
                qB += __shfl_xor_sync(0xffffffffu, qB, mm);
            }
            if (tig == 0) {
                const int row = rg * 32 + af * 16 + gid;
                red_s[row * 4 + cg] = sA; red_q[row * 4 + cg] = qA;
                red_s[(row + 8) * 4 + cg] = sB; red_q[(row + 8) * 4 + cg] = qB;
            }
        }
        NBAR(bar);    // group's LN partials complete

        // --- LN finalize + store (fixed-order 4-term sums -> deterministic) ---
#pragma unroll
        for (int af = 0; af < 2; ++af) {
            const int row = rg * 32 + af * 16 + gid;
            float4 s4 = *(float4*)&red_s[row * 4];
            float4 q4 = *(float4*)&red_q[row * 4];
            float4 s4b = *(float4*)&red_s[(row + 8) * 4];
            float4 q4b = *(float4*)&red_q[(row + 8) * 4];
            const float sA = s4.x + s4.y + s4.z + s4.w;
            const float qA = q4.x + q4.y + q4.z + q4.w;
            const float sB = s4b.x + s4b.y + s4b.z + s4b.w;
            const float qB = q4b.x + q4b.y + q4b.z + q4b.w;
            const float mA = sA * 0.00390625f, mB = sB * 0.00390625f;
            const float rA = rsqrtf(qA * 0.00390625f - mA * mA + LN_EPS);
            const float rB = rsqrtf(qB * 0.00390625f - mB * mB + LN_EPS);

            float* oA = out + ((size_t)b * NN + n0 + row) * OO;
            float* oB = oA + 8 * OO;
#pragma unroll
            for (int nt = 0; nt < 8; ++nt) {
                const int col = cg * 64 + nt * 8 + 2 * tig;
                const float2 ga = gam2[col >> 1];
                const float2 be = bet2[col >> 1];
                float2 wA, wB;
                wA.x = (c[af][nt][0] - mA) * rA * ga.x + be.x;
                wA.y = (c[af][nt][1] - mA) * rA * ga.y + be.y;
                wB.x = (c[af][nt][2] - mB) * rB * ga.x + be.x;
                wB.y = (c[af][nt][3] - mB) * rB * ga.y + be.y;
                *(float2*)(oA + col) = wA;
                *(float2*)(oB + col) = wB;
            }
        }
    }
}

extern "C" void kernel_launch(void* const* d_in, const int* in_sizes, int n_in,
                              void* d_out, int out_size) {
    const float* x1  = (const float*)d_in[0];
    const float* x2  = (const float*)d_in[1];
    const float* w   = (const float*)d_in[2];
    const float* brp = (const float*)d_in[3];
    const float* gam = (const float*)d_in[4];
    const float* bet = (const float*)d_in[5];
    float* out = (float*)d_out;

    cudaFuncSetAttribute(k1_mma, cudaFuncAttributeMaxDynamicSharedMemorySize, K1_SMEM);
    cudaFuncSetAttribute(k3_mma, cudaFuncAttributeMaxDynamicSharedMemorySize, K3_SMEM);

    k0_transpose<<<128, 256>>>(w);
    k1_mma<<<dim3(SPL, BB), 512, K1_SMEM>>>(x1, x2);
    k2_M<<<dim3(32, BB), 256>>>(brp);
    k3_mma<<<148, 512, K3_SMEM>>>(x1, gam, bet, out);
}

// round 14
// speedup vs baseline: 2.0953x; 1.1302x over previous
#include <cuda_runtime.h>
#include <cuda_bf16.h>
#include <math.h>
#include <stdint.h>

#define BB 8
#define NN 16384
#define DD 128
#define OO 256
#define SPL 18                 // K1 n-splits per batch (144 blocks)
#define LN_EPS 1e-5f

typedef unsigned long long u64;

// ---------------- scratch (device globals) ----------------
__device__ float g_ctx_part[(size_t)BB * SPL * DD * DD];   // ~9.4MB
__device__ float g_ksum_part[(size_t)BB * SPL * DD];
__device__ float g_wT[DD * OO];
// B = (ctx_norm@W^T + bias)^T in bf16 hi/lo, packed in mma B-fragment layout
__device__ __align__(16) unsigned char g_Bh[(size_t)BB * 65536];
__device__ __align__(16) unsigned char g_Bl[(size_t)BB * 65536];

__device__ __forceinline__ uint32_t smem_u32(const void* p) {
    uint32_t a;
    asm("{ .reg .u64 t; cvta.to.shared.u64 t, %1; cvt.u32.u64 %0, t; }" : "=r"(a) : "l"(p));
    return a;
}

// mma.sync m16n8k16 row.col f32 += bf16*bf16
__device__ __forceinline__ void mma16816(float* c, const uint32_t* a, u64 b) {
    uint32_t b0 = (uint32_t)b, b1 = (uint32_t)(b >> 32);
    asm volatile(
        "mma.sync.aligned.m16n8k16.row.col.f32.bf16.bf16.f32 "
        "{%0,%1,%2,%3}, {%4,%5,%6,%7}, {%8,%9}, {%0,%1,%2,%3};"
        : "+f"(c[0]), "+f"(c[1]), "+f"(c[2]), "+f"(c[3])
        : "r"(a[0]), "r"(a[1]), "r"(a[2]), "r"(a[3]), "r"(b0), "r"(b1));
}
__device__ __forceinline__ void mma_b2(float* c, const uint32_t* a, uint32_t b0, uint32_t b1) {
    asm volatile(
        "mma.sync.aligned.m16n8k16.row.col.f32.bf16.bf16.f32 "
        "{%0,%1,%2,%3}, {%4,%5,%6,%7}, {%8,%9}, {%0,%1,%2,%3};"
        : "+f"(c[0]), "+f"(c[1]), "+f"(c[2]), "+f"(c[3])
        : "r"(a[0]), "r"(a[1]), "r"(a[2]), "r"(a[3]), "r"(b0), "r"(b1));
}
__device__ __forceinline__ void ldsm4(uint32_t* r, uint32_t addr) {
    asm volatile("ldmatrix.sync.aligned.m8n8.x4.shared.b16 {%0,%1,%2,%3}, [%4];"
                 : "=r"(r[0]), "=r"(r[1]), "=r"(r[2]), "=r"(r[3]) : "r"(addr));
}
__device__ __forceinline__ void ldsm4t(uint32_t* r, uint32_t addr) {
    asm volatile("ldmatrix.sync.aligned.m8n8.x4.trans.shared.b16 {%0,%1,%2,%3}, [%4];"
                 : "=r"(r[0]), "=r"(r[1]), "=r"(r[2]), "=r"(r[3]) : "r"(addr));
}
__device__ __forceinline__ uint32_t bf2_hi(float a, float b) {
    __nv_bfloat162 h; h.x = __float2bfloat16(a); h.y = __float2bfloat16(b);
    return *(uint32_t*)&h;
}
#define NBAR(id) asm volatile("bar.sync %0, 128;" :: "r"(id) : "memory")

// ================== K0: transpose W ==================
__global__ void k0_transpose(const float* __restrict__ w) {
    int i = blockIdx.x * blockDim.x + threadIdx.x;
    if (i < DD * OO) { int o = i / DD, v = i % DD; g_wT[v * OO + o] = w[i]; }
}

// ================== K1: context via mma.sync bf16-split, SW-pipelined ==================
// 64-row chunks, double-buffered staging; LDG for chunk ch+1 issued before
// MMA(ch) so global latency hides under tensor work. 1 barrier per chunk.
#define K1R 272                        // staging row stride (136 bf16)
#define K1_CMP 17408                   // 64 rows * 272
#define K1_BUF (4 * K1_CMP)            // EH|EL|XH|XL per buffer = 69632
#define SM1_CS (2 * K1_BUF)            // 139264: float[16][128]
#define K1_SMEM (SM1_CS + 8192)        // 147456

__global__ void __launch_bounds__(512, 1) k1_mma(const float* __restrict__ x1,
                                                 const float* __restrict__ x2) {
    extern __shared__ __align__(16) unsigned char smem[];
    const uint32_t sb = smem_u32(smem);
    const int t = threadIdx.x, lane = t & 31, g = t >> 5;
    const int mg = g >> 2, cgn = g & 3;
    const int gid = lane >> 2, tig = lane & 3;
    const int b = blockIdx.y, split = blockIdx.x;
    const int c0 = (split * 256) / SPL;        // 64-row chunk range
    const int c1 = ((split + 1) * 256) / SPL;

    // ldmatrix.trans lane addressing (validated in R11)
    const int row_l = (lane & 7) + ((lane >> 4) << 3);
    const int colsel = ((lane >> 3) & 1) << 3;
    uint32_t aoff[2], boff[2];
#pragma unroll
    for (int af = 0; af < 2; ++af)
        aoff[af] = (uint32_t)(row_l * K1R + (mg * 32 + af * 16 + colsel) * 2);
#pragma unroll
    for (int pr = 0; pr < 2; ++pr)
        boff[pr] = (uint32_t)(row_l * K1R + (cgn * 32 + pr * 16 + colsel) * 2);

    float c[2][4][4];
#pragma unroll
    for (int af = 0; af < 2; ++af)
#pragma unroll
        for (int nt = 0; nt < 4; ++nt)
#pragma unroll
            for (int q = 0; q < 4; ++q) c[af][nt][q] = 0.f;

    float4 cs = make_float4(0.f, 0.f, 0.f, 0.f);
    const int sr = g * 4;   // this warp stages rows sr..sr+3 of the 64-row chunk

    float4 v1[4], v2[4];
    {   // preload chunk c0
        const float4* p1 = (const float4*)(x1 + ((size_t)b * NN + c0 * 64 + sr) * DD);
        const float4* p2 = (const float4*)(x2 + ((size_t)b * NN + c0 * 64 + sr) * DD);
#pragma unroll
        for (int j = 0; j < 4; ++j) { v1[j] = p1[j * 32 + lane]; v2[j] = p2[j * 32 + lane]; }
    }

    for (int ch = c0; ch < c1; ++ch) {
        const int buf = ch & 1;
        unsigned char* bufp = smem + buf * K1_BUF;
        unsigned char* Eh = bufp + (size_t)sr * K1R;
        unsigned char* El = bufp + K1_CMP + (size_t)sr * K1R;
        unsigned char* Xh = bufp + 2 * K1_CMP + (size_t)sr * K1R;
        unsigned char* Xl = bufp + 3 * K1_CMP + (size_t)sr * K1R;

        // --- convert & store chunk ch (consumes v1/v2) ---
#pragma unroll
        for (int j = 0; j < 4; ++j) {
            float e0 = __expf(v1[j].x), e1 = __expf(v1[j].y);
            float e2 = __expf(v1[j].z), e3 = __expf(v1[j].w);
            cs.x += e0; cs.y += e1; cs.z += e2; cs.w += e3;
            uint2 ehw, elw, xhw, xlw;
            ehw.x = bf2_hi(e0, e1); ehw.y = bf2_hi(e2, e3);
            {
                __nv_bfloat162* hp = (__nv_bfloat162*)&ehw;
                elw.x = bf2_hi(e0 - __bfloat162float(hp[0].x), e1 - __bfloat162float(hp[0].y));
                elw.y = bf2_hi(e2 - __bfloat162float(hp[1].x), e3 - __bfloat162float(hp[1].y));
            }
            xhw.x = bf2_hi(v2[j].x, v2[j].y); xhw.y = bf2_hi(v2[j].z, v2[j].w);
            {
                __nv_bfloat162* hp = (__nv_bfloat162*)&xhw;
                xlw.x = bf2_hi(v2[j].x - __bfloat162float(hp[0].x), v2[j].y - __bfloat162float(hp[0].y));
                xlw.y = bf2_hi(v2[j].z - __bfloat162float(hp[1].x), v2[j].w - __bfloat162float(hp[1].y));
            }
            const int so = j * K1R + lane * 8;
            *(uint2*)(Eh + so) = ehw;
            *(uint2*)(El + so) = elw;
            *(uint2*)(Xh + so) = xhw;
            *(uint2*)(Xl + so) = xlw;
        }
        __syncthreads();   // chunk ch staged by all warps

        // --- prefetch chunk ch+1 (latency hides under MMA below) ---
        if (ch + 1 < c1) {
            const float4* p1 = (const float4*)(x1 + ((size_t)b * NN + (ch + 1) * 64 + sr) * DD);
            const float4* p2 = (const float4*)(x2 + ((size_t)b * NN + (ch + 1) * 64 + sr) * DD);
#pragma unroll
            for (int j = 0; j < 4; ++j) { v1[j] = p1[j * 32 + lane]; v2[j] = p2[j * 32 + lane]; }
        }

        // --- MMA over chunk ch: 4 k-steps x (2 af x 4 nt) x 3 passes ---
        const uint32_t sbuf = sb + buf * K1_BUF;
#pragma unroll
        for (int ks = 0; ks < 4; ++ks) {
            const uint32_t ro = (uint32_t)(ks * 16 * K1R);
            uint32_t ah[2][4], al[2][4], bh[2][4], bl[2][4];
#pragma unroll
            for (int af = 0; af < 2; ++af) {
                ldsm4t(ah[af], sbuf + aoff[af] + ro);
                ldsm4t(al[af], sbuf + K1_CMP + aoff[af] + ro);
            }
#pragma unroll
            for (int pr = 0; pr < 2; ++pr) {
                ldsm4t(bh[pr], sbuf + 2 * K1_CMP + boff[pr] + ro);
                ldsm4t(bl[pr], sbuf + 3 * K1_CMP + boff[pr] + ro);
            }
#pragma unroll
            for (int af = 0; af < 2; ++af)
#pragma unroll
                for (int pr = 0; pr < 2; ++pr)
#pragma unroll
                    for (int sub = 0; sub < 2; ++sub) {
                        const int nt = pr * 2 + sub;
                        mma_b2(c[af][nt], ah[af], bh[pr][sub], bh[pr][sub + 2]);
                        mma_b2(c[af][nt], al[af], bh[pr][sub], bh[pr][sub + 2]);
                        mma_b2(c[af][nt], ah[af], bl[pr][sub], bl[pr][sub + 2]);
                    }
        }
        // NOTE: no second barrier — next iteration writes the OTHER buffer.
    }

    // --- write 128x128 C partial ---
    float* outp = g_ctx_part + ((size_t)(b * SPL + split)) * DD * DD;
#pragma unroll
    for (int af = 0; af < 2; ++af) {
        const int d0 = mg * 32 + af * 16 + gid;
#pragma unroll
        for (int nt = 0; nt < 4; ++nt) {
            const int v = cgn * 32 + nt * 8 + 2 * tig;
            *(float2*)(outp + (size_t)d0 * DD + v) = make_float2(c[af][nt][0], c[af][nt][1]);
            *(float2*)(outp + (size_t)(d0 + 8) * DD + v) = make_float2(c[af][nt][2], c[af][nt][3]);
        }
    }

    // --- column exp-sum partial (fixed order) ---
    float* csum = (float*)(smem + SM1_CS);
    __syncthreads();   // staging buffers no longer needed
    *(float4*)&csum[g * 128 + 4 * lane] = cs;
    __syncthreads();
    if (t < 128) {
        float s = 0.f;
#pragma unroll
        for (int k = 0; k < 16; ++k) s += csum[k * 128 + t];
        g_ksum_part[((size_t)(b * SPL + split)) * DD + t] = s;
    }
}

// ================== K2: merge, normalize, pack B-fragments bf16 hi/lo ==================
__global__ void k2_M(const float* __restrict__ bias) {
    __shared__ float ctx_s[4][128];
    __shared__ float ks_s[4];
    const int b = blockIdx.y, dg = blockIdx.x;
    const int t = threadIdx.x;

    if (t < 4) {
        float s = 0.f;
        for (int ch = 0; ch < SPL; ++ch)
            s += g_ksum_part[((size_t)(b * SPL + ch)) * DD + dg * 4 + t];
        ks_s[t] = 1.0f / s;
    }
    __syncthreads();

    for (int e = t; e < 512; e += 256) {
        const int d = e >> 7, v = e & 127;
        const float* p = g_ctx_part + (size_t)b * SPL * DD * DD + (size_t)(dg * 4 + d) * DD + v;
        float s = 0.f;
        for (int ch = 0; ch < SPL; ++ch) s += p[(size_t)ch * DD * DD];
        ctx_s[d][v] = s * ks_s[d];
    }
    __syncthreads();

    const float bo = bias[t];
    float av[4] = {bo, bo, bo, bo};
#pragma unroll 8
    for (int v = 0; v < 128; ++v) {
        const float wv = g_wT[v * OO + t];
        av[0] = fmaf(ctx_s[0][v], wv, av[0]);
        av[1] = fmaf(ctx_s[1][v], wv, av[1]);
        av[2] = fmaf(ctx_s[2][v], wv, av[2]);
        av[3] = fmaf(ctx_s[3][v], wv, av[3]);
    }

    const int nt = t >> 3, gid = t & 7;
    unsigned char* Bh = g_Bh + (size_t)b * 65536;
    unsigned char* Bl = g_Bl + (size_t)b * 65536;
#pragma unroll
    for (int d = 0; d < 4; ++d) {
        const int k = dg * 4 + d;
        const int ks = k >> 4, r = k & 15;
        const int half = r >> 3, tg = (r & 7) >> 1, pos = r & 1;
        const size_t off = ((size_t)((ks * 32 + nt) * 32 + (gid * 4 + tg))) * 8
                         + half * 4 + pos * 2;
        const __nv_bfloat16 h = __float2bfloat16(av[d]);
        const __nv_bfloat16 l = __float2bfloat16(av[d] - __bfloat162float(h));
        *(__nv_bfloat16*)(Bh + off) = h;
        *(__nv_bfloat16*)(Bl + off) = l;
    }
}

// K3 smem layout (bytes)
#define SM_GAM 0
#define SM_BET 1024
#define SM_RS  2048
#define SM_RQ  4096
#define SM_AHI 6144
#define SM_ALO (SM_AHI + 34816)
#define SM_BHI (SM_ALO + 34816)
#define SM_BLO (SM_BHI + 65536)
#define K3_SMEM (SM_BLO + 65536)     // 206848

// ================== K3: 128x256 tile, 4 independent row-group pipelines ==================
__global__ void __launch_bounds__(512, 1) k3_mma(const float* __restrict__ x1,
                                                 const float* __restrict__ gamma,
                                                 const float* __restrict__ beta,
                                                 float* __restrict__ out) {
    extern __shared__ __align__(16) unsigned char smem[];
    const uint32_t sb = smem_u32(smem);
    const int t = threadIdx.x, lane = t & 31, g = t >> 5;
    const int rg = g >> 2;
    const int cg = g & 3;
    const int gid = lane >> 2, tig = lane & 3;
    const int m = lane >> 3;
    const int bar = 1 + rg;

    if (t < 256) {
        ((float*)(smem + SM_GAM))[t] = gamma[t];
        ((float*)(smem + SM_BET))[t] = beta[t];
    }

    const int arow0 = rg * 32 + (m & 1) * 8 + (lane & 7);
    const uint32_t acol = (uint32_t)((m >> 1) * 16);
    uint32_t aH[2], aL[2];
#pragma unroll
    for (int af = 0; af < 2; ++af) {
        aH[af] = sb + SM_AHI + (uint32_t)(arow0 + af * 16) * 272 + acol;
        aL[af] = sb + SM_ALO + (uint32_t)(arow0 + af * 16) * 272 + acol;
    }
    const u64* Bh = (const u64*)(smem + SM_BHI);
    const u64* Bl = (const u64*)(smem + SM_BLO);
    const float2* gam2 = (const float2*)(smem + SM_GAM);
    const float2* bet2 = (const float2*)(smem + SM_BET);
    float* red_s = (float*)(smem + SM_RS);
    float* red_q = (float*)(smem + SM_RQ);
    unsigned char* Ah = smem + SM_AHI + (size_t)(g * 8) * 272;
    unsigned char* Al = smem + SM_ALO + (size_t)(g * 8) * 272;

    const int start = (blockIdx.x * 1024) / gridDim.x;
    const int end   = ((blockIdx.x + 1) * 1024) / gridDim.x;
    int curb = -1;

    for (int tile = start; tile < end; ++tile) {
        const int b = tile >> 7;
        const int n0 = (tile & 127) << 7;

        if (b != curb) {                 // uniform branch across the block
            __syncthreads();
            const float4* sh = (const float4*)(g_Bh + (size_t)b * 65536);
            const float4* sl = (const float4*)(g_Bl + (size_t)b * 65536);
            float4* dh = (float4*)(smem + SM_BHI);
            float4* dl = (float4*)(smem + SM_BLO);
            for (int i = t; i < 4096; i += 512) { dh[i] = sh[i]; dl[i] = sl[i]; }
            curb = b;
            __syncthreads();
        }

        // --- stage A: softmax over D for this warp's 8 rows, bf16 hi/lo ---
        const float4* xp = (const float4*)(x1 + ((size_t)b * NN + n0 + g * 8) * DD);
#pragma unroll 4
        for (int j = 0; j < 8; ++j) {
            const float4 v = xp[j * 32 + lane];
            float e0 = __expf(v.x), e1 = __expf(v.y), e2 = __expf(v.z), e3 = __expf(v.w);
            float s = e0 + e1 + e2 + e3;
#pragma unroll
            for (int mm = 16; mm; mm >>= 1) s += __shfl_xor_sync(0xffffffffu, s, mm);
            const float inv = 1.0f / s;
            e0 *= inv; e1 *= inv; e2 *= inv; e3 *= inv;
            uint2 hw, lw;
            hw.x = bf2_hi(e0, e1); hw.y = bf2_hi(e2, e3);
            {
                __nv_bfloat162* hp = (__nv_bfloat162*)&hw;
                lw.x = bf2_hi(e0 - __bfloat162float(hp[0].x), e1 - __bfloat162float(hp[0].y));
                lw.y = bf2_hi(e2 - __bfloat162float(hp[1].x), e3 - __bfloat162float(hp[1].y));
            }
            *(uint2*)(Ah + j * 272 + lane * 8) = hw;
            *(uint2*)(Al + j * 272 + lane * 8) = lw;
        }
        NBAR(bar);

        // --- GEMM: 2 A-frags x 8 n-tiles x 8 k-steps x 3 passes ---
        float c[2][8][4];
#pragma unroll
        for (int af = 0; af < 2; ++af)
#pragma unroll
            for (int nt = 0; nt < 8; ++nt)
#pragma unroll
                for (int q = 0; q < 4; ++q) c[af][nt][q] = 0.f;

        for (int ks = 0; ks < 8; ++ks) {
            uint32_t ah[2][4], al[2][4];
#pragma unroll
            for (int af = 0; af < 2; ++af) {
                ldsm4(ah[af], aH[af] + ks * 32);
                ldsm4(al[af], aL[af] + ks * 32);
            }
            const u64* bhk = Bh + (size_t)(ks * 32 + cg * 8) * 32 + lane;
            const u64* blk = Bl + (size_t)(ks * 32 + cg * 8) * 32 + lane;
#pragma unroll
            for (int nt = 0; nt < 8; ++nt) {
                const u64 bh = bhk[nt * 32];
                const u64 bl = blk[nt * 32];
#pragma unroll
                for (int af = 0; af < 2; ++af) {
                    mma16816(c[af][nt], ah[af], bh);
                    mma16816(c[af][nt], al[af], bh);
                    mma16816(c[af][nt], ah[af], bl);
                }
            }
        }

        // --- LN partial sums (this warp's 64 cols) -> group scratch ---
#pragma unroll
        for (int af = 0; af < 2; ++af) {
            float sA = 0.f, sB = 0.f, qA = 0.f, qB = 0.f;
#pragma unroll
            for (int nt = 0; nt < 8; ++nt) {
                sA += c[af][nt][0] + c[af][nt][1];
                sB += c[af][nt][2] + c[af][nt][3];
                qA = fmaf(c[af][nt][0], c[af][nt][0], qA);
                qA = fmaf(c[af][nt][1], c[af][nt][1], qA);
                qB = fmaf(c[af][nt][2], c[af][nt][2], qB);
                qB = fmaf(c[af][nt][3], c[af][nt][3], qB);
            }
#pragma unroll
            for (int mm = 1; mm <= 2; mm <<= 1) {
                sA += __shfl_xor_sync(0xffffffffu, sA, mm);
                sB += __shfl_xor_sync(0xffffffffu, sB, mm);
                qA += __shfl_xor_sync(0xffffffffu, qA, mm);
                qB += __shfl_xor_sync(0xffffffffu, qB, mm);
            }
            if (tig == 0) {
                const int row = rg * 32 + af * 16 + gid;
                red_s[row * 4 + cg] = sA; red_q[row * 4 + cg] = qA;
                red_s[(row + 8) * 4 + cg] = sB; red_q[(row + 8) * 4 + cg] = qB;
            }
        }
        NBAR(bar);

        // --- LN finalize + store ---
#pragma unroll
        for (int af = 0; af < 2; ++af) {
            const int row = rg * 32 + af * 16 + gid;
            float4 s4 = *(float4*)&red_s[row * 4];
            float4 q4 = *(float4*)&red_q[row * 4];
            float4 s4b = *(float4*)&red_s[(row + 8) * 4];
            float4 q4b = *(float4*)&red_q[(row + 8) * 4];
            const float sA = s4.x + s4.y + s4.z + s4.w;
            const float qA = q4.x + q4.y + q4.z + q4.w;
            const float sB = s4b.x + s4b.y + s4b.z + s4b.w;
            const float qB = q4b.x + q4b.y + q4b.z + q4b.w;
            const float mA = sA * 0.00390625f, mB = sB * 0.00390625f;
            const float rA = rsqrtf(qA * 0.00390625f - mA * mA + LN_EPS);
            const float rB = rsqrtf(qB * 0.00390625f - mB * mB + LN_EPS);

            float* oA = out + ((size_t)b * NN + n0 + row) * OO;
            float* oB = oA + 8 * OO;
#pragma unroll
            for (int nt = 0; nt < 8; ++nt) {
                const int col = cg * 64 + nt * 8 + 2 * tig;
                const float2 ga = gam2[col >> 1];
                const float2 be = bet2[col >> 1];
                float2 wA, wB;
                wA.x = (c[af][nt][0] - mA) * rA * ga.x + be.x;
                wA.y = (c[af][nt][1] - mA) * rA * ga.y + be.y;
                wB.x = (c[af][nt][2] - mB) * rB * ga.x + be.x;
                wB.y = (c[af][nt][3] - mB) * rB * ga.y + be.y;
                *(float2*)(oA + col) = wA;
                *(float2*)(oB + col) = wB;
            }
        }
    }
}

extern "C" void kernel_launch(void* const* d_in, const int* in_sizes, int n_in,
                              void* d_out, int out_size) {
    const float* x1  = (const float*)d_in[0];
    const float* x2  = (const float*)d_in[1];
    const float* w   = (const float*)d_in[2];
    const float* brp = (const float*)d_in[3];
    const float* gam = (const float*)d_in[4];
    const float* bet = (const float*)d_in[5];
    float* out = (float*)d_out;

    cudaFuncSetAttribute(k1_mma, cudaFuncAttributeMaxDynamicSharedMemorySize, K1_SMEM);
    cudaFuncSetAttribute(k3_mma, cudaFuncAttributeMaxDynamicSharedMemorySize, K3_SMEM);

    k0_transpose<<<128, 256>>>(w);
    k1_mma<<<dim3(SPL, BB), 512, K1_SMEM>>>(x1, x2);
    k2_M<<<dim3(32, BB), 256>>>(brp);
    k3_mma<<<148, 512, K3_SMEM>>>(x1, gam, bet, out);
}

// round 15
// speedup vs baseline: 2.5360x; 1.2103x over previous
#include <cuda_runtime.h>
#include <cuda_fp16.h>
#include <math.h>
#include <stdint.h>

#define BB 8
#define NN 16384
#define DD 128
#define OO 256
#define SPL 18                 // K1 n-splits per batch (144 blocks)
#define LN_EPS 1e-5f

typedef unsigned long long u64;

// ---------------- scratch (device globals) ----------------
__device__ float g_ctx_part[(size_t)BB * SPL * DD * DD];   // ~9.4MB
__device__ float g_ksum_part[(size_t)BB * SPL * DD];
__device__ float g_wT[DD * OO];
// B = (ctx_norm@W^T + bias)^T in fp16 (hi only), packed in mma B-fragment layout
__device__ __align__(16) unsigned char g_Bh[(size_t)BB * 65536];

__device__ __forceinline__ uint32_t smem_u32(const void* p) {
    uint32_t a;
    asm("{ .reg .u64 t; cvta.to.shared.u64 t, %1; cvt.u32.u64 %0, t; }" : "=r"(a) : "l"(p));
    return a;
}

// mma.sync m16n8k16 row.col f32 += f16*f16
__device__ __forceinline__ void mma16816(float* c, const uint32_t* a, u64 b) {
    uint32_t b0 = (uint32_t)b, b1 = (uint32_t)(b >> 32);
    asm volatile(
        "mma.sync.aligned.m16n8k16.row.col.f32.f16.f16.f32 "
        "{%0,%1,%2,%3}, {%4,%5,%6,%7}, {%8,%9}, {%0,%1,%2,%3};"
        : "+f"(c[0]), "+f"(c[1]), "+f"(c[2]), "+f"(c[3])
        : "r"(a[0]), "r"(a[1]), "r"(a[2]), "r"(a[3]), "r"(b0), "r"(b1));
}
__device__ __forceinline__ void mma_b2(float* c, const uint32_t* a, uint32_t b0, uint32_t b1) {
    asm volatile(
        "mma.sync.aligned.m16n8k16.row.col.f32.f16.f16.f32 "
        "{%0,%1,%2,%3}, {%4,%5,%6,%7}, {%8,%9}, {%0,%1,%2,%3};"
        : "+f"(c[0]), "+f"(c[1]), "+f"(c[2]), "+f"(c[3])
        : "r"(a[0]), "r"(a[1]), "r"(a[2]), "r"(a[3]), "r"(b0), "r"(b1));
}
__device__ __forceinline__ void ldsm4(uint32_t* r, uint32_t addr) {
    asm volatile("ldmatrix.sync.aligned.m8n8.x4.shared.b16 {%0,%1,%2,%3}, [%4];"
                 : "=r"(r[0]), "=r"(r[1]), "=r"(r[2]), "=r"(r[3]) : "r"(addr));
}
__device__ __forceinline__ void ldsm4t(uint32_t* r, uint32_t addr) {
    asm volatile("ldmatrix.sync.aligned.m8n8.x4.trans.shared.b16 {%0,%1,%2,%3}, [%4];"
                 : "=r"(r[0]), "=r"(r[1]), "=r"(r[2]), "=r"(r[3]) : "r"(addr));
}
#define NBAR(id) asm volatile("bar.sync %0, 128;" :: "r"(id) : "memory")

// ================== K0: transpose W ==================
__global__ void k0_transpose(const float* __restrict__ w) {
    int i = blockIdx.x * blockDim.x + threadIdx.x;
    if (i < DD * OO) { int o = i / DD, v = i % DD; g_wT[v * OO + o] = w[i]; }
}

// ================== K1: context via mma.sync fp16 2-pass, SW-pipelined ==================
// C[d][v] = sum_n exp(x1[n,d]) * x2[n,v] ≈ Eh@Xh + El@Xh (X hi-only).
// 64-row chunks, double-buffered staging; LDG(ch+1) issued before MMA(ch).
#define K1R 272                        // staging row stride (136 fp16)
#define K1_CMP 17408                   // 64 rows * 272
#define K1_BUF (3 * K1_CMP)            // EH|EL|XH per buffer = 52224
#define SM1_CS (2 * K1_BUF)            // 104448: float[16][128]
#define K1_SMEM (SM1_CS + 8192)        // 112640

__global__ void __launch_bounds__(512, 1) k1_mma(const float* __restrict__ x1,
                                                 const float* __restrict__ x2) {
    extern __shared__ __align__(16) unsigned char smem[];
    const uint32_t sb = smem_u32(smem);
    const int t = threadIdx.x, lane = t & 31, g = t >> 5;
    const int mg = g >> 2, cgn = g & 3;
    const int gid = lane >> 2, tig = lane & 3;
    const int b = blockIdx.y, split = blockIdx.x;
    const int c0 = (split * 256) / SPL;        // 64-row chunk range
    const int c1 = ((split + 1) * 256) / SPL;

    const int row_l = (lane & 7) + ((lane >> 4) << 3);
    const int colsel = ((lane >> 3) & 1) << 3;
    uint32_t aoff[2], boff[2];
#pragma unroll
    for (int af = 0; af < 2; ++af)
        aoff[af] = (uint32_t)(row_l * K1R + (mg * 32 + af * 16 + colsel) * 2);
#pragma unroll
    for (int pr = 0; pr < 2; ++pr)
        boff[pr] = (uint32_t)(row_l * K1R + (cgn * 32 + pr * 16 + colsel) * 2);

    float c[2][4][4];
#pragma unroll
    for (int af = 0; af < 2; ++af)
#pragma unroll
        for (int nt = 0; nt < 4; ++nt)
#pragma unroll
            for (int q = 0; q < 4; ++q) c[af][nt][q] = 0.f;

    float4 cs = make_float4(0.f, 0.f, 0.f, 0.f);
    const int sr = g * 4;   // this warp stages rows sr..sr+3 of the 64-row chunk

    float4 v1[4], v2[4];
    {   // preload chunk c0
        const float4* p1 = (const float4*)(x1 + ((size_t)b * NN + c0 * 64 + sr) * DD);
        const float4* p2 = (const float4*)(x2 + ((size_t)b * NN + c0 * 64 + sr) * DD);
#pragma unroll
        for (int j = 0; j < 4; ++j) { v1[j] = p1[j * 32 + lane]; v2[j] = p2[j * 32 + lane]; }
    }

    for (int ch = c0; ch < c1; ++ch) {
        const int buf = ch & 1;
        unsigned char* bufp = smem + buf * K1_BUF;
        unsigned char* Eh = bufp + (size_t)sr * K1R;
        unsigned char* El = bufp + K1_CMP + (size_t)sr * K1R;
        unsigned char* Xh = bufp + 2 * K1_CMP + (size_t)sr * K1R;

        // --- convert & store chunk ch (consumes v1/v2) ---
#pragma unroll
        for (int j = 0; j < 4; ++j) {
            float e0 = __expf(v1[j].x), e1 = __expf(v1[j].y);
            float e2 = __expf(v1[j].z), e3 = __expf(v1[j].w);
            cs.x += e0; cs.y += e1; cs.z += e2; cs.w += e3;
            __half2 eh01 = __floats2half2_rn(e0, e1);
            __half2 eh23 = __floats2half2_rn(e2, e3);
            __half2 el01 = __floats2half2_rn(e0 - __half2float(eh01.x),
                                             e1 - __half2float(eh01.y));
            __half2 el23 = __floats2half2_rn(e2 - __half2float(eh23.x),
                                             e3 - __half2float(eh23.y));
            __half2 xh01 = __floats2half2_rn(v2[j].x, v2[j].y);
            __half2 xh23 = __floats2half2_rn(v2[j].z, v2[j].w);
            uint2 ehw, elw, xhw;
            ehw.x = *(uint32_t*)&eh01; ehw.y = *(uint32_t*)&eh23;
            elw.x = *(uint32_t*)&el01; elw.y = *(uint32_t*)&el23;
            xhw.x = *(uint32_t*)&xh01; xhw.y = *(uint32_t*)&xh23;
            const int so = j * K1R + lane * 8;
            *(uint2*)(Eh + so) = ehw;
            *(uint2*)(El + so) = elw;
            *(uint2*)(Xh + so) = xhw;
        }
        __syncthreads();   // chunk ch staged by all warps

        // --- prefetch chunk ch+1 (latency hides under MMA below) ---
        if (ch + 1 < c1) {
            const float4* p1 = (const float4*)(x1 + ((size_t)b * NN + (ch + 1) * 64 + sr) * DD);
            const float4* p2 = (const float4*)(x2 + ((size_t)b * NN + (ch + 1) * 64 + sr) * DD);
#pragma unroll
            for (int j = 0; j < 4; ++j) { v1[j] = p1[j * 32 + lane]; v2[j] = p2[j * 32 + lane]; }
        }

        // --- MMA over chunk ch: 4 k-steps x (2 af x 4 nt) x 2 passes ---
        const uint32_t sbuf = sb + buf * K1_BUF;
#pragma unroll
        for (int ks = 0; ks < 4; ++ks) {
            const uint32_t ro = (uint32_t)(ks * 16 * K1R);
            uint32_t ah[2][4], al[2][4], bh[2][4];
#pragma unroll
            for (int af = 0; af < 2; ++af) {
                ldsm4t(ah[af], sbuf + aoff[af] + ro);
                ldsm4t(al[af], sbuf + K1_CMP + aoff[af] + ro);
            }
#pragma unroll
            for (int pr = 0; pr < 2; ++pr)
                ldsm4t(bh[pr], sbuf + 2 * K1_CMP + boff[pr] + ro);
#pragma unroll
            for (int af = 0; af < 2; ++af)
#pragma unroll
                for (int pr = 0; pr < 2; ++pr)
#pragma unroll
                    for (int sub = 0; sub < 2; ++sub) {
                        const int nt = pr * 2 + sub;
                        mma_b2(c[af][nt], ah[af], bh[pr][sub], bh[pr][sub + 2]);
                        mma_b2(c[af][nt], al[af], bh[pr][sub], bh[pr][sub + 2]);
                    }
        }
        // no second barrier — next iteration writes the OTHER buffer.
    }

    // --- write 128x128 C partial ---
    float* outp = g_ctx_part + ((size_t)(b * SPL + split)) * DD * DD;
#pragma unroll
    for (int af = 0; af < 2; ++af) {
        const int d0 = mg * 32 + af * 16 + gid;
#pragma unroll
        for (int nt = 0; nt < 4; ++nt) {
            const int v = cgn * 32 + nt * 8 + 2 * tig;
            *(float2*)(outp + (size_t)d0 * DD + v) = make_float2(c[af][nt][0], c[af][nt][1]);
            *(float2*)(outp + (size_t)(d0 + 8) * DD + v) = make_float2(c[af][nt][2], c[af][nt][3]);
        }
    }

    // --- column exp-sum partial (fixed order) ---
    float* csum = (float*)(smem + SM1_CS);
    __syncthreads();
    *(float4*)&csum[g * 128 + 4 * lane] = cs;
    __syncthreads();
    if (t < 128) {
        float s = 0.f;
#pragma unroll
        for (int k = 0; k < 16; ++k) s += csum[k * 128 + t];
        g_ksum_part[((size_t)(b * SPL + split)) * DD + t] = s;
    }
}

// ================== K2: merge, normalize, pack B-fragments fp16 (hi only) ==================
__global__ void k2_M(const float* __restrict__ bias) {
    __shared__ float ctx_s[4][128];
    __shared__ float ks_s[4];
    const int b = blockIdx.y, dg = blockIdx.x;
    const int t = threadIdx.x;

    if (t < 4) {
        float s = 0.f;
        for (int ch = 0; ch < SPL; ++ch)
            s += g_ksum_part[((size_t)(b * SPL + ch)) * DD + dg * 4 + t];
        ks_s[t] = 1.0f / s;
    }
    __syncthreads();

    for (int e = t; e < 512; e += 256) {
        const int d = e >> 7, v = e & 127;
        const float* p = g_ctx_part + (size_t)b * SPL * DD * DD + (size_t)(dg * 4 + d) * DD + v;
        float s = 0.f;
        for (int ch = 0; ch < SPL; ++ch) s += p[(size_t)ch * DD * DD];
        ctx_s[d][v] = s * ks_s[d];
    }
    __syncthreads();

    const float bo = bias[t];   // fold bias (softmax rows sum to 1)
    float av[4] = {bo, bo, bo, bo};
#pragma unroll 8
    for (int v = 0; v < 128; ++v) {
        const float wv = g_wT[v * OO + t];
        av[0] = fmaf(ctx_s[0][v], wv, av[0]);
        av[1] = fmaf(ctx_s[1][v], wv, av[1]);
        av[2] = fmaf(ctx_s[2][v], wv, av[2]);
        av[3] = fmaf(ctx_s[3][v], wv, av[3]);
    }

    const int nt = t >> 3, gid = t & 7;
    unsigned char* Bh = g_Bh + (size_t)b * 65536;
#pragma unroll
    for (int d = 0; d < 4; ++d) {
        const int k = dg * 4 + d;
        const int ks = k >> 4, r = k & 15;
        const int half = r >> 3, tg = (r & 7) >> 1, pos = r & 1;
        const size_t off = ((size_t)((ks * 32 + nt) * 32 + (gid * 4 + tg))) * 8
                         + half * 4 + pos * 2;
        *(__half*)(Bh + off) = __float2half_rn(av[d]);
    }
}

// K3 smem layout (bytes)
#define SM_GAM 0
#define SM_BET 1024
#define SM_RS  2048
#define SM_RQ  4096
#define SM_AHI 6144
#define SM_ALO (SM_AHI + 34816)      // 128 rows * 272B
#define SM_BHI (SM_ALO + 34816)      // 75776
#define K3_SMEM (SM_BHI + 65536)     // 141312

// ================== K3: 128x256 tile, 4 independent row-group pipelines ==================
// fp16 2-pass (Ah@Bh + Al@Bh); next tile's x1 slab L2-prefetched under MMA.
__global__ void __launch_bounds__(512, 1) k3_mma(const float* __restrict__ x1,
                                                 const float* __restrict__ gamma,
                                                 const float* __restrict__ beta,
                                                 float* __restrict__ out) {
    extern __shared__ __align__(16) unsigned char smem[];
    const uint32_t sb = smem_u32(smem);
    const int t = threadIdx.x, lane = t & 31, g = t >> 5;
    const int rg = g >> 2;
    const int cg = g & 3;
    const int gid = lane >> 2, tig = lane & 3;
    const int m = lane >> 3;
    const int bar = 1 + rg;

    if (t < 256) {
        ((float*)(smem + SM_GAM))[t] = gamma[t];
        ((float*)(smem + SM_BET))[t] = beta[t];
    }

    const int arow0 = rg * 32 + (m & 1) * 8 + (lane & 7);
    const uint32_t acol = (uint32_t)((m >> 1) * 16);
    uint32_t aH[2], aL[2];
#pragma unroll
    for (int af = 0; af < 2; ++af) {
        aH[af] = sb + SM_AHI + (uint32_t)(arow0 + af * 16) * 272 + acol;
        aL[af] = sb + SM_ALO + (uint32_t)(arow0 + af * 16) * 272 + acol;
    }
    const u64* Bh = (const u64*)(smem + SM_BHI);
    const float2* gam2 = (const float2*)(smem + SM_GAM);
    const float2* bet2 = (const float2*)(smem + SM_BET);
    float* red_s = (float*)(smem + SM_RS);
    float* red_q = (float*)(smem + SM_RQ);
    unsigned char* Ah = smem + SM_AHI + (size_t)(g * 8) * 272;
    unsigned char* Al = smem + SM_ALO + (size_t)(g * 8) * 272;

    const int start = (blockIdx.x * 1024) / gridDim.x;
    const int end   = ((blockIdx.x + 1) * 1024) / gridDim.x;
    int curb = -1;

    for (int tile = start; tile < end; ++tile) {
        const int b = tile >> 7;
        const int n0 = (tile & 127) << 7;

        if (b != curb) {                 // uniform branch across the block
            __syncthreads();
            const float4* sh = (const float4*)(g_Bh + (size_t)b * 65536);
            float4* dh = (float4*)(smem + SM_BHI);
            for (int i = t; i < 4096; i += 512) dh[i] = sh[i];
            curb = b;
            __syncthreads();
        }

        // --- stage A: softmax over D for this warp's 8 rows, fp16 hi/lo ---
        const float4* xp = (const float4*)(x1 + ((size_t)b * NN + n0 + g * 8) * DD);
#pragma unroll 4
        for (int j = 0; j < 8; ++j) {
            const float4 v = xp[j * 32 + lane];
            float e0 = __expf(v.x), e1 = __expf(v.y), e2 = __expf(v.z), e3 = __expf(v.w);
            float s = e0 + e1 + e2 + e3;
#pragma unroll
            for (int mm = 16; mm; mm >>= 1) s += __shfl_xor_sync(0xffffffffu, s, mm);
            const float inv = 1.0f / s;
            e0 *= inv; e1 *= inv; e2 *= inv; e3 *= inv;
            __half2 h01 = __floats2half2_rn(e0, e1);
            __half2 h23 = __floats2half2_rn(e2, e3);
            __half2 l01 = __floats2half2_rn(e0 - __half2float(h01.x),
                                            e1 - __half2float(h01.y));
            __half2 l23 = __floats2half2_rn(e2 - __half2float(h23.x),
                                            e3 - __half2float(h23.y));
            uint2 hw, lw;
            hw.x = *(uint32_t*)&h01; hw.y = *(uint32_t*)&h23;
            lw.x = *(uint32_t*)&l01; lw.y = *(uint32_t*)&l23;
            *(uint2*)(Ah + j * 272 + lane * 8) = hw;
            *(uint2*)(Al + j * 272 + lane * 8) = lw;
        }
        NBAR(bar);    // group's 32 A rows visible to its 4 warps

        // --- L2-prefetch next tile's x1 slab (64KB, 1 line per thread) ---
        if (tile + 1 < end) {
            const int nb = (tile + 1) >> 7;
            const int nn0 = ((tile + 1) & 127) << 7;
            const char* np = (const char*)(x1 + ((size_t)nb * NN + nn0) * DD);
            asm volatile("prefetch.global.L2 [%0];" :: "l"(np + (size_t)t * 128));
        }

        // --- GEMM: 2 A-frags x 8 n-tiles x 8 k-steps x 2 passes ---
        float c[2][8][4];
#pragma unroll
        for (int af = 0; af < 2; ++af)
#pragma unroll
            for (int nt = 0; nt < 8; ++nt)
#pragma unroll
                for (int q = 0; q < 4; ++q) c[af][nt][q] = 0.f;

        for (int ks = 0; ks < 8; ++ks) {
            uint32_t ah[2][4], al[2][4];
#pragma unroll
            for (int af = 0; af < 2; ++af) {
                ldsm4(ah[af], aH[af] + ks * 32);
                ldsm4(al[af], aL[af] + ks * 32);
            }
            const u64* bhk = Bh + (size_t)(ks * 32 + cg * 8) * 32 + lane;
#pragma unroll
            for (int nt = 0; nt < 8; ++nt) {
                const u64 bh = bhk[nt * 32];
#pragma unroll
                for (int af = 0; af < 2; ++af) {
                    mma16816(c[af][nt], ah[af], bh);
                    mma16816(c[af][nt], al[af], bh);
                }
            }
        }

        // --- LN partial sums (this warp's 64 cols) -> group scratch ---
#pragma unroll
        for (int af = 0; af < 2; ++af) {
            float sA = 0.f, sB = 0.f, qA = 0.f, qB = 0.f;
#pragma unroll
            for (int nt = 0; nt < 8; ++nt) {
                sA += c[af][nt][0] + c[af][nt][1];
                sB += c[af][nt][2] + c[af][nt][3];
                qA = fmaf(c[af][nt][0], c[af][nt][0], qA);
                qA = fmaf(c[af][nt][1], c[af][nt][1], qA);
                qB = fmaf(c[af][nt][2], c[af][nt][2], qB);
                qB = fmaf(c[af][nt][3], c[af][nt][3], qB);
            }
#pragma unroll
            for (int mm = 1; mm <= 2; mm <<= 1) {
                sA += __shfl_xor_sync(0xffffffffu, sA, mm);
                sB += __shfl_xor_sync(0xffffffffu, sB, mm);
                qA += __shfl_xor_sync(0xffffffffu, qA, mm);
                qB += __shfl_xor_sync(0xffffffffu, qB, mm);
            }
            if (tig == 0) {
                const int row = rg * 32 + af * 16 + gid;
                red_s[row * 4 + cg] = sA; red_q[row * 4 + cg] = qA;
                red_s[(row + 8) * 4 + cg] = sB; red_q[(row + 8) * 4 + cg] = qB;
            }
        }
        NBAR(bar);    // group's LN partials complete

        // --- LN finalize + store (fixed-order 4-term sums -> deterministic) ---
#pragma unroll
        for (int af = 0; af < 2; ++af) {
            const int row = rg * 32 + af * 16 + gid;
            float4 s4 = *(float4*)&red_s[row * 4];
            float4 q4 = *(float4*)&red_q[row * 4];
            float4 s4b = *(float4*)&red_s[(row + 8) * 4];
            float4 q4b = *(float4*)&red_q[(row + 8) * 4];
            const float sA = s4.x + s4.y + s4.z + s4.w;
            const float qA = q4.x + q4.y + q4.z + q4.w;
            const float sB = s4b.x + s4b.y + s4b.z + s4b.w;
            const float qB = q4b.x + q4b.y + q4b.z + q4b.w;
            const float mA = sA * 0.00390625f, mB = sB * 0.00390625f;
            const float rA = rsqrtf(qA * 0.00390625f - mA * mA + LN_EPS);
            const float rB = rsqrtf(qB * 0.00390625f - mB * mB + LN_EPS);

            float* oA = out + ((size_t)b * NN + n0 + row) * OO;
            float* oB = oA + 8 * OO;
#pragma unroll
            for (int nt = 0; nt < 8; ++nt) {
                const int col = cg * 64 + nt * 8 + 2 * tig;
                const float2 ga = gam2[col >> 1];
                const float2 be = bet2[col >> 1];
                float2 wA, wB;
                wA.x = (c[af][nt][0] - mA) * rA * ga.x + be.x;
                wA.y = (c[af][nt][1] - mA) * rA * ga.y + be.y;
                wB.x = (c[af][nt][2] - mB) * rB * ga.x + be.x;
                wB.y = (c[af][nt][3] - mB) * rB * ga.y + be.y;
                *(float2*)(oA + col) = wA;
                *(float2*)(oB + col) = wB;
            }
        }
    }
}

extern "C" void kernel_launch(void* const* d_in, const int* in_sizes, int n_in,
                              void* d_out, int out_size) {
    const float* x1  = (const float*)d_in[0];
    const float* x2  = (const float*)d_in[1];
    const float* w   = (const float*)d_in[2];
    const float* brp = (const float*)d_in[3];
    const float* gam = (const float*)d_in[4];
    const float* bet = (const float*)d_in[5];
    float* out = (float*)d_out;

    cudaFuncSetAttribute(k1_mma, cudaFuncAttributeMaxDynamicSharedMemorySize, K1_SMEM);
    cudaFuncSetAttribute(k3_mma, cudaFuncAttributeMaxDynamicSharedMemorySize, K3_SMEM);

    k0_transpose<<<128, 256>>>(w);
    k1_mma<<<dim3(SPL, BB), 512, K1_SMEM>>>(x1, x2);
    k2_M<<<dim3(32, BB), 256>>>(brp);
    k3_mma<<<148, 512, K3_SMEM>>>(x1, gam, bet, out);
}

// round 16
// speedup vs baseline: 2.8130x; 1.1092x over previous
#include <cuda_runtime.h>
#include <cuda_fp16.h>
#include <math.h>
#include <stdint.h>

#define BB 8
#define NN 16384
#define DD 128
#define OO 256
#define SPL 18                 // K1 n-splits per batch (144 blocks)
#define LN_EPS 1e-5f

typedef unsigned long long u64;

// ---------------- scratch (device globals) ----------------
__device__ float g_ctx_part[(size_t)BB * SPL * DD * DD];   // ~9.4MB
__device__ float g_ksum_part[(size_t)BB * SPL * DD];
__device__ float g_wT[DD * OO];
// B = (ctx_norm@W^T + bias)^T in fp16 (hi only), packed in mma B-fragment layout
__device__ __align__(16) unsigned char g_Bh[(size_t)BB * 65536];

__device__ __forceinline__ uint32_t smem_u32(const void* p) {
    uint32_t a;
    asm("{ .reg .u64 t; cvta.to.shared.u64 t, %1; cvt.u32.u64 %0, t; }" : "=r"(a) : "l"(p));
    return a;
}

// mma.sync m16n8k16 row.col f32 += f16*f16
__device__ __forceinline__ void mma16816(float* c, const uint32_t* a, u64 b) {
    uint32_t b0 = (uint32_t)b, b1 = (uint32_t)(b >> 32);
    asm volatile(
        "mma.sync.aligned.m16n8k16.row.col.f32.f16.f16.f32 "
        "{%0,%1,%2,%3}, {%4,%5,%6,%7}, {%8,%9}, {%0,%1,%2,%3};"
        : "+f"(c[0]), "+f"(c[1]), "+f"(c[2]), "+f"(c[3])
        : "r"(a[0]), "r"(a[1]), "r"(a[2]), "r"(a[3]), "r"(b0), "r"(b1));
}
__device__ __forceinline__ void mma_b2(float* c, const uint32_t* a, uint32_t b0, uint32_t b1) {
    asm volatile(
        "mma.sync.aligned.m16n8k16.row.col.f32.f16.f16.f32 "
        "{%0,%1,%2,%3}, {%4,%5,%6,%7}, {%8,%9}, {%0,%1,%2,%3};"
        : "+f"(c[0]), "+f"(c[1]), "+f"(c[2]), "+f"(c[3])
        : "r"(a[0]), "r"(a[1]), "r"(a[2]), "r"(a[3]), "r"(b0), "r"(b1));
}
__device__ __forceinline__ void ldsm4(uint32_t* r, uint32_t addr) {
    asm volatile("ldmatrix.sync.aligned.m8n8.x4.shared.b16 {%0,%1,%2,%3}, [%4];"
                 : "=r"(r[0]), "=r"(r[1]), "=r"(r[2]), "=r"(r[3]) : "r"(addr));
}
__device__ __forceinline__ void ldsm4t(uint32_t* r, uint32_t addr) {
    asm volatile("ldmatrix.sync.aligned.m8n8.x4.trans.shared.b16 {%0,%1,%2,%3}, [%4];"
                 : "=r"(r[0]), "=r"(r[1]), "=r"(r[2]), "=r"(r[3]) : "r"(addr));
}
#define NBAR(id) asm volatile("bar.sync %0, 128;" :: "r"(id) : "memory")

// ================== K0: transpose W ==================
__global__ void k0_transpose(const float* __restrict__ w) {
    int i = blockIdx.x * blockDim.x + threadIdx.x;
    if (i < DD * OO) { int o = i / DD, v = i % DD; g_wT[v * OO + o] = w[i]; }
}

// ================== K1: context via mma.sync fp16 2-pass, SW-pipelined ==================
#define K1R 272                        // staging row stride (136 fp16)
#define K1_CMP 17408                   // 64 rows * 272
#define K1_BUF (3 * K1_CMP)            // EH|EL|XH per buffer = 52224
#define SM1_CS (2 * K1_BUF)            // 104448: float[16][128]
#define K1_SMEM (SM1_CS + 8192)        // 112640

__global__ void __launch_bounds__(512, 1) k1_mma(const float* __restrict__ x1,
                                                 const float* __restrict__ x2) {
    extern __shared__ __align__(16) unsigned char smem[];
    const uint32_t sb = smem_u32(smem);
    const int t = threadIdx.x, lane = t & 31, g = t >> 5;
    const int mg = g >> 2, cgn = g & 3;
    const int gid = lane >> 2, tig = lane & 3;
    const int b = blockIdx.y, split = blockIdx.x;
    const int c0 = (split * 256) / SPL;
    const int c1 = ((split + 1) * 256) / SPL;

    const int row_l = (lane & 7) + ((lane >> 4) << 3);
    const int colsel = ((lane >> 3) & 1) << 3;
    uint32_t aoff[2], boff[2];
#pragma unroll
    for (int af = 0; af < 2; ++af)
        aoff[af] = (uint32_t)(row_l * K1R + (mg * 32 + af * 16 + colsel) * 2);
#pragma unroll
    for (int pr = 0; pr < 2; ++pr)
        boff[pr] = (uint32_t)(row_l * K1R + (cgn * 32 + pr * 16 + colsel) * 2);

    float c[2][4][4];
#pragma unroll
    for (int af = 0; af < 2; ++af)
#pragma unroll
        for (int nt = 0; nt < 4; ++nt)
#pragma unroll
            for (int q = 0; q < 4; ++q) c[af][nt][q] = 0.f;

    float4 cs = make_float4(0.f, 0.f, 0.f, 0.f);
    const int sr = g * 4;

    float4 v1[4], v2[4];
    {
        const float4* p1 = (const float4*)(x1 + ((size_t)b * NN + c0 * 64 + sr) * DD);
        const float4* p2 = (const float4*)(x2 + ((size_t)b * NN + c0 * 64 + sr) * DD);
#pragma unroll
        for (int j = 0; j < 4; ++j) { v1[j] = p1[j * 32 + lane]; v2[j] = p2[j * 32 + lane]; }
    }

    for (int ch = c0; ch < c1; ++ch) {
        const int buf = ch & 1;
        unsigned char* bufp = smem + buf * K1_BUF;
        unsigned char* Eh = bufp + (size_t)sr * K1R;
        unsigned char* El = bufp + K1_CMP + (size_t)sr * K1R;
        unsigned char* Xh = bufp + 2 * K1_CMP + (size_t)sr * K1R;

#pragma unroll
        for (int j = 0; j < 4; ++j) {
            float e0 = __expf(v1[j].x), e1 = __expf(v1[j].y);
            float e2 = __expf(v1[j].z), e3 = __expf(v1[j].w);
            cs.x += e0; cs.y += e1; cs.z += e2; cs.w += e3;
            __half2 eh01 = __floats2half2_rn(e0, e1);
            __half2 eh23 = __floats2half2_rn(e2, e3);
            __half2 el01 = __floats2half2_rn(e0 - __half2float(eh01.x),
                                             e1 - __half2float(eh01.y));
            __half2 el23 = __floats2half2_rn(e2 - __half2float(eh23.x),
                                             e3 - __half2float(eh23.y));
            __half2 xh01 = __floats2half2_rn(v2[j].x, v2[j].y);
            __half2 xh23 = __floats2half2_rn(v2[j].z, v2[j].w);
            uint2 ehw, elw, xhw;
            ehw.x = *(uint32_t*)&eh01; ehw.y = *(uint32_t*)&eh23;
            elw.x = *(uint32_t*)&el01; elw.y = *(uint32_t*)&el23;
            xhw.x = *(uint32_t*)&xh01; xhw.y = *(uint32_t*)&xh23;
            const int so = j * K1R + lane * 8;
            *(uint2*)(Eh + so) = ehw;
            *(uint2*)(El + so) = elw;
            *(uint2*)(Xh + so) = xhw;
        }
        __syncthreads();

        if (ch + 1 < c1) {
            const float4* p1 = (const float4*)(x1 + ((size_t)b * NN + (ch + 1) * 64 + sr) * DD);
            const float4* p2 = (const float4*)(x2 + ((size_t)b * NN + (ch + 1) * 64 + sr) * DD);
#pragma unroll
            for (int j = 0; j < 4; ++j) { v1[j] = p1[j * 32 + lane]; v2[j] = p2[j * 32 + lane]; }
        }

        const uint32_t sbuf = sb + buf * K1_BUF;
#pragma unroll
        for (int ks = 0; ks < 4; ++ks) {
            const uint32_t ro = (uint32_t)(ks * 16 * K1R);
            uint32_t ah[2][4], al[2][4], bh[2][4];
#pragma unroll
            for (int af = 0; af < 2; ++af) {
                ldsm4t(ah[af], sbuf + aoff[af] + ro);
                ldsm4t(al[af], sbuf + K1_CMP + aoff[af] + ro);
            }
#pragma unroll
            for (int pr = 0; pr < 2; ++pr)
                ldsm4t(bh[pr], sbuf + 2 * K1_CMP + boff[pr] + ro);
#pragma unroll
            for (int af = 0; af < 2; ++af)
#pragma unroll
                for (int pr = 0; pr < 2; ++pr)
#pragma unroll
                    for (int sub = 0; sub < 2; ++sub) {
                        const int nt = pr * 2 + sub;
                        mma_b2(c[af][nt], ah[af], bh[pr][sub], bh[pr][sub + 2]);
                        mma_b2(c[af][nt], al[af], bh[pr][sub], bh[pr][sub + 2]);
                    }
        }
    }

    float* outp = g_ctx_part + ((size_t)(b * SPL + split)) * DD * DD;
#pragma unroll
    for (int af = 0; af < 2; ++af) {
        const int d0 = mg * 32 + af * 16 + gid;
#pragma unroll
        for (int nt = 0; nt < 4; ++nt) {
            const int v = cgn * 32 + nt * 8 + 2 * tig;
            *(float2*)(outp + (size_t)d0 * DD + v) = make_float2(c[af][nt][0], c[af][nt][1]);
            *(float2*)(outp + (size_t)(d0 + 8) * DD + v) = make_float2(c[af][nt][2], c[af][nt][3]);
        }
    }

    float* csum = (float*)(smem + SM1_CS);
    __syncthreads();
    *(float4*)&csum[g * 128 + 4 * lane] = cs;
    __syncthreads();
    if (t < 128) {
        float s = 0.f;
#pragma unroll
        for (int k = 0; k < 16; ++k) s += csum[k * 128 + t];
        g_ksum_part[((size_t)(b * SPL + split)) * DD + t] = s;
    }
}

// ================== K2: merge, normalize, pack B-fragments fp16 (hi only) ==================
__global__ void k2_M(const float* __restrict__ bias) {
    __shared__ float ctx_s[4][128];
    __shared__ float ks_s[4];
    const int b = blockIdx.y, dg = blockIdx.x;
    const int t = threadIdx.x;

    if (t < 4) {
        float s = 0.f;
        for (int ch = 0; ch < SPL; ++ch)
            s += g_ksum_part[((size_t)(b * SPL + ch)) * DD + dg * 4 + t];
        ks_s[t] = 1.0f / s;
    }
    __syncthreads();

    for (int e = t; e < 512; e += 256) {
        const int d = e >> 7, v = e & 127;
        const float* p = g_ctx_part + (size_t)b * SPL * DD * DD + (size_t)(dg * 4 + d) * DD + v;
        float s = 0.f;
        for (int ch = 0; ch < SPL; ++ch) s += p[(size_t)ch * DD * DD];
        ctx_s[d][v] = s * ks_s[d];
    }
    __syncthreads();

    const float bo = bias[t];
    float av[4] = {bo, bo, bo, bo};
#pragma unroll 8
    for (int v = 0; v < 128; ++v) {
        const float wv = g_wT[v * OO + t];
        av[0] = fmaf(ctx_s[0][v], wv, av[0]);
        av[1] = fmaf(ctx_s[1][v], wv, av[1]);
        av[2] = fmaf(ctx_s[2][v], wv, av[2]);
        av[3] = fmaf(ctx_s[3][v], wv, av[3]);
    }

    const int nt = t >> 3, gid = t & 7;
    unsigned char* Bh = g_Bh + (size_t)b * 65536;
#pragma unroll
    for (int d = 0; d < 4; ++d) {
        const int k = dg * 4 + d;
        const int ks = k >> 4, r = k & 15;
        const int half = r >> 3, tg = (r & 7) >> 1, pos = r & 1;
        const size_t off = ((size_t)((ks * 32 + nt) * 32 + (gid * 4 + tg))) * 8
                         + half * 4 + pos * 2;
        *(__half*)(Bh + off) = __float2half_rn(av[d]);
    }
}

// K3 smem layout (bytes)
#define SM_GAM 0
#define SM_BET 1024
#define SM_RS  2048                   // [2][512] floats (double-buffered)
#define SM_RQ  6144                   // [2][512] floats
#define SM_A   10240                  // 2 buffers x (AHI 34816 + ALO 34816)
#define ABUF   69632
#define SM_B   (SM_A + 2 * ABUF)      // 149504
#define K3_SMEM (SM_B + 65536)        // 215040

// softmax one row -> fp16 hi/lo staged
__device__ __forceinline__ void k3_row(float4 v, unsigned char* Ah, unsigned char* Al,
                                       int j, int lane) {
    float e0 = __expf(v.x), e1 = __expf(v.y), e2 = __expf(v.z), e3 = __expf(v.w);
    float s = e0 + e1 + e2 + e3;
#pragma unroll
    for (int mm = 16; mm; mm >>= 1) s += __shfl_xor_sync(0xffffffffu, s, mm);
    const float inv = 1.0f / s;
    e0 *= inv; e1 *= inv; e2 *= inv; e3 *= inv;
    __half2 h01 = __floats2half2_rn(e0, e1);
    __half2 h23 = __floats2half2_rn(e2, e3);
    __half2 l01 = __floats2half2_rn(e0 - __half2float(h01.x), e1 - __half2float(h01.y));
    __half2 l23 = __floats2half2_rn(e2 - __half2float(h23.x), e3 - __half2float(h23.y));
    uint2 hw, lw;
    hw.x = *(uint32_t*)&h01; hw.y = *(uint32_t*)&h23;
    lw.x = *(uint32_t*)&l01; lw.y = *(uint32_t*)&l23;
    *(uint2*)(Ah + j * 272 + lane * 8) = hw;
    *(uint2*)(Al + j * 272 + lane * 8) = lw;
}

// ================== K3: SW-pipelined 128x256 tile, A double-buffered ==================
// Per tile: prefetch x1(t+1) into regs -> MMA(t) (hides LDG) -> stage A(t+1)
// -> LN partials(scratch[cur]) -> ONE group barrier -> finalize+STG(t).
__global__ void __launch_bounds__(512, 1) k3_mma(const float* __restrict__ x1,
                                                 const float* __restrict__ gamma,
                                                 const float* __restrict__ beta,
                                                 float* __restrict__ out) {
    extern __shared__ __align__(16) unsigned char smem[];
    const uint32_t sb = smem_u32(smem);
    const int t = threadIdx.x, lane = t & 31, g = t >> 5;
    const int rg = g >> 2;
    const int cg = g & 3;
    const int gid = lane >> 2, tig = lane & 3;
    const int m = lane >> 3;
    const int bar = 1 + rg;

    if (t < 256) {
        ((float*)(smem + SM_GAM))[t] = gamma[t];
        ((float*)(smem + SM_BET))[t] = beta[t];
    }

    const int arow0 = rg * 32 + (m & 1) * 8 + (lane & 7);
    const uint32_t acol = (uint32_t)((m >> 1) * 16);
    uint32_t aH[2], aL[2];
#pragma unroll
    for (int af = 0; af < 2; ++af) {
        aH[af] = sb + SM_A + (uint32_t)(arow0 + af * 16) * 272 + acol;
        aL[af] = aH[af] + 34816;
    }
    const u64* Bh = (const u64*)(smem + SM_B);
    const float2* gam2 = (const float2*)(smem + SM_GAM);
    const float2* bet2 = (const float2*)(smem + SM_BET);

    const int start = (blockIdx.x * 1024) / gridDim.x;
    const int end   = ((blockIdx.x + 1) * 1024) / gridDim.x;
    int curb = -1;

    // ---- prologue: stage tile 'start' into A buffer 0 ----
    {
        const int b0 = start >> 7, n00 = (start & 127) << 7;
        const float4* xp = (const float4*)(x1 + ((size_t)b0 * NN + n00 + g * 8) * DD);
        unsigned char* Ah = smem + SM_A + (size_t)(g * 8) * 272;
        unsigned char* Al = Ah + 34816;
#pragma unroll 4
        for (int j = 0; j < 8; ++j) k3_row(xp[j * 32 + lane], Ah, Al, j, lane);
        NBAR(bar);
    }

    for (int tile = start; tile < end; ++tile) {
        const int b = tile >> 7;
        const int n0 = (tile & 127) << 7;
        const int cur = (tile - start) & 1;
        const uint32_t abase = (uint32_t)(cur * ABUF);
        const bool has_next = (tile + 1 < end);

        if (b != curb) {                 // uniform branch across the block
            __syncthreads();
            const float4* sh = (const float4*)(g_Bh + (size_t)b * 65536);
            float4* dh = (float4*)(smem + SM_B);
            for (int i = t; i < 4096; i += 512) dh[i] = sh[i];
            curb = b;
            __syncthreads();
        }

        // --- prefetch next tile's x1 rows (registers; consumed after MMA) ---
        float4 va[4], vb[4];
        const float4* xnp = 0;
        if (has_next) {
            const int nb = (tile + 1) >> 7, nn0 = ((tile + 1) & 127) << 7;
            xnp = (const float4*)(x1 + ((size_t)nb * NN + nn0 + g * 8) * DD);
#pragma unroll
            for (int j = 0; j < 4; ++j) va[j] = xnp[j * 32 + lane];
        }

        // --- GEMM (ks 0..3) ---
        float c[2][8][4];
#pragma unroll
        for (int af = 0; af < 2; ++af)
#pragma unroll
            for (int nt = 0; nt < 8; ++nt)
#pragma unroll
                for (int q = 0; q < 4; ++q) c[af][nt][q] = 0.f;

#pragma unroll
        for (int ks = 0; ks < 4; ++ks) {
            uint32_t ah[2][4], al[2][4];
#pragma unroll
            for (int af = 0; af < 2; ++af) {
                ldsm4(ah[af], aH[af] + abase + ks * 32);
                ldsm4(al[af], aL[af] + abase + ks * 32);
            }
            const u64* bhk = Bh + (size_t)(ks * 32 + cg * 8) * 32 + lane;
#pragma unroll
            for (int nt = 0; nt < 8; ++nt) {
                const u64 bh = bhk[nt * 32];
#pragma unroll
                for (int af = 0; af < 2; ++af) {
                    mma16816(c[af][nt], ah[af], bh);
                    mma16816(c[af][nt], al[af], bh);
                }
            }
        }

        if (has_next) {
#pragma unroll
            for (int j = 0; j < 4; ++j) vb[j] = xnp[(4 + j) * 32 + lane];
        }

        // --- GEMM (ks 4..7) ---
#pragma unroll
        for (int ks = 4; ks < 8; ++ks) {
            uint32_t ah[2][4], al[2][4];
#pragma unroll
            for (int af = 0; af < 2; ++af) {
                ldsm4(ah[af], aH[af] + abase + ks * 32);
                ldsm4(al[af], aL[af] + abase + ks * 32);
            }
            const u64* bhk = Bh + (size_t)(ks * 32 + cg * 8) * 32 + lane;
#pragma unroll
            for (int nt = 0; nt < 8; ++nt) {
                const u64 bh = bhk[nt * 32];
#pragma unroll
                for (int af = 0; af < 2; ++af) {
                    mma16816(c[af][nt], ah[af], bh);
                    mma16816(c[af][nt], al[af], bh);
                }
            }
        }

        // --- stage A(t+1) into the other buffer (v registers now consumed) ---
        if (has_next) {
            unsigned char* AhN = smem + SM_A + (cur ^ 1) * ABUF + (size_t)(g * 8) * 272;
            unsigned char* AlN = AhN + 34816;
#pragma unroll
            for (int j = 0; j < 4; ++j) k3_row(va[j], AhN, AlN, j, lane);
#pragma unroll
            for (int j = 0; j < 4; ++j) k3_row(vb[j], AhN, AlN, 4 + j, lane);
        }

        // --- LN partial sums -> scratch[cur] ---
        float* red_s = (float*)(smem + SM_RS) + cur * 512;
        float* red_q = (float*)(smem + SM_RQ) + cur * 512;
#pragma unroll
        for (int af = 0; af < 2; ++af) {
            float sA = 0.f, sB = 0.f, qA = 0.f, qB = 0.f;
#pragma unroll
            for (int nt = 0; nt < 8; ++nt) {
                sA += c[af][nt][0] + c[af][nt][1];
                sB += c[af][nt][2] + c[af][nt][3];
                qA = fmaf(c[af][nt][0], c[af][nt][0], qA);
                qA = fmaf(c[af][nt][1], c[af][nt][1], qA);
                qB = fmaf(c[af][nt][2], c[af][nt][2], qB);
                qB = fmaf(c[af][nt][3], c[af][nt][3], qB);
            }
#pragma unroll
            for (int mm = 1; mm <= 2; mm <<= 1) {
                sA += __shfl_xor_sync(0xffffffffu, sA, mm);
                sB += __shfl_xor_sync(0xffffffffu, sB, mm);
                qA += __shfl_xor_sync(0xffffffffu, qA, mm);
                qB += __shfl_xor_sync(0xffffffffu, qB, mm);
            }
            if (tig == 0) {
                const int row = rg * 32 + af * 16 + gid;
                red_s[row * 4 + cg] = sA; red_q[row * 4 + cg] = qA;
                red_s[(row + 8) * 4 + cg] = sB; red_q[(row + 8) * 4 + cg] = qB;
            }
        }
        NBAR(bar);   // one barrier: orders A(t+1) staging AND LN partials

        // --- LN finalize + store (fixed-order 4-term sums -> deterministic) ---
#pragma unroll
        for (int af = 0; af < 2; ++af) {
            const int row = rg * 32 + af * 16 + gid;
            float4 s4 = *(float4*)&red_s[row * 4];
            float4 q4 = *(float4*)&red_q[row * 4];
            float4 s4b = *(float4*)&red_s[(row + 8) * 4];
            float4 q4b = *(float4*)&red_q[(row + 8) * 4];
            const float sA = s4.x + s4.y + s4.z + s4.w;
            const float qA = q4.x + q4.y + q4.z + q4.w;
            const float sB = s4b.x + s4b.y + s4b.z + s4b.w;
            const float qB = q4b.x + q4b.y + q4b.z + q4b.w;
            const float mA = sA * 0.00390625f, mB = sB * 0.00390625f;
            const float rA = rsqrtf(qA * 0.00390625f - mA * mA + LN_EPS);
            const float rB = rsqrtf(qB * 0.00390625f - mB * mB + LN_EPS);

            float* oA = out + ((size_t)b * NN + n0 + row) * OO;
            float* oB = oA + 8 * OO;
#pragma unroll
            for (int nt = 0; nt < 8; ++nt) {
                const int col = cg * 64 + nt * 8 + 2 * tig;
                const float2 ga = gam2[col >> 1];
                const float2 be = bet2[col >> 1];
                float2 wA, wB;
                wA.x = (c[af][nt][0] - mA) * rA * ga.x + be.x;
                wA.y = (c[af][nt][1] - mA) * rA * ga.y + be.y;
                wB.x = (c[af][nt][2] - mB) * rB * ga.x + be.x;
                wB.y = (c[af][nt][3] - mB) * rB * ga.y + be.y;
                *(float2*)(oA + col) = wA;
                *(float2*)(oB + col) = wB;
            }
        }
    }
}

extern "C" void kernel_launch(void* const* d_in, const int* in_sizes, int n_in,
                              void* d_out, int out_size) {
    const float* x1  = (const float*)d_in[0];
    const float* x2  = (const float*)d_in[1];
    const float* w   = (const float*)d_in[2];
    const float* brp = (const float*)d_in[3];
    const float* gam = (const float*)d_in[4];
    const float* bet = (const float*)d_in[5];
    float* out = (float*)d_out;

    cudaFuncSetAttribute(k1_mma, cudaFuncAttributeMaxDynamicSharedMemorySize, K1_SMEM);
    cudaFuncSetAttribute(k3_mma, cudaFuncAttributeMaxDynamicSharedMemorySize, K3_SMEM);

    k0_transpose<<<128, 256>>>(w);
    k1_mma<<<dim3(SPL, BB), 512, K1_SMEM>>>(x1, x2);
    k2_M<<<dim3(32, BB), 256>>>(brp);
    k3_mma<<<148, 512, K3_SMEM>>>(x1, gam, bet, out);
}

// round 17
// speedup vs baseline: 3.2772x; 1.1650x over previous
#include <cuda_runtime.h>
#include <cuda_fp16.h>
#include <math.h>
#include <stdint.h>

#define BB 8
#define NN 16384
#define DD 128
#define OO 256
#define SPL 18                 // K1 n-splits per batch (144 blocks)
#define LN_EPS 1e-5f

typedef unsigned long long u64;

// ---------------- scratch (device globals) ----------------
__device__ float g_ctx_part[(size_t)BB * SPL * DD * DD];   // ~9.4MB
__device__ float g_ksum_part[(size_t)BB * SPL * DD];
__device__ float g_wT[DD * OO];
// B = (ctx_norm@W^T + bias)^T in fp16, packed in mma B-fragment layout
__device__ __align__(16) unsigned char g_Bh[(size_t)BB * 65536];

__device__ __forceinline__ uint32_t smem_u32(const void* p) {
    uint32_t a;
    asm("{ .reg .u64 t; cvta.to.shared.u64 t, %1; cvt.u32.u64 %0, t; }" : "=r"(a) : "l"(p));
    return a;
}

// mma.sync m16n8k16 row.col f32 += f16*f16
__device__ __forceinline__ void mma16816(float* c, const uint32_t* a, u64 b) {
    uint32_t b0 = (uint32_t)b, b1 = (uint32_t)(b >> 32);
    asm volatile(
        "mma.sync.aligned.m16n8k16.row.col.f32.f16.f16.f32 "
        "{%0,%1,%2,%3}, {%4,%5,%6,%7}, {%8,%9}, {%0,%1,%2,%3};"
        : "+f"(c[0]), "+f"(c[1]), "+f"(c[2]), "+f"(c[3])
        : "r"(a[0]), "r"(a[1]), "r"(a[2]), "r"(a[3]), "r"(b0), "r"(b1));
}
__device__ __forceinline__ void mma_b2(float* c, const uint32_t* a, uint32_t b0, uint32_t b1) {
    asm volatile(
        "mma.sync.aligned.m16n8k16.row.col.f32.f16.f16.f32 "
        "{%0,%1,%2,%3}, {%4,%5,%6,%7}, {%8,%9}, {%0,%1,%2,%3};"
        : "+f"(c[0]), "+f"(c[1]), "+f"(c[2]), "+f"(c[3])
        : "r"(a[0]), "r"(a[1]), "r"(a[2]), "r"(a[3]), "r"(b0), "r"(b1));
}
__device__ __forceinline__ void ldsm4(uint32_t* r, uint32_t addr) {
    asm volatile("ldmatrix.sync.aligned.m8n8.x4.shared.b16 {%0,%1,%2,%3}, [%4];"
                 : "=r"(r[0]), "=r"(r[1]), "=r"(r[2]), "=r"(r[3]) : "r"(addr));
}
__device__ __forceinline__ void ldsm4t(uint32_t* r, uint32_t addr) {
    asm volatile("ldmatrix.sync.aligned.m8n8.x4.trans.shared.b16 {%0,%1,%2,%3}, [%4];"
                 : "=r"(r[0]), "=r"(r[1]), "=r"(r[2]), "=r"(r[3]) : "r"(addr));
}
#define NBAR(id) asm volatile("bar.sync %0, 128;" :: "r"(id) : "memory")

// ================== K0: transpose W ==================
__global__ void k0_transpose(const float* __restrict__ w) {
    int i = blockIdx.x * blockDim.x + threadIdx.x;
    if (i < DD * OO) { int o = i / DD, v = i % DD; g_wT[v * OO + o] = w[i]; }
}

// ================== K1: context via mma.sync fp16 single-pass, SW-pipelined ==================
// C[d][v] = sum_n exp(x1[n,d]) * x2[n,v] ≈ Eh@Xh (both fp16).
#define K1R 272                        // staging row stride (136 fp16)
#define K1_CMP 17408                   // 64 rows * 272
#define K1_BUF (2 * K1_CMP)            // EH|XH per buffer = 34816
#define SM1_CS (2 * K1_BUF)            // 69632: float[16][128]
#define K1_SMEM (SM1_CS + 8192)        // 77824

__global__ void __launch_bounds__(512, 1) k1_mma(const float* __restrict__ x1,
                                                 const float* __restrict__ x2) {
    extern __shared__ __align__(16) unsigned char smem[];
    const uint32_t sb = smem_u32(smem);
    const int t = threadIdx.x, lane = t & 31, g = t >> 5;
    const int mg = g >> 2, cgn = g & 3;
    const int gid = lane >> 2, tig = lane & 3;
    const int b = blockIdx.y, split = blockIdx.x;
    const int c0 = (split * 256) / SPL;
    const int c1 = ((split + 1) * 256) / SPL;

    const int row_l = (lane & 7) + ((lane >> 4) << 3);
    const int colsel = ((lane >> 3) & 1) << 3;
    uint32_t aoff[2], boff[2];
#pragma unroll
    for (int af = 0; af < 2; ++af)
        aoff[af] = (uint32_t)(row_l * K1R + (mg * 32 + af * 16 + colsel) * 2);
#pragma unroll
    for (int pr = 0; pr < 2; ++pr)
        boff[pr] = (uint32_t)(row_l * K1R + (cgn * 32 + pr * 16 + colsel) * 2);

    float c[2][4][4];
#pragma unroll
    for (int af = 0; af < 2; ++af)
#pragma unroll
        for (int nt = 0; nt < 4; ++nt)
#pragma unroll
            for (int q = 0; q < 4; ++q) c[af][nt][q] = 0.f;

    float4 cs = make_float4(0.f, 0.f, 0.f, 0.f);
    const int sr = g * 4;

    float4 v1[4], v2[4];
    {
        const float4* p1 = (const float4*)(x1 + ((size_t)b * NN + c0 * 64 + sr) * DD);
        const float4* p2 = (const float4*)(x2 + ((size_t)b * NN + c0 * 64 + sr) * DD);
#pragma unroll
        for (int j = 0; j < 4; ++j) { v1[j] = p1[j * 32 + lane]; v2[j] = p2[j * 32 + lane]; }
    }

    for (int ch = c0; ch < c1; ++ch) {
        const int buf = ch & 1;
        unsigned char* bufp = smem + buf * K1_BUF;
        unsigned char* Eh = bufp + (size_t)sr * K1R;
        unsigned char* Xh = bufp + K1_CMP + (size_t)sr * K1R;

        // --- convert & store chunk ch ---
#pragma unroll
        for (int j = 0; j < 4; ++j) {
            float e0 = __expf(v1[j].x), e1 = __expf(v1[j].y);
            float e2 = __expf(v1[j].z), e3 = __expf(v1[j].w);
            cs.x += e0; cs.y += e1; cs.z += e2; cs.w += e3;
            __half2 eh01 = __floats2half2_rn(e0, e1);
            __half2 eh23 = __floats2half2_rn(e2, e3);
            __half2 xh01 = __floats2half2_rn(v2[j].x, v2[j].y);
            __half2 xh23 = __floats2half2_rn(v2[j].z, v2[j].w);
            uint2 ehw, xhw;
            ehw.x = *(uint32_t*)&eh01; ehw.y = *(uint32_t*)&eh23;
            xhw.x = *(uint32_t*)&xh01; xhw.y = *(uint32_t*)&xh23;
            const int so = j * K1R + lane * 8;
            *(uint2*)(Eh + so) = ehw;
            *(uint2*)(Xh + so) = xhw;
        }
        __syncthreads();

        // --- prefetch chunk ch+1 (latency hides under MMA below) ---
        if (ch + 1 < c1) {
            const float4* p1 = (const float4*)(x1 + ((size_t)b * NN + (ch + 1) * 64 + sr) * DD);
            const float4* p2 = (const float4*)(x2 + ((size_t)b * NN + (ch + 1) * 64 + sr) * DD);
#pragma unroll
            for (int j = 0; j < 4; ++j) { v1[j] = p1[j * 32 + lane]; v2[j] = p2[j * 32 + lane]; }
        }

        // --- MMA over chunk ch: 4 k-steps x (2 af x 4 nt) ---
        const uint32_t sbuf = sb + buf * K1_BUF;
#pragma unroll
        for (int ks = 0; ks < 4; ++ks) {
            const uint32_t ro = (uint32_t)(ks * 16 * K1R);
            uint32_t ah[2][4], bh[2][4];
#pragma unroll
            for (int af = 0; af < 2; ++af)
                ldsm4t(ah[af], sbuf + aoff[af] + ro);
#pragma unroll
            for (int pr = 0; pr < 2; ++pr)
                ldsm4t(bh[pr], sbuf + K1_CMP + boff[pr] + ro);
#pragma unroll
            for (int af = 0; af < 2; ++af)
#pragma unroll
                for (int pr = 0; pr < 2; ++pr)
#pragma unroll
                    for (int sub = 0; sub < 2; ++sub)
                        mma_b2(c[af][pr * 2 + sub], ah[af], bh[pr][sub], bh[pr][sub + 2]);
        }
    }

    float* outp = g_ctx_part + ((size_t)(b * SPL + split)) * DD * DD;
#pragma unroll
    for (int af = 0; af < 2; ++af) {
        const int d0 = mg * 32 + af * 16 + gid;
#pragma unroll
        for (int nt = 0; nt < 4; ++nt) {
            const int v = cgn * 32 + nt * 8 + 2 * tig;
            *(float2*)(outp + (size_t)d0 * DD + v) = make_float2(c[af][nt][0], c[af][nt][1]);
            *(float2*)(outp + (size_t)(d0 + 8) * DD + v) = make_float2(c[af][nt][2], c[af][nt][3]);
        }
    }

    float* csum = (float*)(smem + SM1_CS);
    __syncthreads();
    *(float4*)&csum[g * 128 + 4 * lane] = cs;
    __syncthreads();
    if (t < 128) {
        float s = 0.f;
#pragma unroll
        for (int k = 0; k < 16; ++k) s += csum[k * 128 + t];
        g_ksum_part[((size_t)(b * SPL + split)) * DD + t] = s;
    }
}

// ================== K2: merge, normalize, pack B-fragments fp16 ==================
__global__ void k2_M(const float* __restrict__ bias) {
    __shared__ float ctx_s[4][128];
    __shared__ float ks_s[4];
    const int b = blockIdx.y, dg = blockIdx.x;
    const int t = threadIdx.x;

    if (t < 4) {
        float s = 0.f;
        for (int ch = 0; ch < SPL; ++ch)
            s += g_ksum_part[((size_t)(b * SPL + ch)) * DD + dg * 4 + t];
        ks_s[t] = 1.0f / s;
    }
    __syncthreads();

    for (int e = t; e < 512; e += 256) {
        const int d = e >> 7, v = e & 127;
        const float* p = g_ctx_part + (size_t)b * SPL * DD * DD + (size_t)(dg * 4 + d) * DD + v;
        float s = 0.f;
        for (int ch = 0; ch < SPL; ++ch) s += p[(size_t)ch * DD * DD];
        ctx_s[d][v] = s * ks_s[d];
    }
    __syncthreads();

    const float bo = bias[t];
    float av[4] = {bo, bo, bo, bo};
#pragma unroll 8
    for (int v = 0; v < 128; ++v) {
        const float wv = g_wT[v * OO + t];
        av[0] = fmaf(ctx_s[0][v], wv, av[0]);
        av[1] = fmaf(ctx_s[1][v], wv, av[1]);
        av[2] = fmaf(ctx_s[2][v], wv, av[2]);
        av[3] = fmaf(ctx_s[3][v], wv, av[3]);
    }

    const int nt = t >> 3, gid = t & 7;
    unsigned char* Bh = g_Bh + (size_t)b * 65536;
#pragma unroll
    for (int d = 0; d < 4; ++d) {
        const int k = dg * 4 + d;
        const int ks = k >> 4, r = k & 15;
        const int half = r >> 3, tg = (r & 7) >> 1, pos = r & 1;
        const size_t off = ((size_t)((ks * 32 + nt) * 32 + (gid * 4 + tg))) * 8
                         + half * 4 + pos * 2;
        *(__half*)(Bh + off) = __float2half_rn(av[d]);
    }
}

// K3 smem layout (bytes)
#define SM_GAM 0
#define SM_BET 1024
#define SM_RS  2048                   // [2][512] floats (double-buffered)
#define SM_RQ  6144                   // [2][512] floats
#define SM_A   10240                  // 2 buffers x AHI(34816)
#define ABUF   34816
#define SM_B   (SM_A + 2 * ABUF)      // 79872
#define K3_SMEM (SM_B + 65536)        // 145408

// softmax one row -> fp16 staged
__device__ __forceinline__ void k3_row(float4 v, unsigned char* Ah, int j, int lane) {
    float e0 = __expf(v.x), e1 = __expf(v.y), e2 = __expf(v.z), e3 = __expf(v.w);
    float s = e0 + e1 + e2 + e3;
#pragma unroll
    for (int mm = 16; mm; mm >>= 1) s += __shfl_xor_sync(0xffffffffu, s, mm);
    const float inv = 1.0f / s;
    __half2 h01 = __floats2half2_rn(e0 * inv, e1 * inv);
    __half2 h23 = __floats2half2_rn(e2 * inv, e3 * inv);
    uint2 hw;
    hw.x = *(uint32_t*)&h01; hw.y = *(uint32_t*)&h23;
    *(uint2*)(Ah + j * 272 + lane * 8) = hw;
}

// ================== K3: SW-pipelined 128x256 tile, fp16 single-pass ==================
__global__ void __launch_bounds__(512, 1) k3_mma(const float* __restrict__ x1,
                                                 const float* __restrict__ gamma,
                                                 const float* __restrict__ beta,
                                                 float* __restrict__ out) {
    extern __shared__ __align__(16) unsigned char smem[];
    const uint32_t sb = smem_u32(smem);
    const int t = threadIdx.x, lane = t & 31, g = t >> 5;
    const int rg = g >> 2;
    const int cg = g & 3;
    const int gid = lane >> 2, tig = lane & 3;
    const int m = lane >> 3;
    const int bar = 1 + rg;

    if (t < 256) {
        ((float*)(smem + SM_GAM))[t] = gamma[t];
        ((float*)(smem + SM_BET))[t] = beta[t];
    }

    const int arow0 = rg * 32 + (m & 1) * 8 + (lane & 7);
    const uint32_t acol = (uint32_t)((m >> 1) * 16);
    uint32_t aH[2];
#pragma unroll
    for (int af = 0; af < 2; ++af)
        aH[af] = sb + SM_A + (uint32_t)(arow0 + af * 16) * 272 + acol;
    const u64* Bh = (const u64*)(smem + SM_B);
    const float2* gam2 = (const float2*)(smem + SM_GAM);
    const float2* bet2 = (const float2*)(smem + SM_BET);

    const int start = (blockIdx.x * 1024) / gridDim.x;
    const int end   = ((blockIdx.x + 1) * 1024) / gridDim.x;
    int curb = -1;

    // ---- prologue: stage tile 'start' into A buffer 0 ----
    {
        const int b0 = start >> 7, n00 = (start & 127) << 7;
        const float4* xp = (const float4*)(x1 + ((size_t)b0 * NN + n00 + g * 8) * DD);
        unsigned char* Ah = smem + SM_A + (size_t)(g * 8) * 272;
#pragma unroll 4
        for (int j = 0; j < 8; ++j) k3_row(xp[j * 32 + lane], Ah, j, lane);
        NBAR(bar);
    }

    for (int tile = start; tile < end; ++tile) {
        const int b = tile >> 7;
        const int n0 = (tile & 127) << 7;
        const int cur = (tile - start) & 1;
        const uint32_t abase = (uint32_t)(cur * ABUF);
        const bool has_next = (tile + 1 < end);

        if (b != curb) {                 // uniform branch across the block
            __syncthreads();
            const float4* sh = (const float4*)(g_Bh + (size_t)b * 65536);
            float4* dh = (float4*)(smem + SM_B);
            for (int i = t; i < 4096; i += 512) dh[i] = sh[i];
            curb = b;
            __syncthreads();
        }

        // --- prefetch next tile's x1 rows ---
        float4 va[4], vb[4];
        const float4* xnp = 0;
        if (has_next) {
            const int nb = (tile + 1) >> 7, nn0 = ((tile + 1) & 127) << 7;
            xnp = (const float4*)(x1 + ((size_t)nb * NN + nn0 + g * 8) * DD);
#pragma unroll
            for (int j = 0; j < 4; ++j) va[j] = xnp[j * 32 + lane];
        }

        // --- GEMM (ks 0..3) ---
        float c[2][8][4];
#pragma unroll
        for (int af = 0; af < 2; ++af)
#pragma unroll
            for (int nt = 0; nt < 8; ++nt)
#pragma unroll
                for (int q = 0; q < 4; ++q) c[af][nt][q] = 0.f;

#pragma unroll
        for (int ks = 0; ks < 4; ++ks) {
            uint32_t ah[2][4];
#pragma unroll
            for (int af = 0; af < 2; ++af)
                ldsm4(ah[af], aH[af] + abase + ks * 32);
            const u64* bhk = Bh + (size_t)(ks * 32 + cg * 8) * 32 + lane;
#pragma unroll
            for (int nt = 0; nt < 8; ++nt) {
                const u64 bh = bhk[nt * 32];
#pragma unroll
                for (int af = 0; af < 2; ++af)
                    mma16816(c[af][nt], ah[af], bh);
            }
        }

        if (has_next) {
#pragma unroll
            for (int j = 0; j < 4; ++j) vb[j] = xnp[(4 + j) * 32 + lane];
        }

        // --- GEMM (ks 4..7) ---
#pragma unroll
        for (int ks = 4; ks < 8; ++ks) {
            uint32_t ah[2][4];
#pragma unroll
            for (int af = 0; af < 2; ++af)
                ldsm4(ah[af], aH[af] + abase + ks * 32);
            const u64* bhk = Bh + (size_t)(ks * 32 + cg * 8) * 32 + lane;
#pragma unroll
            for (int nt = 0; nt < 8; ++nt) {
                const u64 bh = bhk[nt * 32];
#pragma unroll
                for (int af = 0; af < 2; ++af)
                    mma16816(c[af][nt], ah[af], bh);
            }
        }

        // --- stage A(t+1) into the other buffer ---
        if (has_next) {
            unsigned char* AhN = smem + SM_A + (cur ^ 1) * ABUF + (size_t)(g * 8) * 272;
#pragma unroll
            for (int j = 0; j < 4; ++j) k3_row(va[j], AhN, j, lane);
#pragma unroll
            for (int j = 0; j < 4; ++j) k3_row(vb[j], AhN, 4 + j, lane);
        }

        // --- LN partial sums -> scratch[cur] ---
        float* red_s = (float*)(smem + SM_RS) + cur * 512;
        float* red_q = (float*)(smem + SM_RQ) + cur * 512;
#pragma unroll
        for (int af = 0; af < 2; ++af) {
            float sA = 0.f, sB = 0.f, qA = 0.f, qB = 0.f;
#pragma unroll
            for (int nt = 0; nt < 8; ++nt) {
                sA += c[af][nt][0] + c[af][nt][1];
                sB += c[af][nt][2] + c[af][nt][3];
                qA = fmaf(c[af][nt][0], c[af][nt][0], qA);
                qA = fmaf(c[af][nt][1], c[af][nt][1], qA);
                qB = fmaf(c[af][nt][2], c[af][nt][2], qB);
                qB = fmaf(c[af][nt][3], c[af][nt][3], qB);
            }
#pragma unroll
            for (int mm = 1; mm <= 2; mm <<= 1) {
                sA += __shfl_xor_sync(0xffffffffu, sA, mm);
                sB += __shfl_xor_sync(0xffffffffu, sB, mm);
                qA += __shfl_xor_sync(0xffffffffu, qA, mm);
                qB += __shfl_xor_sync(0xffffffffu, qB, mm);
            }
            if (tig == 0) {
                const int row = rg * 32 + af * 16 + gid;
                red_s[row * 4 + cg] = sA; red_q[row * 4 + cg] = qA;
                red_s[(row + 8) * 4 + cg] = sB; red_q[(row + 8) * 4 + cg] = qB;
            }
        }
        NBAR(bar);   // one barrier: orders A(t+1) staging AND LN partials

        // --- LN finalize + store ---
#pragma unroll
        for (int af = 0; af < 2; ++af) {
            const int row = rg * 32 + af * 16 + gid;
            float4 s4 = *(float4*)&red_s[row * 4];
            float4 q4 = *(float4*)&red_q[row * 4];
            float4 s4b = *(float4*)&red_s[(row + 8) * 4];
            float4 q4b = *(float4*)&red_q[(row + 8) * 4];
            const float sA = s4.x + s4.y + s4.z + s4.w;
            const float qA = q4.x + q4.y + q4.z + q4.w;
            const float sB = s4b.x + s4b.y + s4b.z + s4b.w;
            const float qB = q4b.x + q4b.y + q4b.z + q4b.w;
            const float mA = sA * 0.00390625f, mB = sB * 0.00390625f;
            const float rA = rsqrtf(qA * 0.00390625f - mA * mA + LN_EPS);
            const float rB = rsqrtf(qB * 0.00390625f - mB * mB + LN_EPS);

            float* oA = out + ((size_t)b * NN + n0 + row) * OO;
            float* oB = oA + 8 * OO;
#pragma unroll
            for (int nt = 0; nt < 8; ++nt) {
                const int col = cg * 64 + nt * 8 + 2 * tig;
                const float2 ga = gam2[col >> 1];
                const float2 be = bet2[col >> 1];
                float2 wA, wB;
                wA.x = (c[af][nt][0] - mA) * rA * ga.x + be.x;
                wA.y = (c[af][nt][1] - mA) * rA * ga.y + be.y;
                wB.x = (c[af][nt][2] - mB) * rB * ga.x + be.x;
                wB.y = (c[af][nt][3] - mB) * rB * ga.y + be.y;
                *(float2*)(oA + col) = wA;
                *(float2*)(oB + col) = wB;
            }
        }
    }
}

extern "C" void kernel_launch(void* const* d_in, const int* in_sizes, int n_in,
                              void* d_out, int out_size) {
    const float* x1  = (const float*)d_in[0];
    const float* x2  = (const float*)d_in[1];
    const float* w   = (const float*)d_in[2];
    const float* brp = (const float*)d_in[3];
    const float* gam = (const float*)d_in[4];
    const float* bet = (const float*)d_in[5];
    float* out = (float*)d_out;

    cudaFuncSetAttribute(k1_mma, cudaFuncAttributeMaxDynamicSharedMemorySize, K1_SMEM);
    cudaFuncSetAttribute(k3_mma, cudaFuncAttributeMaxDynamicSharedMemorySize, K3_SMEM);

    k0_transpose<<<128, 256>>>(w);
    k1_mma<<<dim3(SPL, BB), 512, K1_SMEM>>>(x1, x2);
    k2_M<<<dim3(32, BB), 256>>>(brp);
    k3_mma<<<148, 512, K3_SMEM>>>(x1, gam, bet, out);
}